// round 10
// baseline (speedup 1.0000x reference)
#include <cuda_runtime.h>
#include <math.h>
#include <stdint.h>

// Problem constants
#define B_   4
#define S_   1024
#define E_   256
#define H_   32
#define DK_  8
#define NQ_  8
#define FF_  1024
#define M_   (B_ * S_)   // 4096

typedef unsigned long long ULL;

// ---------------- f32x2 packed math helpers (PTX-only on sm_103a) ----------
__device__ __forceinline__ ULL fma2(ULL a, ULL b, ULL c) {
    ULL d; asm("fma.rn.f32x2 %0, %1, %2, %3;" : "=l"(d) : "l"(a), "l"(b), "l"(c)); return d;
}
__device__ __forceinline__ ULL mul2(ULL a, ULL b) {
    ULL d; asm("mul.rn.f32x2 %0, %1, %2;" : "=l"(d) : "l"(a), "l"(b)); return d;
}
__device__ __forceinline__ ULL add2(ULL a, ULL b) {
    ULL d; asm("add.rn.f32x2 %0, %1, %2;" : "=l"(d) : "l"(a), "l"(b)); return d;
}
__device__ __forceinline__ ULL pk(float lo, float hi) {
    ULL r; asm("mov.b64 %0, {%1, %2};" : "=l"(r) : "f"(lo), "f"(hi)); return r;
}
__device__ __forceinline__ void unpk(ULL v, float& lo, float& hi) {
    asm("mov.b64 {%0, %1}, %2;" : "=f"(lo), "=f"(hi) : "l"(v));
}
__device__ __forceinline__ float ex2f_(float x) {
    float y; asm("ex2.approx.f32 %0, %1;" : "=f"(y) : "f"(x)); return y;
}

// ---------------- scratch (device globals; no runtime allocation) ----------
__device__ __align__(16) float g_qkv[M_ * 3 * E_];
__device__ __align__(16) float g_ctx[M_ * E_];
__device__ __align__(16) float g_Wf[E_ * E_];
__device__ __align__(16) float g_bf[E_];
__device__ __align__(16) float g_tmp[M_ * E_];
__device__ __align__(16) float g_h[M_ * E_];
__device__ __align__(16) float g_qf[M_ * NQ_];
__device__ __align__(16) ULL   g_w1p[FF_ / 2 * NQ_];   // packed w1 pairs
__device__ __align__(16) ULL   g_b1p[FF_ / 2];          // packed b1 pairs
// split-K attention partials (plain floats; lo/hi combined in pass 1)
__device__ __align__(16) float g_plf[131072 * 4];
__device__ __align__(16) float g_paccf[(size_t)131072 * 32];

// ---------------- fold: Wf = w_comb @ w_out, bf = w_comb@b_out + b_comb -----
__global__ __launch_bounds__(256) void fold_w_kernel(
    const float* __restrict__ w_comb, const float* __restrict__ w_out,
    const float* __restrict__ b_out, const float* __restrict__ b_comb)
{
    int i = blockIdx.x;
    int j = threadIdx.x;
    float s = 0.f;
    #pragma unroll 8
    for (int k = 0; k < E_; k++)
        s = fmaf(w_comb[i * E_ + k], w_out[k * E_ + j], s);
    g_Wf[i * E_ + j] = s;

    __shared__ float red[256];
    red[j] = w_comb[i * E_ + j] * b_out[j];
    __syncthreads();
    #pragma unroll
    for (int off = 128; off > 0; off >>= 1) {
        if (j < off) red[j] += red[j + off];
        __syncthreads();
    }
    if (j == 0) g_bf[i] = red[0] + b_comb[i];
}

// ---------------- pack w1/b1 into duplicated-pair form ----------------------
// g_w1p[gkp*8+j] = (w1[2*gkp][j], w1[2*gkp+1][j]); g_b1p[i] = (b1[2i], b1[2i+1])
__global__ __launch_bounds__(256) void pack_w1_kernel(
    const float* __restrict__ w1, const float* __restrict__ b1)
{
    int idx = blockIdx.x * 256 + threadIdx.x;
    if (idx < FF_ / 2 * NQ_) {
        int gkp = idx >> 3, j = idx & 7;
        g_w1p[idx] = pk(w1[gkp * 16 + j], w1[gkp * 16 + 8 + j]);
    } else if (idx < FF_ / 2 * NQ_ + FF_ / 2) {
        int i = idx - FF_ / 2 * NQ_;
        g_b1p[i] = pk(b1[2 * i], b1[2 * i + 1]);
    }
}

// ---------------- f32x2 SGEMM (R5): C = A @ Bw^T + bias --------------------
// BM=128, BN=64, BK=16, 256 threads, 8x4 microtile.
__global__ __launch_bounds__(256) void sgemm2_kernel(
    const float* __restrict__ A, const float* __restrict__ Bw,
    const float* __restrict__ bias, float* __restrict__ C,
    int M, int N, int K)
{
    __shared__ float As[16][132];
    __shared__ float Bs[16][68];

    int tid = threadIdx.x;
    int bm = blockIdx.y * 128;
    int bn = blockIdx.x * 64;
    int ty = tid >> 4;
    int tx = tid & 15;

    int alr = tid >> 1;
    int alc = (tid & 1) * 8;
    int blr = tid >> 2;
    int blc = (tid & 3) * 4;

    const float* Aptr = A  + (size_t)(bm + alr) * K + alc;
    const float* Bptr = Bw + (size_t)(bn + blr) * K + blc;

    float4 a0 = *(const float4*)(Aptr);
    float4 a1 = *(const float4*)(Aptr + 4);
    float4 b0 = *(const float4*)(Bptr);

    ULL acc[4][4];
    #pragma unroll
    for (int r = 0; r < 4; r++)
        #pragma unroll
        for (int j = 0; j < 4; j++) acc[r][j] = 0ULL;

    for (int k0 = 0; ; k0 += 16) {
        As[alc + 0][alr] = a0.x; As[alc + 1][alr] = a0.y;
        As[alc + 2][alr] = a0.z; As[alc + 3][alr] = a0.w;
        As[alc + 4][alr] = a1.x; As[alc + 5][alr] = a1.y;
        As[alc + 6][alr] = a1.z; As[alc + 7][alr] = a1.w;
        Bs[blc + 0][blr] = b0.x; Bs[blc + 1][blr] = b0.y;
        Bs[blc + 2][blr] = b0.z; Bs[blc + 3][blr] = b0.w;
        __syncthreads();

        bool last = (k0 + 16 >= K);
        if (!last) {
            Aptr += 16; Bptr += 16;
            a0 = *(const float4*)(Aptr);
            a1 = *(const float4*)(Aptr + 4);
            b0 = *(const float4*)(Bptr);
        }

        #pragma unroll
        for (int kk = 0; kk < 16; kk++) {
            ulonglong2 am0 = *(const ulonglong2*)&As[kk][ty * 8];
            ulonglong2 am1 = *(const ulonglong2*)&As[kk][ty * 8 + 4];
            float4 b4 = *(const float4*)&Bs[kk][tx * 4];
            ULL bb0 = pk(b4.x, b4.x), bb1 = pk(b4.y, b4.y);
            ULL bb2 = pk(b4.z, b4.z), bb3 = pk(b4.w, b4.w);
            ULL am[4] = {am0.x, am0.y, am1.x, am1.y};
            #pragma unroll
            for (int r = 0; r < 4; r++) {
                acc[r][0] = fma2(am[r], bb0, acc[r][0]);
                acc[r][1] = fma2(am[r], bb1, acc[r][1]);
                acc[r][2] = fma2(am[r], bb2, acc[r][2]);
                acc[r][3] = fma2(am[r], bb3, acc[r][3]);
            }
        }
        if (last) break;
        __syncthreads();
    }

    int col = bn + tx * 4;
    float4 bb = *(const float4*)(bias + col);
    #pragma unroll
    for (int r = 0; r < 4; r++) {
        float lo0, hi0, lo1, hi1, lo2v, hi2, lo3, hi3;
        unpk(acc[r][0], lo0, hi0);
        unpk(acc[r][1], lo1, hi1);
        unpk(acc[r][2], lo2v, hi2);
        unpk(acc[r][3], lo3, hi3);
        int row0 = bm + ty * 8 + 2 * r;
        *(float4*)(C + (size_t)row0 * N + col) =
            make_float4(lo0 + bb.x, lo1 + bb.y, lo2v + bb.z, lo3 + bb.w);
        *(float4*)(C + (size_t)(row0 + 1) * N + col) =
            make_float4(hi0 + bb.x, hi1 + bb.y, hi2 + bb.z, hi3 + bb.w);
    }
}

// ---------------- qkv GEMM with fused cos encoding --------------------------
// A[m][k] = cos(x[m][k] + theta[k & 7]); since (k0+alc) % 8 == 0, each
// thread's 8 staged values use theta[0..7] in order.
__global__ __launch_bounds__(256) void sgemm_qkv_kernel(
    const float* __restrict__ X, const float* __restrict__ theta,
    const float* __restrict__ Bw, const float* __restrict__ bias,
    float* __restrict__ C, int M, int N, int K)
{
    __shared__ float As[16][132];
    __shared__ float Bs[16][68];

    int tid = threadIdx.x;
    int bm = blockIdx.y * 128;
    int bn = blockIdx.x * 64;
    int ty = tid >> 4;
    int tx = tid & 15;

    int alr = tid >> 1;
    int alc = (tid & 1) * 8;
    int blr = tid >> 2;
    int blc = (tid & 3) * 4;

    float th[8];
    #pragma unroll
    for (int j = 0; j < 8; j++) th[j] = theta[j];

    const float* Aptr = X  + (size_t)(bm + alr) * K + alc;
    const float* Bptr = Bw + (size_t)(bn + blr) * K + blc;

    float4 a0 = *(const float4*)(Aptr);
    float4 a1 = *(const float4*)(Aptr + 4);
    float4 b0 = *(const float4*)(Bptr);

    ULL acc[4][4];
    #pragma unroll
    for (int r = 0; r < 4; r++)
        #pragma unroll
        for (int j = 0; j < 4; j++) acc[r][j] = 0ULL;

    for (int k0 = 0; ; k0 += 16) {
        As[alc + 0][alr] = __cosf(a0.x + th[0]);
        As[alc + 1][alr] = __cosf(a0.y + th[1]);
        As[alc + 2][alr] = __cosf(a0.z + th[2]);
        As[alc + 3][alr] = __cosf(a0.w + th[3]);
        As[alc + 4][alr] = __cosf(a1.x + th[4]);
        As[alc + 5][alr] = __cosf(a1.y + th[5]);
        As[alc + 6][alr] = __cosf(a1.z + th[6]);
        As[alc + 7][alr] = __cosf(a1.w + th[7]);
        Bs[blc + 0][blr] = b0.x; Bs[blc + 1][blr] = b0.y;
        Bs[blc + 2][blr] = b0.z; Bs[blc + 3][blr] = b0.w;
        __syncthreads();

        bool last = (k0 + 16 >= K);
        if (!last) {
            Aptr += 16; Bptr += 16;
            a0 = *(const float4*)(Aptr);
            a1 = *(const float4*)(Aptr + 4);
            b0 = *(const float4*)(Bptr);
        }

        #pragma unroll
        for (int kk = 0; kk < 16; kk++) {
            ulonglong2 am0 = *(const ulonglong2*)&As[kk][ty * 8];
            ulonglong2 am1 = *(const ulonglong2*)&As[kk][ty * 8 + 4];
            float4 b4 = *(const float4*)&Bs[kk][tx * 4];
            ULL bb0 = pk(b4.x, b4.x), bb1 = pk(b4.y, b4.y);
            ULL bb2 = pk(b4.z, b4.z), bb3 = pk(b4.w, b4.w);
            ULL am[4] = {am0.x, am0.y, am1.x, am1.y};
            #pragma unroll
            for (int r = 0; r < 4; r++) {
                acc[r][0] = fma2(am[r], bb0, acc[r][0]);
                acc[r][1] = fma2(am[r], bb1, acc[r][1]);
                acc[r][2] = fma2(am[r], bb2, acc[r][2]);
                acc[r][3] = fma2(am[r], bb3, acc[r][3]);
            }
        }
        if (last) break;
        __syncthreads();
    }

    int col = bn + tx * 4;
    float4 bb = *(const float4*)(bias + col);
    #pragma unroll
    for (int r = 0; r < 4; r++) {
        float lo0, hi0, lo1, hi1, lo2v, hi2, lo3, hi3;
        unpk(acc[r][0], lo0, hi0);
        unpk(acc[r][1], lo1, hi1);
        unpk(acc[r][2], lo2v, hi2);
        unpk(acc[r][3], lo3, hi3);
        int row0 = bm + ty * 8 + 2 * r;
        *(float4*)(C + (size_t)row0 * N + col) =
            make_float4(lo0 + bb.x, lo1 + bb.y, lo2v + bb.z, lo3 + bb.w);
        *(float4*)(C + (size_t)(row0 + 1) * N + col) =
            make_float4(hi0 + bb.x, hi1 + bb.y, hi2 + bb.z, hi3 + bb.w);
    }
}

// ---------------- fused FFN GEMM (sgemm2 frame, 256 threads) ----------------
// C = relu(qf @ w1^T + b1) @ w2^T + b2.  A-tile generated in-kernel:
// thread owns row bm+alr (qf dup-packed in regs), 8 ff-cols per tile via
// packed w1 pairs (broadcast LDG, L1-resident).
__global__ __launch_bounds__(256) void sgemm_ffn_kernel(
    const float* __restrict__ w2, const float* __restrict__ b2,
    float* __restrict__ C)
{
    __shared__ float As[16][132];
    __shared__ float Bs[16][68];

    int tid = threadIdx.x;
    int bm = blockIdx.y * 128;
    int bn = blockIdx.x * 64;
    int ty = tid >> 4;
    int tx = tid & 15;

    int alr = tid >> 1;
    int alc = (tid & 1) * 8;
    int blr = tid >> 2;
    int blc = (tid & 3) * 4;

    // qf row for this thread, duplicated-packed
    ULL qfd[8];
    {
        const float4* qp = (const float4*)(g_qf + (size_t)(bm + alr) * NQ_);
        float4 q0 = qp[0], q1 = qp[1];
        qfd[0] = pk(q0.x, q0.x); qfd[1] = pk(q0.y, q0.y);
        qfd[2] = pk(q0.z, q0.z); qfd[3] = pk(q0.w, q0.w);
        qfd[4] = pk(q1.x, q1.x); qfd[5] = pk(q1.y, q1.y);
        qfd[6] = pk(q1.z, q1.z); qfd[7] = pk(q1.w, q1.w);
    }

    const float* Bptr = w2 + (size_t)(bn + blr) * FF_ + blc;
    float4 b0 = *(const float4*)(Bptr);

    ULL acc[4][4];
    #pragma unroll
    for (int r = 0; r < 4; r++)
        #pragma unroll
        for (int j = 0; j < 4; j++) acc[r][j] = 0ULL;

    for (int k0 = 0; ; k0 += 16) {
        // generate 8 hidden values (4 packed pairs) for cols k0+alc .. +7
        {
            int gk = (k0 + alc) >> 1;
            #pragma unroll
            for (int p = 0; p < 4; p++) {
                const ulonglong2* wp = (const ulonglong2*)(g_w1p + (size_t)(gk + p) * 8);
                ulonglong2 w01 = wp[0], w23 = wp[1], w45 = wp[2], w67 = wp[3];
                ULL hp = g_b1p[gk + p];
                hp = fma2(qfd[0], w01.x, hp);
                hp = fma2(qfd[1], w01.y, hp);
                hp = fma2(qfd[2], w23.x, hp);
                hp = fma2(qfd[3], w23.y, hp);
                hp = fma2(qfd[4], w45.x, hp);
                hp = fma2(qfd[5], w45.y, hp);
                hp = fma2(qfd[6], w67.x, hp);
                hp = fma2(qfd[7], w67.y, hp);
                float h0, h1;
                unpk(hp, h0, h1);
                As[alc + 2 * p][alr]     = fmaxf(h0, 0.f);
                As[alc + 2 * p + 1][alr] = fmaxf(h1, 0.f);
            }
        }
        Bs[blc + 0][blr] = b0.x; Bs[blc + 1][blr] = b0.y;
        Bs[blc + 2][blr] = b0.z; Bs[blc + 3][blr] = b0.w;
        __syncthreads();

        bool last = (k0 + 16 >= FF_);
        if (!last) {
            Bptr += 16;
            b0 = *(const float4*)(Bptr);
        }

        #pragma unroll
        for (int kk = 0; kk < 16; kk++) {
            ulonglong2 am0 = *(const ulonglong2*)&As[kk][ty * 8];
            ulonglong2 am1 = *(const ulonglong2*)&As[kk][ty * 8 + 4];
            float4 b4 = *(const float4*)&Bs[kk][tx * 4];
            ULL bb0 = pk(b4.x, b4.x), bb1 = pk(b4.y, b4.y);
            ULL bb2 = pk(b4.z, b4.z), bb3 = pk(b4.w, b4.w);
            ULL am[4] = {am0.x, am0.y, am1.x, am1.y};
            #pragma unroll
            for (int r = 0; r < 4; r++) {
                acc[r][0] = fma2(am[r], bb0, acc[r][0]);
                acc[r][1] = fma2(am[r], bb1, acc[r][1]);
                acc[r][2] = fma2(am[r], bb2, acc[r][2]);
                acc[r][3] = fma2(am[r], bb3, acc[r][3]);
            }
        }
        if (last) break;
        __syncthreads();
    }

    int col = bn + tx * 4;
    float4 bb = *(const float4*)(b2 + col);
    #pragma unroll
    for (int r = 0; r < 4; r++) {
        float lo0, hi0, lo1, hi1, lo2v, hi2, lo3, hi3;
        unpk(acc[r][0], lo0, hi0);
        unpk(acc[r][1], lo1, hi1);
        unpk(acc[r][2], lo2v, hi2);
        unpk(acc[r][3], lo3, hi3);
        int row0 = bm + ty * 8 + 2 * r;
        *(float4*)(C + (size_t)row0 * E_ + col) =
            make_float4(lo0 + bb.x, lo1 + bb.y, lo2v + bb.z, lo3 + bb.w);
        *(float4*)(C + (size_t)(row0 + 1) * E_ + col) =
            make_float4(hi0 + bb.x, hi1 + bb.y, hi2 + bb.z, hi3 + bb.w);
    }
}

// ---------------- attention pass 1: keys-packed, no-max softmax (R8) --------
__global__ __launch_bounds__(128) void attn_p1_kernel()
{
    __shared__ ULL Kp[128 * 8];   // 8 KB: Kp[sp*8+c] = (k_{2sp}[c], k_{2sp+1}[c])
    __shared__ ULL Vp[128 * 8];   // 8 KB

    int kq = blockIdx.x;
    int qh = blockIdx.y;
    int bh = blockIdx.z;
    int b = bh >> 5;
    int h = bh & 31;
    int t = threadIdx.x;
    const float* base = g_qkv + (size_t)b * S_ * (3 * E_) + h * DK_;

    // stage: thread t packs keys (2t, 2t+1)
    {
        const float* ra = base + (size_t)(kq * 256 + 2 * t) * (3 * E_);
        const float* rb = ra + 3 * E_;
        float4 ka0 = *(const float4*)(ra + E_);
        float4 ka1 = *(const float4*)(ra + E_ + 4);
        float4 kb0 = *(const float4*)(rb + E_);
        float4 kb1 = *(const float4*)(rb + E_ + 4);
        ulonglong2* kw = (ulonglong2*)(Kp + t * 8);
        kw[0] = make_ulonglong2(pk(ka0.x, kb0.x), pk(ka0.y, kb0.y));
        kw[1] = make_ulonglong2(pk(ka0.z, kb0.z), pk(ka0.w, kb0.w));
        kw[2] = make_ulonglong2(pk(ka1.x, kb1.x), pk(ka1.y, kb1.y));
        kw[3] = make_ulonglong2(pk(ka1.z, kb1.z), pk(ka1.w, kb1.w));
        float4 va0 = *(const float4*)(ra + 2 * E_);
        float4 va1 = *(const float4*)(ra + 2 * E_ + 4);
        float4 vb0 = *(const float4*)(rb + 2 * E_);
        float4 vb1 = *(const float4*)(rb + 2 * E_ + 4);
        ulonglong2* vw = (ulonglong2*)(Vp + t * 8);
        vw[0] = make_ulonglong2(pk(va0.x, vb0.x), pk(va0.y, vb0.y));
        vw[1] = make_ulonglong2(pk(va0.z, vb0.z), pk(va0.w, vb0.w));
        vw[2] = make_ulonglong2(pk(va1.x, vb1.x), pk(va1.y, vb1.y));
        vw[3] = make_ulonglong2(pk(va1.z, vb1.z), pk(va1.w, vb1.w));
    }
    __syncthreads();

    const float qscale = 0.35355339059327373f * 1.4426950408889634f; // log2e/sqrt(8)

    ULL qd[4][8];
    #pragma unroll
    for (int i = 0; i < 4; i++) {
        const float* r = base + (size_t)(qh * 512 + t + i * 128) * (3 * E_);
        float4 q0 = *(const float4*)(r);
        float4 q1 = *(const float4*)(r + 4);
        float s;
        s = q0.x * qscale; qd[i][0] = pk(s, s);
        s = q0.y * qscale; qd[i][1] = pk(s, s);
        s = q0.z * qscale; qd[i][2] = pk(s, s);
        s = q0.w * qscale; qd[i][3] = pk(s, s);
        s = q1.x * qscale; qd[i][4] = pk(s, s);
        s = q1.y * qscale; qd[i][5] = pk(s, s);
        s = q1.z * qscale; qd[i][6] = pk(s, s);
        s = q1.w * qscale; qd[i][7] = pk(s, s);
    }

    ULL l[4] = {0ULL, 0ULL, 0ULL, 0ULL};
    ULL acc[4][8];
    #pragma unroll
    for (int i = 0; i < 4; i++)
        #pragma unroll
        for (int c = 0; c < 8; c++) acc[i][c] = 0ULL;

    #pragma unroll 1
    for (int sp = 0; sp < 128; sp++) {
        const ulonglong2* kr = (const ulonglong2*)(Kp + sp * 8);
        ulonglong2 k01 = kr[0], k23 = kr[1], k45 = kr[2], k67 = kr[3];

        ULL t0 = mul2(qd[0][0], k01.x);
        ULL t1 = mul2(qd[1][0], k01.x);
        ULL t2 = mul2(qd[2][0], k01.x);
        ULL t3 = mul2(qd[3][0], k01.x);
        t0 = fma2(qd[0][1], k01.y, t0);
        t1 = fma2(qd[1][1], k01.y, t1);
        t2 = fma2(qd[2][1], k01.y, t2);
        t3 = fma2(qd[3][1], k01.y, t3);
        t0 = fma2(qd[0][2], k23.x, t0);
        t1 = fma2(qd[1][2], k23.x, t1);
        t2 = fma2(qd[2][2], k23.x, t2);
        t3 = fma2(qd[3][2], k23.x, t3);
        t0 = fma2(qd[0][3], k23.y, t0);
        t1 = fma2(qd[1][3], k23.y, t1);
        t2 = fma2(qd[2][3], k23.y, t2);
        t3 = fma2(qd[3][3], k23.y, t3);
        t0 = fma2(qd[0][4], k45.x, t0);
        t1 = fma2(qd[1][4], k45.x, t1);
        t2 = fma2(qd[2][4], k45.x, t2);
        t3 = fma2(qd[3][4], k45.x, t3);
        t0 = fma2(qd[0][5], k45.y, t0);
        t1 = fma2(qd[1][5], k45.y, t1);
        t2 = fma2(qd[2][5], k45.y, t2);
        t3 = fma2(qd[3][5], k45.y, t3);
        t0 = fma2(qd[0][6], k67.x, t0);
        t1 = fma2(qd[1][6], k67.x, t1);
        t2 = fma2(qd[2][6], k67.x, t2);
        t3 = fma2(qd[3][6], k67.x, t3);
        t0 = fma2(qd[0][7], k67.y, t0);
        t1 = fma2(qd[1][7], k67.y, t1);
        t2 = fma2(qd[2][7], k67.y, t2);
        t3 = fma2(qd[3][7], k67.y, t3);

        float d0, d1;
        unpk(t0, d0, d1);
        ULL pp0 = pk(ex2f_(d0), ex2f_(d1));
        unpk(t1, d0, d1);
        ULL pp1 = pk(ex2f_(d0), ex2f_(d1));
        unpk(t2, d0, d1);
        ULL pp2 = pk(ex2f_(d0), ex2f_(d1));
        unpk(t3, d0, d1);
        ULL pp3 = pk(ex2f_(d0), ex2f_(d1));
        l[0] = add2(l[0], pp0);
        l[1] = add2(l[1], pp1);
        l[2] = add2(l[2], pp2);
        l[3] = add2(l[3], pp3);

        const ulonglong2* vr = (const ulonglong2*)(Vp + sp * 8);
        ulonglong2 v01 = vr[0], v23 = vr[1], v45 = vr[2], v67 = vr[3];
        acc[0][0] = fma2(pp0, v01.x, acc[0][0]);
        acc[1][0] = fma2(pp1, v01.x, acc[1][0]);
        acc[2][0] = fma2(pp2, v01.x, acc[2][0]);
        acc[3][0] = fma2(pp3, v01.x, acc[3][0]);
        acc[0][1] = fma2(pp0, v01.y, acc[0][1]);
        acc[1][1] = fma2(pp1, v01.y, acc[1][1]);
        acc[2][1] = fma2(pp2, v01.y, acc[2][1]);
        acc[3][1] = fma2(pp3, v01.y, acc[3][1]);
        acc[0][2] = fma2(pp0, v23.x, acc[0][2]);
        acc[1][2] = fma2(pp1, v23.x, acc[1][2]);
        acc[2][2] = fma2(pp2, v23.x, acc[2][2]);
        acc[3][2] = fma2(pp3, v23.x, acc[3][2]);
        acc[0][3] = fma2(pp0, v23.y, acc[0][3]);
        acc[1][3] = fma2(pp1, v23.y, acc[1][3]);
        acc[2][3] = fma2(pp2, v23.y, acc[2][3]);
        acc[3][3] = fma2(pp3, v23.y, acc[3][3]);
        acc[0][4] = fma2(pp0, v45.x, acc[0][4]);
        acc[1][4] = fma2(pp1, v45.x, acc[1][4]);
        acc[2][4] = fma2(pp2, v45.x, acc[2][4]);
        acc[3][4] = fma2(pp3, v45.x, acc[3][4]);
        acc[0][5] = fma2(pp0, v45.y, acc[0][5]);
        acc[1][5] = fma2(pp1, v45.y, acc[1][5]);
        acc[2][5] = fma2(pp2, v45.y, acc[2][5]);
        acc[3][5] = fma2(pp3, v45.y, acc[3][5]);
        acc[0][6] = fma2(pp0, v67.x, acc[0][6]);
        acc[1][6] = fma2(pp1, v67.x, acc[1][6]);
        acc[2][6] = fma2(pp2, v67.x, acc[2][6]);
        acc[3][6] = fma2(pp3, v67.x, acc[3][6]);
        acc[0][7] = fma2(pp0, v67.y, acc[0][7]);
        acc[1][7] = fma2(pp1, v67.y, acc[1][7]);
        acc[2][7] = fma2(pp2, v67.y, acc[2][7]);
        acc[3][7] = fma2(pp3, v67.y, acc[3][7]);
    }

    int pidx = ((bh * 4 + kq) * 2 + qh) * 128 + t;
    {
        float lo, hi;
        float lv[4];
        #pragma unroll
        for (int i = 0; i < 4; i++) { unpk(l[i], lo, hi); lv[i] = lo + hi; }
        *(float4*)(g_plf + pidx * 4) = make_float4(lv[0], lv[1], lv[2], lv[3]);
        float* pa = g_paccf + (size_t)pidx * 32;
        #pragma unroll
        for (int i = 0; i < 4; i++) {
            float av[8];
            #pragma unroll
            for (int c = 0; c < 8; c++) { unpk(acc[i][c], lo, hi); av[c] = lo + hi; }
            *(float4*)(pa + i * 8)     = make_float4(av[0], av[1], av[2], av[3]);
            *(float4*)(pa + i * 8 + 4) = make_float4(av[4], av[5], av[6], av[7]);
        }
    }
}

// ---------------- attention pass 2: sum 4 partials, normalize ---------------
__global__ __launch_bounds__(256) void attn_p2_kernel()
{
    int idx = blockIdx.x * 256 + threadIdx.x;   // 32768 threads
    int bh = idx >> 8;
    int r  = idx & 255;
    int qh = r >> 7;
    int t  = r & 127;
    int b = bh >> 5;
    int h = bh & 31;

    float L[4] = {0.f, 0.f, 0.f, 0.f};
    float c[4][8];
    #pragma unroll
    for (int i = 0; i < 4; i++)
        #pragma unroll
        for (int j = 0; j < 8; j++) c[i][j] = 0.f;

    #pragma unroll
    for (int kq = 0; kq < 4; kq++) {
        int pidx = ((bh * 4 + kq) * 2 + qh) * 128 + t;
        float4 lv = *(const float4*)(g_plf + pidx * 4);
        L[0] += lv.x; L[1] += lv.y; L[2] += lv.z; L[3] += lv.w;
        const float4* pa = (const float4*)(g_paccf + (size_t)pidx * 32);
        #pragma unroll
        for (int i = 0; i < 4; i++) {
            float4 a0 = pa[2 * i], a1 = pa[2 * i + 1];
            c[i][0] += a0.x; c[i][1] += a0.y; c[i][2] += a0.z; c[i][3] += a0.w;
            c[i][4] += a1.x; c[i][5] += a1.y; c[i][6] += a1.z; c[i][7] += a1.w;
        }
    }

    #pragma unroll
    for (int i = 0; i < 4; i++) {
        float rr = 1.f / L[i];
        int q = qh * 512 + t + i * 128;
        float* o = g_ctx + ((size_t)b * S_ + q) * E_ + h * DK_;
        *(float4*)(o)     = make_float4(c[i][0] * rr, c[i][1] * rr, c[i][2] * rr, c[i][3] * rr);
        *(float4*)(o + 4) = make_float4(c[i][4] * rr, c[i][5] * rr, c[i][6] * rr, c[i][7] * rr);
    }
}

// ---------------- layernorm: out = LN(a + b) * g + beta  (warp per row) -----
__global__ __launch_bounds__(256) void ln_kernel(
    const float* __restrict__ a, const float* __restrict__ bsrc,
    const float* __restrict__ g, const float* __restrict__ beta,
    float* __restrict__ out)
{
    int row  = (blockIdx.x * 256 + threadIdx.x) >> 5;
    int lane = threadIdx.x & 31;
    size_t off = (size_t)row * E_ + lane * 8;

    const float4* ap = (const float4*)(a + off);
    const float4* bp = (const float4*)(bsrc + off);
    float4 a0 = ap[0], a1 = ap[1], b0 = bp[0], b1 = bp[1];
    float v[8];
    v[0] = a0.x + b0.x; v[1] = a0.y + b0.y; v[2] = a0.z + b0.z; v[3] = a0.w + b0.w;
    v[4] = a1.x + b1.x; v[5] = a1.y + b1.y; v[6] = a1.z + b1.z; v[7] = a1.w + b1.w;

    float s = 0.f, ss = 0.f;
    #pragma unroll
    for (int i = 0; i < 8; i++) { s += v[i]; ss = fmaf(v[i], v[i], ss); }
    #pragma unroll
    for (int o = 16; o > 0; o >>= 1) {
        s  += __shfl_xor_sync(0xFFFFFFFFu, s,  o);
        ss += __shfl_xor_sync(0xFFFFFFFFu, ss, o);
    }
    float mu  = s * (1.f / E_);
    float var = ss * (1.f / E_) - mu * mu;
    float rs  = rsqrtf(var + 1e-5f);

    const float4* gp  = (const float4*)(g    + lane * 8);
    const float4* bep = (const float4*)(beta + lane * 8);
    float4 g0 = gp[0], g1v = gp[1], e0 = bep[0], e1 = bep[1];

    float4 w;
    w.x = (v[0]-mu)*rs*g0.x + e0.x; w.y = (v[1]-mu)*rs*g0.y + e0.y;
    w.z = (v[2]-mu)*rs*g0.z + e0.z; w.w = (v[3]-mu)*rs*g0.w + e0.w;
    *(float4*)(out + off) = w;
    w.x = (v[4]-mu)*rs*g1v.x + e1.x; w.y = (v[5]-mu)*rs*g1v.y + e1.y;
    w.z = (v[6]-mu)*rs*g1v.z + e1.z; w.w = (v[7]-mu)*rs*g1v.w + e1.w;
    *(float4*)(out + off + 4) = w;
}

// ---------------- qf = cos(theta)*cos(h @ w_ip^T + b_ip), warp per row ------
__global__ __launch_bounds__(256) void qf_kernel(
    const float* __restrict__ w_ip, const float* __restrict__ b_ip,
    const float* __restrict__ theta_ffn)
{
    int tid = threadIdx.x;
    int m = blockIdx.x * 8 + (tid >> 5);
    int lane = tid & 31;
    int j = lane >> 2, p = lane & 3;
    const float* hr = g_h + (size_t)m * E_ + p * 64;
    const float* wr = w_ip + (size_t)j * E_ + p * 64;
    ULL acc = 0ULL;
    #pragma unroll
    for (int i = 0; i < 64; i += 8) {
        float4 hA = *(const float4*)(hr + i);
        float4 hB = *(const float4*)(hr + i + 4);
        float4 wA = *(const float4*)(wr + i);
        float4 wB = *(const float4*)(wr + i + 4);
        acc = fma2(pk(hA.x, hA.y), pk(wA.x, wA.y), acc);
        acc = fma2(pk(hA.z, hA.w), pk(wA.z, wA.w), acc);
        acc = fma2(pk(hB.x, hB.y), pk(wB.x, wB.y), acc);
        acc = fma2(pk(hB.z, hB.w), pk(wB.z, wB.w), acc);
    }
    float s0, s1;
    unpk(acc, s0, s1);
    float s = s0 + s1;
    s += __shfl_xor_sync(0xFFFFFFFFu, s, 1);
    s += __shfl_xor_sync(0xFFFFFFFFu, s, 2);
    if (p == 0)
        g_qf[m * NQ_ + j] = __cosf(theta_ffn[j]) * __cosf(s + b_ip[j]);
}

// ---------------- launch ----------------------------------------------------
extern "C" void kernel_launch(void* const* d_in, const int* in_sizes, int n_in,
                              void* d_out, int out_size)
{
    (void)in_sizes; (void)n_in; (void)out_size;

    const float* x          = (const float*)d_in[0];
    const float* theta_attn = (const float*)d_in[1];
    const float* w_in       = (const float*)d_in[2];
    const float* b_in       = (const float*)d_in[3];
    const float* w_out      = (const float*)d_in[4];
    const float* b_out      = (const float*)d_in[5];
    const float* w_comb     = (const float*)d_in[6];
    const float* b_comb     = (const float*)d_in[7];
    const float* g1         = (const float*)d_in[8];
    const float* be1        = (const float*)d_in[9];
    const float* g2         = (const float*)d_in[10];
    const float* be2        = (const float*)d_in[11];
    const float* w_ip       = (const float*)d_in[12];
    const float* b_ip       = (const float*)d_in[13];
    const float* theta_ffn  = (const float*)d_in[14];
    const float* w1         = (const float*)d_in[15];
    const float* b1         = (const float*)d_in[16];
    const float* w2         = (const float*)d_in[17];
    const float* b2         = (const float*)d_in[18];
    float* out = (float*)d_out;

    float *p_qkv, *p_ctx, *p_Wf, *p_bf, *p_tmp, *p_h;
    cudaGetSymbolAddress((void**)&p_qkv,  g_qkv);
    cudaGetSymbolAddress((void**)&p_ctx,  g_ctx);
    cudaGetSymbolAddress((void**)&p_Wf,   g_Wf);
    cudaGetSymbolAddress((void**)&p_bf,   g_bf);
    cudaGetSymbolAddress((void**)&p_tmp,  g_tmp);
    cudaGetSymbolAddress((void**)&p_h,    g_h);

    // 1. fold w_comb @ w_out ; pack w1/b1 pairs (independent of main chain)
    fold_w_kernel<<<E_, 256>>>(w_comb, w_out, b_out, b_comb);
    pack_w1_kernel<<<18, 256>>>(w1, b1);

    // 2. qkv = cos(x + theta) @ w_in^T + b_in   [4096 x 768], fused cos
    {
        dim3 grid((3 * E_) / 64, M_ / 128);
        sgemm_qkv_kernel<<<grid, 256>>>(x, theta_attn, w_in, b_in, p_qkv,
                                        M_, 3 * E_, E_);
    }

    // 3a. attention pass 1 (split-K partials, keys-packed)
    {
        dim3 grid(4, 2, B_ * H_);
        attn_p1_kernel<<<grid, 128>>>();
    }
    // 3b. attention pass 2 (sum + normalize) -> ctx
    attn_p2_kernel<<<128, 256>>>();

    // 4. attn_out = ctx @ Wf^T + bf       [4096 x 256]
    {
        dim3 grid(E_ / 64, M_ / 128);
        sgemm2_kernel<<<grid, 256>>>(p_ctx, p_Wf, p_bf, p_tmp, M_, E_, E_);
    }

    // 5. h = LN(x + attn_out) * g1 + be1
    ln_kernel<<<M_ / 8, 256>>>(x, p_tmp, g1, be1, p_h);

    // 6. qf = cos(theta_ffn) * cos(h @ w_ip^T + b_ip)
    qf_kernel<<<M_ / 8, 256>>>(w_ip, b_ip, theta_ffn);

    // 7. ffn_out = relu(qf @ w1^T + b1) @ w2^T + b2   (fused hidden)
    {
        dim3 grid(E_ / 64, M_ / 128);
        sgemm_ffn_kernel<<<grid, 256>>>(w2, b2, p_tmp);
    }

    // 8. out = LN(h + ffn_out) * g2 + be2
    ln_kernel<<<M_ / 8, 256>>>(p_h, p_tmp, g2, be2, out);
}

// round 11
// speedup vs baseline: 1.0504x; 1.0504x over previous
#include <cuda_runtime.h>
#include <math.h>
#include <stdint.h>

// Problem constants
#define B_   4
#define S_   1024
#define E_   256
#define H_   32
#define DK_  8
#define NQ_  8
#define FF_  1024
#define M_   (B_ * S_)   // 4096

typedef unsigned long long ULL;

// ---------------- f32x2 packed math helpers (PTX-only on sm_103a) ----------
__device__ __forceinline__ ULL fma2(ULL a, ULL b, ULL c) {
    ULL d; asm("fma.rn.f32x2 %0, %1, %2, %3;" : "=l"(d) : "l"(a), "l"(b), "l"(c)); return d;
}
__device__ __forceinline__ ULL mul2(ULL a, ULL b) {
    ULL d; asm("mul.rn.f32x2 %0, %1, %2;" : "=l"(d) : "l"(a), "l"(b)); return d;
}
__device__ __forceinline__ ULL add2(ULL a, ULL b) {
    ULL d; asm("add.rn.f32x2 %0, %1, %2;" : "=l"(d) : "l"(a), "l"(b)); return d;
}
__device__ __forceinline__ ULL pk(float lo, float hi) {
    ULL r; asm("mov.b64 %0, {%1, %2};" : "=l"(r) : "f"(lo), "f"(hi)); return r;
}
__device__ __forceinline__ void unpk(ULL v, float& lo, float& hi) {
    asm("mov.b64 {%0, %1}, %2;" : "=f"(lo), "=f"(hi) : "l"(v));
}
__device__ __forceinline__ float ex2f_(float x) {
    float y; asm("ex2.approx.f32 %0, %1;" : "=f"(y) : "f"(x)); return y;
}

// ---------------- scratch (device globals; no runtime allocation) ----------
__device__ __align__(16) float g_qout[M_ * E_];
__device__ __align__(16) float g_qkv[M_ * 3 * E_];
__device__ __align__(16) float g_ctx[M_ * E_];
__device__ __align__(16) float g_Wf[E_ * E_];
__device__ __align__(16) float g_bf[E_];
__device__ __align__(16) float g_tmp[M_ * E_];
__device__ __align__(16) float g_h[M_ * E_];
__device__ __align__(16) float g_qf[M_ * NQ_];
__device__ __align__(16) float g_hidden[M_ * FF_];
// split-K attention partials (plain floats; lo/hi combined in pass 1)
// pidx = ((bh*2 + kq)*2 + qh)*128 + t ; queries qh*512 + t + {0,128,256,384}
__device__ __align__(16) float g_plf[65536 * 4];
__device__ __align__(16) float g_paccf[(size_t)65536 * 32];

// ---------------- q_out = cos(x + theta[e % 8]), float4 --------------------
__global__ __launch_bounds__(256) void cos_encode_kernel(
    const float* __restrict__ x, const float* __restrict__ theta)
{
    int i = (blockIdx.x * 256 + threadIdx.x) * 4;
    float4 v = *(const float4*)(x + i);
    int j = i & 7;
    v.x = __cosf(v.x + theta[j + 0]);
    v.y = __cosf(v.y + theta[j + 1]);
    v.z = __cosf(v.z + theta[j + 2]);
    v.w = __cosf(v.w + theta[j + 3]);
    *(float4*)(g_qout + i) = v;
}

// ---------------- fold: Wf = w_comb @ w_out, bf = w_comb@b_out + b_comb -----
__global__ __launch_bounds__(256) void fold_w_kernel(
    const float* __restrict__ w_comb, const float* __restrict__ w_out,
    const float* __restrict__ b_out, const float* __restrict__ b_comb)
{
    int i = blockIdx.x;
    int j = threadIdx.x;
    float s = 0.f;
    #pragma unroll 8
    for (int k = 0; k < E_; k++)
        s = fmaf(w_comb[i * E_ + k], w_out[k * E_ + j], s);
    g_Wf[i * E_ + j] = s;

    __shared__ float red[256];
    red[j] = w_comb[i * E_ + j] * b_out[j];
    __syncthreads();
    #pragma unroll
    for (int off = 128; off > 0; off >>= 1) {
        if (j < off) red[j] += red[j + off];
        __syncthreads();
    }
    if (j == 0) g_bf[i] = red[0] + b_comb[i];
}

// ---------------- f32x2 SGEMM (R5): C = A @ Bw^T + bias --------------------
// BM=128, BN=64, BK=16, 256 threads, 8x4 microtile.
__global__ __launch_bounds__(256) void sgemm2_kernel(
    const float* __restrict__ A, const float* __restrict__ Bw,
    const float* __restrict__ bias, float* __restrict__ C,
    int M, int N, int K)
{
    __shared__ float As[16][132];
    __shared__ float Bs[16][68];

    int tid = threadIdx.x;
    int bm = blockIdx.y * 128;
    int bn = blockIdx.x * 64;
    int ty = tid >> 4;
    int tx = tid & 15;

    int alr = tid >> 1;
    int alc = (tid & 1) * 8;
    int blr = tid >> 2;
    int blc = (tid & 3) * 4;

    const float* Aptr = A  + (size_t)(bm + alr) * K + alc;
    const float* Bptr = Bw + (size_t)(bn + blr) * K + blc;

    float4 a0 = *(const float4*)(Aptr);
    float4 a1 = *(const float4*)(Aptr + 4);
    float4 b0 = *(const float4*)(Bptr);

    ULL acc[4][4];
    #pragma unroll
    for (int r = 0; r < 4; r++)
        #pragma unroll
        for (int j = 0; j < 4; j++) acc[r][j] = 0ULL;

    for (int k0 = 0; ; k0 += 16) {
        As[alc + 0][alr] = a0.x; As[alc + 1][alr] = a0.y;
        As[alc + 2][alr] = a0.z; As[alc + 3][alr] = a0.w;
        As[alc + 4][alr] = a1.x; As[alc + 5][alr] = a1.y;
        As[alc + 6][alr] = a1.z; As[alc + 7][alr] = a1.w;
        Bs[blc + 0][blr] = b0.x; Bs[blc + 1][blr] = b0.y;
        Bs[blc + 2][blr] = b0.z; Bs[blc + 3][blr] = b0.w;
        __syncthreads();

        bool last = (k0 + 16 >= K);
        if (!last) {
            Aptr += 16; Bptr += 16;
            a0 = *(const float4*)(Aptr);
            a1 = *(const float4*)(Aptr + 4);
            b0 = *(const float4*)(Bptr);
        }

        #pragma unroll
        for (int kk = 0; kk < 16; kk++) {
            ulonglong2 am0 = *(const ulonglong2*)&As[kk][ty * 8];
            ulonglong2 am1 = *(const ulonglong2*)&As[kk][ty * 8 + 4];
            float4 b4 = *(const float4*)&Bs[kk][tx * 4];
            ULL bb0 = pk(b4.x, b4.x), bb1 = pk(b4.y, b4.y);
            ULL bb2 = pk(b4.z, b4.z), bb3 = pk(b4.w, b4.w);
            ULL am[4] = {am0.x, am0.y, am1.x, am1.y};
            #pragma unroll
            for (int r = 0; r < 4; r++) {
                acc[r][0] = fma2(am[r], bb0, acc[r][0]);
                acc[r][1] = fma2(am[r], bb1, acc[r][1]);
                acc[r][2] = fma2(am[r], bb2, acc[r][2]);
                acc[r][3] = fma2(am[r], bb3, acc[r][3]);
            }
        }
        if (last) break;
        __syncthreads();
    }

    int col = bn + tx * 4;
    float4 bb = *(const float4*)(bias + col);
    #pragma unroll
    for (int r = 0; r < 4; r++) {
        float lo0, hi0, lo1, hi1, lo2v, hi2, lo3, hi3;
        unpk(acc[r][0], lo0, hi0);
        unpk(acc[r][1], lo1, hi1);
        unpk(acc[r][2], lo2v, hi2);
        unpk(acc[r][3], lo3, hi3);
        int row0 = bm + ty * 8 + 2 * r;
        *(float4*)(C + (size_t)row0 * N + col) =
            make_float4(lo0 + bb.x, lo1 + bb.y, lo2v + bb.z, lo3 + bb.w);
        *(float4*)(C + (size_t)(row0 + 1) * N + col) =
            make_float4(hi0 + bb.x, hi1 + bb.y, hi2 + bb.z, hi3 + bb.w);
    }
}

// ---------------- attention pass 1: keys-packed, no-max softmax -------------
// grid = (2 key-halves, 2 query-halves, 128 bh), 128 threads.
// K/V packed across ADJACENT KEY PAIRS in smem (32 KB, 512 keys);
// 4 queries/thread duplicated in registers. 512 CTAs -> one full wave.
__global__ __launch_bounds__(128) void attn_p1_kernel()
{
    __shared__ ULL Kp[256 * 8];   // 16 KB: Kp[sp*8+c] = (k_{2sp}[c], k_{2sp+1}[c])
    __shared__ ULL Vp[256 * 8];   // 16 KB

    int kq = blockIdx.x;
    int qh = blockIdx.y;
    int bh = blockIdx.z;
    int b = bh >> 5;
    int h = bh & 31;
    int t = threadIdx.x;
    const float* base = g_qkv + (size_t)b * S_ * (3 * E_) + h * DK_;

    // stage: 2 pair-stages, thread t packs keys (2sp, 2sp+1)
    #pragma unroll
    for (int rep = 0; rep < 2; rep++) {
        int sp = rep * 128 + t;
        const float* ra = base + (size_t)(kq * 512 + 2 * sp) * (3 * E_);
        const float* rb = ra + 3 * E_;
        float4 ka0 = *(const float4*)(ra + E_);
        float4 ka1 = *(const float4*)(ra + E_ + 4);
        float4 kb0 = *(const float4*)(rb + E_);
        float4 kb1 = *(const float4*)(rb + E_ + 4);
        ulonglong2* kw = (ulonglong2*)(Kp + sp * 8);
        kw[0] = make_ulonglong2(pk(ka0.x, kb0.x), pk(ka0.y, kb0.y));
        kw[1] = make_ulonglong2(pk(ka0.z, kb0.z), pk(ka0.w, kb0.w));
        kw[2] = make_ulonglong2(pk(ka1.x, kb1.x), pk(ka1.y, kb1.y));
        kw[3] = make_ulonglong2(pk(ka1.z, kb1.z), pk(ka1.w, kb1.w));
        float4 va0 = *(const float4*)(ra + 2 * E_);
        float4 va1 = *(const float4*)(ra + 2 * E_ + 4);
        float4 vb0 = *(const float4*)(rb + 2 * E_);
        float4 vb1 = *(const float4*)(rb + 2 * E_ + 4);
        ulonglong2* vw = (ulonglong2*)(Vp + sp * 8);
        vw[0] = make_ulonglong2(pk(va0.x, vb0.x), pk(va0.y, vb0.y));
        vw[1] = make_ulonglong2(pk(va0.z, vb0.z), pk(va0.w, vb0.w));
        vw[2] = make_ulonglong2(pk(va1.x, vb1.x), pk(va1.y, vb1.y));
        vw[3] = make_ulonglong2(pk(va1.z, vb1.z), pk(va1.w, vb1.w));
    }
    __syncthreads();

    const float qscale = 0.35355339059327373f * 1.4426950408889634f; // log2e/sqrt(8)

    // 4 queries duplicated in regs: qd[i][c] = (q_i[c]*s, q_i[c]*s)
    ULL qd[4][8];
    #pragma unroll
    for (int i = 0; i < 4; i++) {
        const float* r = base + (size_t)(qh * 512 + t + i * 128) * (3 * E_);
        float4 q0 = *(const float4*)(r);
        float4 q1 = *(const float4*)(r + 4);
        float s;
        s = q0.x * qscale; qd[i][0] = pk(s, s);
        s = q0.y * qscale; qd[i][1] = pk(s, s);
        s = q0.z * qscale; qd[i][2] = pk(s, s);
        s = q0.w * qscale; qd[i][3] = pk(s, s);
        s = q1.x * qscale; qd[i][4] = pk(s, s);
        s = q1.y * qscale; qd[i][5] = pk(s, s);
        s = q1.z * qscale; qd[i][6] = pk(s, s);
        s = q1.w * qscale; qd[i][7] = pk(s, s);
    }

    ULL l[4] = {0ULL, 0ULL, 0ULL, 0ULL};
    ULL acc[4][8];
    #pragma unroll
    for (int i = 0; i < 4; i++)
        #pragma unroll
        for (int c = 0; c < 8; c++) acc[i][c] = 0ULL;

    #pragma unroll 1
    for (int sp = 0; sp < 256; sp++) {
        const ulonglong2* kr = (const ulonglong2*)(Kp + sp * 8);
        ulonglong2 k01 = kr[0], k23 = kr[1], k45 = kr[2], k67 = kr[3];

        ULL t0 = mul2(qd[0][0], k01.x);
        ULL t1 = mul2(qd[1][0], k01.x);
        ULL t2 = mul2(qd[2][0], k01.x);
        ULL t3 = mul2(qd[3][0], k01.x);
        t0 = fma2(qd[0][1], k01.y, t0);
        t1 = fma2(qd[1][1], k01.y, t1);
        t2 = fma2(qd[2][1], k01.y, t2);
        t3 = fma2(qd[3][1], k01.y, t3);
        t0 = fma2(qd[0][2], k23.x, t0);
        t1 = fma2(qd[1][2], k23.x, t1);
        t2 = fma2(qd[2][2], k23.x, t2);
        t3 = fma2(qd[3][2], k23.x, t3);
        t0 = fma2(qd[0][3], k23.y, t0);
        t1 = fma2(qd[1][3], k23.y, t1);
        t2 = fma2(qd[2][3], k23.y, t2);
        t3 = fma2(qd[3][3], k23.y, t3);
        t0 = fma2(qd[0][4], k45.x, t0);
        t1 = fma2(qd[1][4], k45.x, t1);
        t2 = fma2(qd[2][4], k45.x, t2);
        t3 = fma2(qd[3][4], k45.x, t3);
        t0 = fma2(qd[0][5], k45.y, t0);
        t1 = fma2(qd[1][5], k45.y, t1);
        t2 = fma2(qd[2][5], k45.y, t2);
        t3 = fma2(qd[3][5], k45.y, t3);
        t0 = fma2(qd[0][6], k67.x, t0);
        t1 = fma2(qd[1][6], k67.x, t1);
        t2 = fma2(qd[2][6], k67.x, t2);
        t3 = fma2(qd[3][6], k67.x, t3);
        t0 = fma2(qd[0][7], k67.y, t0);
        t1 = fma2(qd[1][7], k67.y, t1);
        t2 = fma2(qd[2][7], k67.y, t2);
        t3 = fma2(qd[3][7], k67.y, t3);

        float d0, d1;
        unpk(t0, d0, d1);
        ULL pp0 = pk(ex2f_(d0), ex2f_(d1));
        unpk(t1, d0, d1);
        ULL pp1 = pk(ex2f_(d0), ex2f_(d1));
        unpk(t2, d0, d1);
        ULL pp2 = pk(ex2f_(d0), ex2f_(d1));
        unpk(t3, d0, d1);
        ULL pp3 = pk(ex2f_(d0), ex2f_(d1));
        l[0] = add2(l[0], pp0);
        l[1] = add2(l[1], pp1);
        l[2] = add2(l[2], pp2);
        l[3] = add2(l[3], pp3);

        const ulonglong2* vr = (const ulonglong2*)(Vp + sp * 8);
        ulonglong2 v01 = vr[0], v23 = vr[1], v45 = vr[2], v67 = vr[3];
        acc[0][0] = fma2(pp0, v01.x, acc[0][0]);
        acc[1][0] = fma2(pp1, v01.x, acc[1][0]);
        acc[2][0] = fma2(pp2, v01.x, acc[2][0]);
        acc[3][0] = fma2(pp3, v01.x, acc[3][0]);
        acc[0][1] = fma2(pp0, v01.y, acc[0][1]);
        acc[1][1] = fma2(pp1, v01.y, acc[1][1]);
        acc[2][1] = fma2(pp2, v01.y, acc[2][1]);
        acc[3][1] = fma2(pp3, v01.y, acc[3][1]);
        acc[0][2] = fma2(pp0, v23.x, acc[0][2]);
        acc[1][2] = fma2(pp1, v23.x, acc[1][2]);
        acc[2][2] = fma2(pp2, v23.x, acc[2][2]);
        acc[3][2] = fma2(pp3, v23.x, acc[3][2]);
        acc[0][3] = fma2(pp0, v23.y, acc[0][3]);
        acc[1][3] = fma2(pp1, v23.y, acc[1][3]);
        acc[2][3] = fma2(pp2, v23.y, acc[2][3]);
        acc[3][3] = fma2(pp3, v23.y, acc[3][3]);
        acc[0][4] = fma2(pp0, v45.x, acc[0][4]);
        acc[1][4] = fma2(pp1, v45.x, acc[1][4]);
        acc[2][4] = fma2(pp2, v45.x, acc[2][4]);
        acc[3][4] = fma2(pp3, v45.x, acc[3][4]);
        acc[0][5] = fma2(pp0, v45.y, acc[0][5]);
        acc[1][5] = fma2(pp1, v45.y, acc[1][5]);
        acc[2][5] = fma2(pp2, v45.y, acc[2][5]);
        acc[3][5] = fma2(pp3, v45.y, acc[3][5]);
        acc[0][6] = fma2(pp0, v67.x, acc[0][6]);
        acc[1][6] = fma2(pp1, v67.x, acc[1][6]);
        acc[2][6] = fma2(pp2, v67.x, acc[2][6]);
        acc[3][6] = fma2(pp3, v67.x, acc[3][6]);
        acc[0][7] = fma2(pp0, v67.y, acc[0][7]);
        acc[1][7] = fma2(pp1, v67.y, acc[1][7]);
        acc[2][7] = fma2(pp2, v67.y, acc[2][7]);
        acc[3][7] = fma2(pp3, v67.y, acc[3][7]);
    }

    // fold packed even/odd halves and write float partials
    int pidx = ((bh * 2 + kq) * 2 + qh) * 128 + t;
    {
        float lo, hi;
        float lv[4];
        #pragma unroll
        for (int i = 0; i < 4; i++) { unpk(l[i], lo, hi); lv[i] = lo + hi; }
        *(float4*)(g_plf + pidx * 4) = make_float4(lv[0], lv[1], lv[2], lv[3]);
        float* pa = g_paccf + (size_t)pidx * 32;
        #pragma unroll
        for (int i = 0; i < 4; i++) {
            float av[8];
            #pragma unroll
            for (int c = 0; c < 8; c++) { unpk(acc[i][c], lo, hi); av[c] = lo + hi; }
            *(float4*)(pa + i * 8)     = make_float4(av[0], av[1], av[2], av[3]);
            *(float4*)(pa + i * 8 + 4) = make_float4(av[4], av[5], av[6], av[7]);
        }
    }
}

// ---------------- attention pass 2: sum 2 partials, normalize ---------------
__global__ __launch_bounds__(256) void attn_p2_kernel()
{
    int idx = blockIdx.x * 256 + threadIdx.x;   // 32768 threads
    int bh = idx >> 8;
    int r  = idx & 255;
    int qh = r >> 7;
    int t  = r & 127;
    int b = bh >> 5;
    int h = bh & 31;

    float L[4] = {0.f, 0.f, 0.f, 0.f};
    float c[4][8];
    #pragma unroll
    for (int i = 0; i < 4; i++)
        #pragma unroll
        for (int j = 0; j < 8; j++) c[i][j] = 0.f;

    #pragma unroll
    for (int kq = 0; kq < 2; kq++) {
        int pidx = ((bh * 2 + kq) * 2 + qh) * 128 + t;
        float4 lv = *(const float4*)(g_plf + pidx * 4);
        L[0] += lv.x; L[1] += lv.y; L[2] += lv.z; L[3] += lv.w;
        const float4* pa = (const float4*)(g_paccf + (size_t)pidx * 32);
        #pragma unroll
        for (int i = 0; i < 4; i++) {
            float4 a0 = pa[2 * i], a1 = pa[2 * i + 1];
            c[i][0] += a0.x; c[i][1] += a0.y; c[i][2] += a0.z; c[i][3] += a0.w;
            c[i][4] += a1.x; c[i][5] += a1.y; c[i][6] += a1.z; c[i][7] += a1.w;
        }
    }

    #pragma unroll
    for (int i = 0; i < 4; i++) {
        float rr = 1.f / L[i];
        int q = qh * 512 + t + i * 128;
        float* o = g_ctx + ((size_t)b * S_ + q) * E_ + h * DK_;
        *(float4*)(o)     = make_float4(c[i][0] * rr, c[i][1] * rr, c[i][2] * rr, c[i][3] * rr);
        *(float4*)(o + 4) = make_float4(c[i][4] * rr, c[i][5] * rr, c[i][6] * rr, c[i][7] * rr);
    }
}

// ---------------- layernorm: out = LN(a + b) * g + beta  (warp per row) -----
__global__ __launch_bounds__(256) void ln_kernel(
    const float* __restrict__ a, const float* __restrict__ bsrc,
    const float* __restrict__ g, const float* __restrict__ beta,
    float* __restrict__ out)
{
    int row  = (blockIdx.x * 256 + threadIdx.x) >> 5;
    int lane = threadIdx.x & 31;
    size_t off = (size_t)row * E_ + lane * 8;

    const float4* ap = (const float4*)(a + off);
    const float4* bp = (const float4*)(bsrc + off);
    float4 a0 = ap[0], a1 = ap[1], b0 = bp[0], b1 = bp[1];
    float v[8];
    v[0] = a0.x + b0.x; v[1] = a0.y + b0.y; v[2] = a0.z + b0.z; v[3] = a0.w + b0.w;
    v[4] = a1.x + b1.x; v[5] = a1.y + b1.y; v[6] = a1.z + b1.z; v[7] = a1.w + b1.w;

    float s = 0.f, ss = 0.f;
    #pragma unroll
    for (int i = 0; i < 8; i++) { s += v[i]; ss = fmaf(v[i], v[i], ss); }
    #pragma unroll
    for (int o = 16; o > 0; o >>= 1) {
        s  += __shfl_xor_sync(0xFFFFFFFFu, s,  o);
        ss += __shfl_xor_sync(0xFFFFFFFFu, ss, o);
    }
    float mu  = s * (1.f / E_);
    float var = ss * (1.f / E_) - mu * mu;
    float rs  = rsqrtf(var + 1e-5f);

    const float4* gp  = (const float4*)(g    + lane * 8);
    const float4* bep = (const float4*)(beta + lane * 8);
    float4 g0 = gp[0], g1v = gp[1], e0 = bep[0], e1 = bep[1];

    float4 w;
    w.x = (v[0]-mu)*rs*g0.x + e0.x; w.y = (v[1]-mu)*rs*g0.y + e0.y;
    w.z = (v[2]-mu)*rs*g0.z + e0.z; w.w = (v[3]-mu)*rs*g0.w + e0.w;
    *(float4*)(out + off) = w;
    w.x = (v[4]-mu)*rs*g1v.x + e1.x; w.y = (v[5]-mu)*rs*g1v.y + e1.y;
    w.z = (v[6]-mu)*rs*g1v.z + e1.z; w.w = (v[7]-mu)*rs*g1v.w + e1.w;
    *(float4*)(out + off + 4) = w;
}

// ---------------- qf = cos(theta)*cos(h @ w_ip^T + b_ip), warp per row ------
__global__ __launch_bounds__(256) void qf_kernel(
    const float* __restrict__ w_ip, const float* __restrict__ b_ip,
    const float* __restrict__ theta_ffn)
{
    int tid = threadIdx.x;
    int m = blockIdx.x * 8 + (tid >> 5);
    int lane = tid & 31;
    int j = lane >> 2, p = lane & 3;
    const float* hr = g_h + (size_t)m * E_ + p * 64;
    const float* wr = w_ip + (size_t)j * E_ + p * 64;
    ULL acc = 0ULL;
    #pragma unroll
    for (int i = 0; i < 64; i += 8) {
        float4 hA = *(const float4*)(hr + i);
        float4 hB = *(const float4*)(hr + i + 4);
        float4 wA = *(const float4*)(wr + i);
        float4 wB = *(const float4*)(wr + i + 4);
        acc = fma2(pk(hA.x, hA.y), pk(wA.x, wA.y), acc);
        acc = fma2(pk(hA.z, hA.w), pk(wA.z, wA.w), acc);
        acc = fma2(pk(hB.x, hB.y), pk(wB.x, wB.y), acc);
        acc = fma2(pk(hB.z, hB.w), pk(wB.z, wB.w), acc);
    }
    float s0, s1;
    unpk(acc, s0, s1);
    float s = s0 + s1;
    s += __shfl_xor_sync(0xFFFFFFFFu, s, 1);
    s += __shfl_xor_sync(0xFFFFFFFFu, s, 2);
    if (p == 0)
        g_qf[m * NQ_ + j] = __cosf(theta_ffn[j]) * __cosf(s + b_ip[j]);
}

// ---------------- hidden = relu(qf @ w1^T + b1)   (K=8) ---------------------
__global__ __launch_bounds__(256) void hidden_kernel(
    const float* __restrict__ w1, const float* __restrict__ b1)
{
    int m = blockIdx.x >> 2;
    int f = ((blockIdx.x & 3) << 8) + threadIdx.x;
    const float* qr = g_qf + (size_t)m * NQ_;
    const float* wr = w1 + (size_t)f * NQ_;
    float s = b1[f];
    #pragma unroll
    for (int j = 0; j < NQ_; j++)
        s = fmaf(qr[j], wr[j], s);
    g_hidden[(size_t)m * FF_ + f] = fmaxf(s, 0.f);
}

// ---------------- launch ----------------------------------------------------
extern "C" void kernel_launch(void* const* d_in, const int* in_sizes, int n_in,
                              void* d_out, int out_size)
{
    (void)in_sizes; (void)n_in; (void)out_size;

    const float* x          = (const float*)d_in[0];
    const float* theta_attn = (const float*)d_in[1];
    const float* w_in       = (const float*)d_in[2];
    const float* b_in       = (const float*)d_in[3];
    const float* w_out      = (const float*)d_in[4];
    const float* b_out      = (const float*)d_in[5];
    const float* w_comb     = (const float*)d_in[6];
    const float* b_comb     = (const float*)d_in[7];
    const float* g1         = (const float*)d_in[8];
    const float* be1        = (const float*)d_in[9];
    const float* g2         = (const float*)d_in[10];
    const float* be2        = (const float*)d_in[11];
    const float* w_ip       = (const float*)d_in[12];
    const float* b_ip       = (const float*)d_in[13];
    const float* theta_ffn  = (const float*)d_in[14];
    const float* w1         = (const float*)d_in[15];
    const float* b1         = (const float*)d_in[16];
    const float* w2         = (const float*)d_in[17];
    const float* b2         = (const float*)d_in[18];
    float* out = (float*)d_out;

    float *p_qout, *p_qkv, *p_ctx, *p_Wf, *p_bf, *p_tmp, *p_h, *p_hidden;
    cudaGetSymbolAddress((void**)&p_qout,   g_qout);
    cudaGetSymbolAddress((void**)&p_qkv,    g_qkv);
    cudaGetSymbolAddress((void**)&p_ctx,    g_ctx);
    cudaGetSymbolAddress((void**)&p_Wf,     g_Wf);
    cudaGetSymbolAddress((void**)&p_bf,     g_bf);
    cudaGetSymbolAddress((void**)&p_tmp,    g_tmp);
    cudaGetSymbolAddress((void**)&p_h,      g_h);
    cudaGetSymbolAddress((void**)&p_hidden, g_hidden);

    // 1. q_out = cos(x + theta)
    cos_encode_kernel<<<(M_ * E_) / 1024, 256>>>(x, theta_attn);

    // 2. fold w_comb @ w_out
    fold_w_kernel<<<E_, 256>>>(w_comb, w_out, b_out, b_comb);

    // 3. qkv = q_out @ w_in^T + b_in      [4096 x 768]
    {
        dim3 grid((3 * E_) / 64, M_ / 128);
        sgemm2_kernel<<<grid, 256>>>(p_qout, w_in, b_in, p_qkv, M_, 3 * E_, E_);
    }

    // 4a. attention pass 1 (split-K=2 partials, keys-packed, single wave)
    {
        dim3 grid(2, 2, B_ * H_);
        attn_p1_kernel<<<grid, 128>>>();
    }
    // 4b. attention pass 2 (sum + normalize) -> ctx
    attn_p2_kernel<<<128, 256>>>();

    // 5. attn_out = ctx @ Wf^T + bf       [4096 x 256]
    {
        dim3 grid(E_ / 64, M_ / 128);
        sgemm2_kernel<<<grid, 256>>>(p_ctx, p_Wf, p_bf, p_tmp, M_, E_, E_);
    }

    // 6. h = LN(x + attn_out) * g1 + be1
    ln_kernel<<<M_ / 8, 256>>>(x, p_tmp, g1, be1, p_h);

    // 7. qf = cos(theta_ffn) * cos(h @ w_ip^T + b_ip)
    qf_kernel<<<M_ / 8, 256>>>(w_ip, b_ip, theta_ffn);

    // 8. hidden = relu(qf @ w1^T + b1)    [4096 x 1024]
    hidden_kernel<<<M_ * 4, 256>>>(w1, b1);

    // 9. ffn_out = hidden @ w2^T + b2     [4096 x 256]
    {
        dim3 grid(E_ / 64, M_ / 128);
        sgemm2_kernel<<<grid, 256>>>(p_hidden, w2, b2, p_tmp, M_, E_, FF_);
    }

    // 10. out = LN(h + ffn_out) * g2 + be2
    ln_kernel<<<M_ / 8, 256>>>(p_h, p_tmp, g2, be2, out);
}

// round 12
// speedup vs baseline: 1.1057x; 1.0526x over previous
#include <cuda_runtime.h>
#include <math.h>
#include <stdint.h>

// Problem constants
#define B_   4
#define S_   1024
#define E_   256
#define H_   32
#define DK_  8
#define NQ_  8
#define FF_  1024
#define M_   (B_ * S_)   // 4096

typedef unsigned long long ULL;

// ---------------- f32x2 packed math helpers (PTX-only on sm_103a) ----------
__device__ __forceinline__ ULL fma2(ULL a, ULL b, ULL c) {
    ULL d; asm("fma.rn.f32x2 %0, %1, %2, %3;" : "=l"(d) : "l"(a), "l"(b), "l"(c)); return d;
}
__device__ __forceinline__ ULL mul2(ULL a, ULL b) {
    ULL d; asm("mul.rn.f32x2 %0, %1, %2;" : "=l"(d) : "l"(a), "l"(b)); return d;
}
__device__ __forceinline__ ULL add2(ULL a, ULL b) {
    ULL d; asm("add.rn.f32x2 %0, %1, %2;" : "=l"(d) : "l"(a), "l"(b)); return d;
}
__device__ __forceinline__ ULL pk(float lo, float hi) {
    ULL r; asm("mov.b64 %0, {%1, %2};" : "=l"(r) : "f"(lo), "f"(hi)); return r;
}
__device__ __forceinline__ void unpk(ULL v, float& lo, float& hi) {
    asm("mov.b64 {%0, %1}, %2;" : "=f"(lo), "=f"(hi) : "l"(v));
}
__device__ __forceinline__ float ex2f_(float x) {
    float y; asm("ex2.approx.f32 %0, %1;" : "=f"(y) : "f"(x)); return y;
}

// ---------------- scratch (device globals; no runtime allocation) ----------
__device__ __align__(16) float g_qout[M_ * E_];
__device__ __align__(16) float g_qkv[M_ * 3 * E_];
__device__ __align__(16) float g_ctx[M_ * E_];
__device__ __align__(16) float g_Wf[E_ * E_];
__device__ __align__(16) float g_bf[E_];
__device__ __align__(16) float g_tmp[M_ * E_];
__device__ __align__(16) float g_h[M_ * E_];
__device__ __align__(16) float g_qf[M_ * NQ_];
__device__ __align__(16) float g_hidden[M_ * FF_];
// split-K attention partials (plain floats; lo/hi combined in pass 1)
// pidx = ((bh*4 + kq)*2 + qh)*128 + t ; queries qh*512 + t + {0,128,256,384}
__device__ __align__(16) float g_plf[131072 * 4];
__device__ __align__(16) float g_paccf[(size_t)131072 * 32];

// ---------------- q_out = cos(x + theta[e % 8]), float4 --------------------
__global__ __launch_bounds__(256) void cos_encode_kernel(
    const float* __restrict__ x, const float* __restrict__ theta)
{
    int i = (blockIdx.x * 256 + threadIdx.x) * 4;
    float4 v = *(const float4*)(x + i);
    int j = i & 7;
    v.x = __cosf(v.x + theta[j + 0]);
    v.y = __cosf(v.y + theta[j + 1]);
    v.z = __cosf(v.z + theta[j + 2]);
    v.w = __cosf(v.w + theta[j + 3]);
    *(float4*)(g_qout + i) = v;
}

// ---------------- fold: Wf = w_comb @ w_out, bf = w_comb@b_out + b_comb -----
__global__ __launch_bounds__(256) void fold_w_kernel(
    const float* __restrict__ w_comb, const float* __restrict__ w_out,
    const float* __restrict__ b_out, const float* __restrict__ b_comb)
{
    int i = blockIdx.x;
    int j = threadIdx.x;
    float s = 0.f;
    #pragma unroll 8
    for (int k = 0; k < E_; k++)
        s = fmaf(w_comb[i * E_ + k], w_out[k * E_ + j], s);
    g_Wf[i * E_ + j] = s;

    __shared__ float red[256];
    red[j] = w_comb[i * E_ + j] * b_out[j];
    __syncthreads();
    #pragma unroll
    for (int off = 128; off > 0; off >>= 1) {
        if (j < off) red[j] += red[j + off];
        __syncthreads();
    }
    if (j == 0) g_bf[i] = red[0] + b_comb[i];
}

// ---------------- f32x2 SGEMM, double-buffered: C = A @ Bw^T + bias --------
// BM=128, BN=64, BK=16, 256 threads, 8x4 microtile, ONE sync per k-iter.
__global__ __launch_bounds__(256) void sgemm2_kernel(
    const float* __restrict__ A, const float* __restrict__ Bw,
    const float* __restrict__ bias, float* __restrict__ C,
    int M, int N, int K)
{
    __shared__ float As[2][16][132];
    __shared__ float Bs[2][16][68];

    int tid = threadIdx.x;
    int bm = blockIdx.y * 128;
    int bn = blockIdx.x * 64;
    int ty = tid >> 4;
    int tx = tid & 15;

    int alr = tid >> 1;
    int alc = (tid & 1) * 8;
    int blr = tid >> 2;
    int blc = (tid & 3) * 4;

    const float* Aptr = A  + (size_t)(bm + alr) * K + alc;
    const float* Bptr = Bw + (size_t)(bn + blr) * K + blc;

    float4 a0 = *(const float4*)(Aptr);
    float4 a1 = *(const float4*)(Aptr + 4);
    float4 b0 = *(const float4*)(Bptr);

    ULL acc[4][4];
    #pragma unroll
    for (int r = 0; r < 4; r++)
        #pragma unroll
        for (int j = 0; j < 4; j++) acc[r][j] = 0ULL;

    // stage tile 0 into buffer 0
    As[0][alc + 0][alr] = a0.x; As[0][alc + 1][alr] = a0.y;
    As[0][alc + 2][alr] = a0.z; As[0][alc + 3][alr] = a0.w;
    As[0][alc + 4][alr] = a1.x; As[0][alc + 5][alr] = a1.y;
    As[0][alc + 6][alr] = a1.z; As[0][alc + 7][alr] = a1.w;
    Bs[0][blc + 0][blr] = b0.x; Bs[0][blc + 1][blr] = b0.y;
    Bs[0][blc + 2][blr] = b0.z; Bs[0][blc + 3][blr] = b0.w;
    __syncthreads();

    int buf = 0;
    for (int k0 = 0; ; k0 += 16) {
        bool last = (k0 + 16 >= K);
        if (!last) {   // prefetch next tile into registers
            Aptr += 16; Bptr += 16;
            a0 = *(const float4*)(Aptr);
            a1 = *(const float4*)(Aptr + 4);
            b0 = *(const float4*)(Bptr);
        }

        #pragma unroll
        for (int kk = 0; kk < 16; kk++) {
            ulonglong2 am0 = *(const ulonglong2*)&As[buf][kk][ty * 8];
            ulonglong2 am1 = *(const ulonglong2*)&As[buf][kk][ty * 8 + 4];
            float4 b4 = *(const float4*)&Bs[buf][kk][tx * 4];
            ULL bb0 = pk(b4.x, b4.x), bb1 = pk(b4.y, b4.y);
            ULL bb2 = pk(b4.z, b4.z), bb3 = pk(b4.w, b4.w);
            ULL am[4] = {am0.x, am0.y, am1.x, am1.y};
            #pragma unroll
            for (int r = 0; r < 4; r++) {
                acc[r][0] = fma2(am[r], bb0, acc[r][0]);
                acc[r][1] = fma2(am[r], bb1, acc[r][1]);
                acc[r][2] = fma2(am[r], bb2, acc[r][2]);
                acc[r][3] = fma2(am[r], bb3, acc[r][3]);
            }
        }
        if (last) break;

        int nb = buf ^ 1;   // store prefetched tile into other buffer
        As[nb][alc + 0][alr] = a0.x; As[nb][alc + 1][alr] = a0.y;
        As[nb][alc + 2][alr] = a0.z; As[nb][alc + 3][alr] = a0.w;
        As[nb][alc + 4][alr] = a1.x; As[nb][alc + 5][alr] = a1.y;
        As[nb][alc + 6][alr] = a1.z; As[nb][alc + 7][alr] = a1.w;
        Bs[nb][blc + 0][blr] = b0.x; Bs[nb][blc + 1][blr] = b0.y;
        Bs[nb][blc + 2][blr] = b0.z; Bs[nb][blc + 3][blr] = b0.w;
        buf = nb;
        __syncthreads();
    }

    int col = bn + tx * 4;
    float4 bb = *(const float4*)(bias + col);
    #pragma unroll
    for (int r = 0; r < 4; r++) {
        float lo0, hi0, lo1, hi1, lo2v, hi2, lo3, hi3;
        unpk(acc[r][0], lo0, hi0);
        unpk(acc[r][1], lo1, hi1);
        unpk(acc[r][2], lo2v, hi2);
        unpk(acc[r][3], lo3, hi3);
        int row0 = bm + ty * 8 + 2 * r;
        *(float4*)(C + (size_t)row0 * N + col) =
            make_float4(lo0 + bb.x, lo1 + bb.y, lo2v + bb.z, lo3 + bb.w);
        *(float4*)(C + (size_t)(row0 + 1) * N + col) =
            make_float4(hi0 + bb.x, hi1 + bb.y, hi2 + bb.z, hi3 + bb.w);
    }
}

// ---------------- attention pass 1 (R8 exact): keys-packed, no-max softmax --
// grid = (4 key-quarters, 2 query-halves, 128 bh), 128 threads.
__global__ __launch_bounds__(128) void attn_p1_kernel()
{
    __shared__ ULL Kp[128 * 8];   // 8 KB: Kp[sp*8+c] = (k_{2sp}[c], k_{2sp+1}[c])
    __shared__ ULL Vp[128 * 8];   // 8 KB

    int kq = blockIdx.x;
    int qh = blockIdx.y;
    int bh = blockIdx.z;
    int b = bh >> 5;
    int h = bh & 31;
    int t = threadIdx.x;
    const float* base = g_qkv + (size_t)b * S_ * (3 * E_) + h * DK_;

    // stage: thread t packs keys (2t, 2t+1)
    {
        const float* ra = base + (size_t)(kq * 256 + 2 * t) * (3 * E_);
        const float* rb = ra + 3 * E_;
        float4 ka0 = *(const float4*)(ra + E_);
        float4 ka1 = *(const float4*)(ra + E_ + 4);
        float4 kb0 = *(const float4*)(rb + E_);
        float4 kb1 = *(const float4*)(rb + E_ + 4);
        ulonglong2* kw = (ulonglong2*)(Kp + t * 8);
        kw[0] = make_ulonglong2(pk(ka0.x, kb0.x), pk(ka0.y, kb0.y));
        kw[1] = make_ulonglong2(pk(ka0.z, kb0.z), pk(ka0.w, kb0.w));
        kw[2] = make_ulonglong2(pk(ka1.x, kb1.x), pk(ka1.y, kb1.y));
        kw[3] = make_ulonglong2(pk(ka1.z, kb1.z), pk(ka1.w, kb1.w));
        float4 va0 = *(const float4*)(ra + 2 * E_);
        float4 va1 = *(const float4*)(ra + 2 * E_ + 4);
        float4 vb0 = *(const float4*)(rb + 2 * E_);
        float4 vb1 = *(const float4*)(rb + 2 * E_ + 4);
        ulonglong2* vw = (ulonglong2*)(Vp + t * 8);
        vw[0] = make_ulonglong2(pk(va0.x, vb0.x), pk(va0.y, vb0.y));
        vw[1] = make_ulonglong2(pk(va0.z, vb0.z), pk(va0.w, vb0.w));
        vw[2] = make_ulonglong2(pk(va1.x, vb1.x), pk(va1.y, vb1.y));
        vw[3] = make_ulonglong2(pk(va1.z, vb1.z), pk(va1.w, vb1.w));
    }
    __syncthreads();

    const float qscale = 0.35355339059327373f * 1.4426950408889634f; // log2e/sqrt(8)

    // 4 queries duplicated in regs: qd[i][c] = (q_i[c]*s, q_i[c]*s)
    ULL qd[4][8];
    #pragma unroll
    for (int i = 0; i < 4; i++) {
        const float* r = base + (size_t)(qh * 512 + t + i * 128) * (3 * E_);
        float4 q0 = *(const float4*)(r);
        float4 q1 = *(const float4*)(r + 4);
        float s;
        s = q0.x * qscale; qd[i][0] = pk(s, s);
        s = q0.y * qscale; qd[i][1] = pk(s, s);
        s = q0.z * qscale; qd[i][2] = pk(s, s);
        s = q0.w * qscale; qd[i][3] = pk(s, s);
        s = q1.x * qscale; qd[i][4] = pk(s, s);
        s = q1.y * qscale; qd[i][5] = pk(s, s);
        s = q1.z * qscale; qd[i][6] = pk(s, s);
        s = q1.w * qscale; qd[i][7] = pk(s, s);
    }

    ULL l[4] = {0ULL, 0ULL, 0ULL, 0ULL};
    ULL acc[4][8];
    #pragma unroll
    for (int i = 0; i < 4; i++)
        #pragma unroll
        for (int c = 0; c < 8; c++) acc[i][c] = 0ULL;

    #pragma unroll 1
    for (int sp = 0; sp < 128; sp++) {
        const ulonglong2* kr = (const ulonglong2*)(Kp + sp * 8);
        ulonglong2 k01 = kr[0], k23 = kr[1], k45 = kr[2], k67 = kr[3];

        ULL t0 = mul2(qd[0][0], k01.x);
        ULL t1 = mul2(qd[1][0], k01.x);
        ULL t2 = mul2(qd[2][0], k01.x);
        ULL t3 = mul2(qd[3][0], k01.x);
        t0 = fma2(qd[0][1], k01.y, t0);
        t1 = fma2(qd[1][1], k01.y, t1);
        t2 = fma2(qd[2][1], k01.y, t2);
        t3 = fma2(qd[3][1], k01.y, t3);
        t0 = fma2(qd[0][2], k23.x, t0);
        t1 = fma2(qd[1][2], k23.x, t1);
        t2 = fma2(qd[2][2], k23.x, t2);
        t3 = fma2(qd[3][2], k23.x, t3);
        t0 = fma2(qd[0][3], k23.y, t0);
        t1 = fma2(qd[1][3], k23.y, t1);
        t2 = fma2(qd[2][3], k23.y, t2);
        t3 = fma2(qd[3][3], k23.y, t3);
        t0 = fma2(qd[0][4], k45.x, t0);
        t1 = fma2(qd[1][4], k45.x, t1);
        t2 = fma2(qd[2][4], k45.x, t2);
        t3 = fma2(qd[3][4], k45.x, t3);
        t0 = fma2(qd[0][5], k45.y, t0);
        t1 = fma2(qd[1][5], k45.y, t1);
        t2 = fma2(qd[2][5], k45.y, t2);
        t3 = fma2(qd[3][5], k45.y, t3);
        t0 = fma2(qd[0][6], k67.x, t0);
        t1 = fma2(qd[1][6], k67.x, t1);
        t2 = fma2(qd[2][6], k67.x, t2);
        t3 = fma2(qd[3][6], k67.x, t3);
        t0 = fma2(qd[0][7], k67.y, t0);
        t1 = fma2(qd[1][7], k67.y, t1);
        t2 = fma2(qd[2][7], k67.y, t2);
        t3 = fma2(qd[3][7], k67.y, t3);

        float d0, d1;
        unpk(t0, d0, d1);
        ULL pp0 = pk(ex2f_(d0), ex2f_(d1));
        unpk(t1, d0, d1);
        ULL pp1 = pk(ex2f_(d0), ex2f_(d1));
        unpk(t2, d0, d1);
        ULL pp2 = pk(ex2f_(d0), ex2f_(d1));
        unpk(t3, d0, d1);
        ULL pp3 = pk(ex2f_(d0), ex2f_(d1));
        l[0] = add2(l[0], pp0);
        l[1] = add2(l[1], pp1);
        l[2] = add2(l[2], pp2);
        l[3] = add2(l[3], pp3);

        const ulonglong2* vr = (const ulonglong2*)(Vp + sp * 8);
        ulonglong2 v01 = vr[0], v23 = vr[1], v45 = vr[2], v67 = vr[3];
        acc[0][0] = fma2(pp0, v01.x, acc[0][0]);
        acc[1][0] = fma2(pp1, v01.x, acc[1][0]);
        acc[2][0] = fma2(pp2, v01.x, acc[2][0]);
        acc[3][0] = fma2(pp3, v01.x, acc[3][0]);
        acc[0][1] = fma2(pp0, v01.y, acc[0][1]);
        acc[1][1] = fma2(pp1, v01.y, acc[1][1]);
        acc[2][1] = fma2(pp2, v01.y, acc[2][1]);
        acc[3][1] = fma2(pp3, v01.y, acc[3][1]);
        acc[0][2] = fma2(pp0, v23.x, acc[0][2]);
        acc[1][2] = fma2(pp1, v23.x, acc[1][2]);
        acc[2][2] = fma2(pp2, v23.x, acc[2][2]);
        acc[3][2] = fma2(pp3, v23.x, acc[3][2]);
        acc[0][3] = fma2(pp0, v23.y, acc[0][3]);
        acc[1][3] = fma2(pp1, v23.y, acc[1][3]);
        acc[2][3] = fma2(pp2, v23.y, acc[2][3]);
        acc[3][3] = fma2(pp3, v23.y, acc[3][3]);
        acc[0][4] = fma2(pp0, v45.x, acc[0][4]);
        acc[1][4] = fma2(pp1, v45.x, acc[1][4]);
        acc[2][4] = fma2(pp2, v45.x, acc[2][4]);
        acc[3][4] = fma2(pp3, v45.x, acc[3][4]);
        acc[0][5] = fma2(pp0, v45.y, acc[0][5]);
        acc[1][5] = fma2(pp1, v45.y, acc[1][5]);
        acc[2][5] = fma2(pp2, v45.y, acc[2][5]);
        acc[3][5] = fma2(pp3, v45.y, acc[3][5]);
        acc[0][6] = fma2(pp0, v67.x, acc[0][6]);
        acc[1][6] = fma2(pp1, v67.x, acc[1][6]);
        acc[2][6] = fma2(pp2, v67.x, acc[2][6]);
        acc[3][6] = fma2(pp3, v67.x, acc[3][6]);
        acc[0][7] = fma2(pp0, v67.y, acc[0][7]);
        acc[1][7] = fma2(pp1, v67.y, acc[1][7]);
        acc[2][7] = fma2(pp2, v67.y, acc[2][7]);
        acc[3][7] = fma2(pp3, v67.y, acc[3][7]);
    }

    // fold packed even/odd halves and write float partials
    int pidx = ((bh * 4 + kq) * 2 + qh) * 128 + t;
    {
        float lo, hi;
        float lv[4];
        #pragma unroll
        for (int i = 0; i < 4; i++) { unpk(l[i], lo, hi); lv[i] = lo + hi; }
        *(float4*)(g_plf + pidx * 4) = make_float4(lv[0], lv[1], lv[2], lv[3]);
        float* pa = g_paccf + (size_t)pidx * 32;
        #pragma unroll
        for (int i = 0; i < 4; i++) {
            float av[8];
            #pragma unroll
            for (int c = 0; c < 8; c++) { unpk(acc[i][c], lo, hi); av[c] = lo + hi; }
            *(float4*)(pa + i * 8)     = make_float4(av[0], av[1], av[2], av[3]);
            *(float4*)(pa + i * 8 + 4) = make_float4(av[4], av[5], av[6], av[7]);
        }
    }
}

// ---------------- attention pass 2: sum 4 partials, normalize ---------------
__global__ __launch_bounds__(256) void attn_p2_kernel()
{
    int idx = blockIdx.x * 256 + threadIdx.x;   // 32768 threads
    int bh = idx >> 8;
    int r  = idx & 255;
    int qh = r >> 7;
    int t  = r & 127;
    int b = bh >> 5;
    int h = bh & 31;

    float L[4] = {0.f, 0.f, 0.f, 0.f};
    float c[4][8];
    #pragma unroll
    for (int i = 0; i < 4; i++)
        #pragma unroll
        for (int j = 0; j < 8; j++) c[i][j] = 0.f;

    #pragma unroll
    for (int kq = 0; kq < 4; kq++) {
        int pidx = ((bh * 4 + kq) * 2 + qh) * 128 + t;
        float4 lv = *(const float4*)(g_plf + pidx * 4);
        L[0] += lv.x; L[1] += lv.y; L[2] += lv.z; L[3] += lv.w;
        const float4* pa = (const float4*)(g_paccf + (size_t)pidx * 32);
        #pragma unroll
        for (int i = 0; i < 4; i++) {
            float4 a0 = pa[2 * i], a1 = pa[2 * i + 1];
            c[i][0] += a0.x; c[i][1] += a0.y; c[i][2] += a0.z; c[i][3] += a0.w;
            c[i][4] += a1.x; c[i][5] += a1.y; c[i][6] += a1.z; c[i][7] += a1.w;
        }
    }

    #pragma unroll
    for (int i = 0; i < 4; i++) {
        float rr = 1.f / L[i];
        int q = qh * 512 + t + i * 128;
        float* o = g_ctx + ((size_t)b * S_ + q) * E_ + h * DK_;
        *(float4*)(o)     = make_float4(c[i][0] * rr, c[i][1] * rr, c[i][2] * rr, c[i][3] * rr);
        *(float4*)(o + 4) = make_float4(c[i][4] * rr, c[i][5] * rr, c[i][6] * rr, c[i][7] * rr);
    }
}

// ---------------- layernorm: out = LN(a + b) * g + beta  (warp per row) -----
__global__ __launch_bounds__(256) void ln_kernel(
    const float* __restrict__ a, const float* __restrict__ bsrc,
    const float* __restrict__ g, const float* __restrict__ beta,
    float* __restrict__ out)
{
    int row  = (blockIdx.x * 256 + threadIdx.x) >> 5;
    int lane = threadIdx.x & 31;
    size_t off = (size_t)row * E_ + lane * 8;

    const float4* ap = (const float4*)(a + off);
    const float4* bp = (const float4*)(bsrc + off);
    float4 a0 = ap[0], a1 = ap[1], b0 = bp[0], b1 = bp[1];
    float v[8];
    v[0] = a0.x + b0.x; v[1] = a0.y + b0.y; v[2] = a0.z + b0.z; v[3] = a0.w + b0.w;
    v[4] = a1.x + b1.x; v[5] = a1.y + b1.y; v[6] = a1.z + b1.z; v[7] = a1.w + b1.w;

    float s = 0.f, ss = 0.f;
    #pragma unroll
    for (int i = 0; i < 8; i++) { s += v[i]; ss = fmaf(v[i], v[i], ss); }
    #pragma unroll
    for (int o = 16; o > 0; o >>= 1) {
        s  += __shfl_xor_sync(0xFFFFFFFFu, s,  o);
        ss += __shfl_xor_sync(0xFFFFFFFFu, ss, o);
    }
    float mu  = s * (1.f / E_);
    float var = ss * (1.f / E_) - mu * mu;
    float rs  = rsqrtf(var + 1e-5f);

    const float4* gp  = (const float4*)(g    + lane * 8);
    const float4* bep = (const float4*)(beta + lane * 8);
    float4 g0 = gp[0], g1v = gp[1], e0 = bep[0], e1 = bep[1];

    float4 w;
    w.x = (v[0]-mu)*rs*g0.x + e0.x; w.y = (v[1]-mu)*rs*g0.y + e0.y;
    w.z = (v[2]-mu)*rs*g0.z + e0.z; w.w = (v[3]-mu)*rs*g0.w + e0.w;
    *(float4*)(out + off) = w;
    w.x = (v[4]-mu)*rs*g1v.x + e1.x; w.y = (v[5]-mu)*rs*g1v.y + e1.y;
    w.z = (v[6]-mu)*rs*g1v.z + e1.z; w.w = (v[7]-mu)*rs*g1v.w + e1.w;
    *(float4*)(out + off + 4) = w;
}

// ---------------- qf = cos(theta)*cos(h @ w_ip^T + b_ip), warp per row ------
__global__ __launch_bounds__(256) void qf_kernel(
    const float* __restrict__ w_ip, const float* __restrict__ b_ip,
    const float* __restrict__ theta_ffn)
{
    int tid = threadIdx.x;
    int m = blockIdx.x * 8 + (tid >> 5);
    int lane = tid & 31;
    int j = lane >> 2, p = lane & 3;
    const float* hr = g_h + (size_t)m * E_ + p * 64;
    const float* wr = w_ip + (size_t)j * E_ + p * 64;
    ULL acc = 0ULL;
    #pragma unroll
    for (int i = 0; i < 64; i += 8) {
        float4 hA = *(const float4*)(hr + i);
        float4 hB = *(const float4*)(hr + i + 4);
        float4 wA = *(const float4*)(wr + i);
        float4 wB = *(const float4*)(wr + i + 4);
        acc = fma2(pk(hA.x, hA.y), pk(wA.x, wA.y), acc);
        acc = fma2(pk(hA.z, hA.w), pk(wA.z, wA.w), acc);
        acc = fma2(pk(hB.x, hB.y), pk(wB.x, wB.y), acc);
        acc = fma2(pk(hB.z, hB.w), pk(wB.z, wB.w), acc);
    }
    float s0, s1;
    unpk(acc, s0, s1);
    float s = s0 + s1;
    s += __shfl_xor_sync(0xFFFFFFFFu, s, 1);
    s += __shfl_xor_sync(0xFFFFFFFFu, s, 2);
    if (p == 0)
        g_qf[m * NQ_ + j] = __cosf(theta_ffn[j]) * __cosf(s + b_ip[j]);
}

// ---------------- hidden = relu(qf @ w1^T + b1)   (K=8) ---------------------
__global__ __launch_bounds__(256) void hidden_kernel(
    const float* __restrict__ w1, const float* __restrict__ b1)
{
    int m = blockIdx.x >> 2;
    int f = ((blockIdx.x & 3) << 8) + threadIdx.x;
    const float* qr = g_qf + (size_t)m * NQ_;
    const float* wr = w1 + (size_t)f * NQ_;
    float s = b1[f];
    #pragma unroll
    for (int j = 0; j < NQ_; j++)
        s = fmaf(qr[j], wr[j], s);
    g_hidden[(size_t)m * FF_ + f] = fmaxf(s, 0.f);
}

// ---------------- launch ----------------------------------------------------
extern "C" void kernel_launch(void* const* d_in, const int* in_sizes, int n_in,
                              void* d_out, int out_size)
{
    (void)in_sizes; (void)n_in; (void)out_size;

    const float* x          = (const float*)d_in[0];
    const float* theta_attn = (const float*)d_in[1];
    const float* w_in       = (const float*)d_in[2];
    const float* b_in       = (const float*)d_in[3];
    const float* w_out      = (const float*)d_in[4];
    const float* b_out      = (const float*)d_in[5];
    const float* w_comb     = (const float*)d_in[6];
    const float* b_comb     = (const float*)d_in[7];
    const float* g1         = (const float*)d_in[8];
    const float* be1        = (const float*)d_in[9];
    const float* g2         = (const float*)d_in[10];
    const float* be2        = (const float*)d_in[11];
    const float* w_ip       = (const float*)d_in[12];
    const float* b_ip       = (const float*)d_in[13];
    const float* theta_ffn  = (const float*)d_in[14];
    const float* w1         = (const float*)d_in[15];
    const float* b1         = (const float*)d_in[16];
    const float* w2         = (const float*)d_in[17];
    const float* b2         = (const float*)d_in[18];
    float* out = (float*)d_out;

    float *p_qout, *p_qkv, *p_ctx, *p_Wf, *p_bf, *p_tmp, *p_h, *p_hidden;
    cudaGetSymbolAddress((void**)&p_qout,   g_qout);
    cudaGetSymbolAddress((void**)&p_qkv,    g_qkv);
    cudaGetSymbolAddress((void**)&p_ctx,    g_ctx);
    cudaGetSymbolAddress((void**)&p_Wf,     g_Wf);
    cudaGetSymbolAddress((void**)&p_bf,     g_bf);
    cudaGetSymbolAddress((void**)&p_tmp,    g_tmp);
    cudaGetSymbolAddress((void**)&p_h,      g_h);
    cudaGetSymbolAddress((void**)&p_hidden, g_hidden);

    // 1. q_out = cos(x + theta)
    cos_encode_kernel<<<(M_ * E_) / 1024, 256>>>(x, theta_attn);

    // 2. fold w_comb @ w_out
    fold_w_kernel<<<E_, 256>>>(w_comb, w_out, b_out, b_comb);

    // 3. qkv = q_out @ w_in^T + b_in      [4096 x 768]
    {
        dim3 grid((3 * E_) / 64, M_ / 128);
        sgemm2_kernel<<<grid, 256>>>(p_qout, w_in, b_in, p_qkv, M_, 3 * E_, E_);
    }

    // 4a. attention pass 1 (split-K=4 partials, keys-packed)
    {
        dim3 grid(4, 2, B_ * H_);
        attn_p1_kernel<<<grid, 128>>>();
    }
    // 4b. attention pass 2 (sum + normalize) -> ctx
    attn_p2_kernel<<<128, 256>>>();

    // 5. attn_out = ctx @ Wf^T + bf       [4096 x 256]
    {
        dim3 grid(E_ / 64, M_ / 128);
        sgemm2_kernel<<<grid, 256>>>(p_ctx, p_Wf, p_bf, p_tmp, M_, E_, E_);
    }

    // 6. h = LN(x + attn_out) * g1 + be1
    ln_kernel<<<M_ / 8, 256>>>(x, p_tmp, g1, be1, p_h);

    // 7. qf = cos(theta_ffn) * cos(h @ w_ip^T + b_ip)
    qf_kernel<<<M_ / 8, 256>>>(w_ip, b_ip, theta_ffn);

    // 8. hidden = relu(qf @ w1^T + b1)    [4096 x 1024]
    hidden_kernel<<<M_ * 4, 256>>>(w1, b1);

    // 9. ffn_out = hidden @ w2^T + b2     [4096 x 256]
    {
        dim3 grid(E_ / 64, M_ / 128);
        sgemm2_kernel<<<grid, 256>>>(p_hidden, w2, b2, p_tmp, M_, E_, FF_);
    }

    // 10. out = LN(h + ffn_out) * g2 + be2
    ln_kernel<<<M_ / 8, 256>>>(p_h, p_tmp, g2, be2, out);
}

// round 13
// speedup vs baseline: 1.1355x; 1.0270x over previous
#include <cuda_runtime.h>
#include <math.h>
#include <stdint.h>

// Problem constants
#define B_   4
#define S_   1024
#define E_   256
#define H_   32
#define DK_  8
#define NQ_  8
#define FF_  1024
#define M_   (B_ * S_)   // 4096

typedef unsigned long long ULL;

// ---------------- f32x2 packed math helpers (PTX-only on sm_103a) ----------
__device__ __forceinline__ ULL fma2(ULL a, ULL b, ULL c) {
    ULL d; asm("fma.rn.f32x2 %0, %1, %2, %3;" : "=l"(d) : "l"(a), "l"(b), "l"(c)); return d;
}
__device__ __forceinline__ ULL mul2(ULL a, ULL b) {
    ULL d; asm("mul.rn.f32x2 %0, %1, %2;" : "=l"(d) : "l"(a), "l"(b)); return d;
}
__device__ __forceinline__ ULL add2(ULL a, ULL b) {
    ULL d; asm("add.rn.f32x2 %0, %1, %2;" : "=l"(d) : "l"(a), "l"(b)); return d;
}
__device__ __forceinline__ ULL pk(float lo, float hi) {
    ULL r; asm("mov.b64 %0, {%1, %2};" : "=l"(r) : "f"(lo), "f"(hi)); return r;
}
__device__ __forceinline__ void unpk(ULL v, float& lo, float& hi) {
    asm("mov.b64 {%0, %1}, %2;" : "=f"(lo), "=f"(hi) : "l"(v));
}
__device__ __forceinline__ float ex2f_(float x) {
    float y; asm("ex2.approx.f32 %0, %1;" : "=f"(y) : "f"(x)); return y;
}

// ---------------- scratch (device globals; no runtime allocation) ----------
__device__ __align__(16) float g_qout[M_ * E_];
__device__ __align__(16) float g_qkv[M_ * 3 * E_];
__device__ __align__(16) float g_ctx[M_ * E_];
__device__ __align__(16) float g_Wf[E_ * E_];
__device__ __align__(16) float g_bf[E_];
__device__ __align__(16) float g_tmp[M_ * E_];
__device__ __align__(16) float g_tmp2[M_ * E_];
__device__ __align__(16) float g_h[M_ * E_];
__device__ __align__(16) float g_qf[M_ * NQ_];
__device__ __align__(16) float g_hidden[M_ * FF_];
// split-K attention partials (plain floats; lo/hi combined in pass 1)
__device__ __align__(16) float g_plf[131072 * 4];
__device__ __align__(16) float g_paccf[(size_t)131072 * 32];

// ---------------- q_out = cos(x + theta[e % 8]), float4 --------------------
__global__ __launch_bounds__(256) void cos_encode_kernel(
    const float* __restrict__ x, const float* __restrict__ theta)
{
    int i = (blockIdx.x * 256 + threadIdx.x) * 4;
    float4 v = *(const float4*)(x + i);
    int j = i & 7;
    v.x = __cosf(v.x + theta[j + 0]);
    v.y = __cosf(v.y + theta[j + 1]);
    v.z = __cosf(v.z + theta[j + 2]);
    v.w = __cosf(v.w + theta[j + 3]);
    *(float4*)(g_qout + i) = v;
}

// ---------------- fold: Wf = w_comb @ w_out, bf = w_comb@b_out + b_comb -----
__global__ __launch_bounds__(256) void fold_w_kernel(
    const float* __restrict__ w_comb, const float* __restrict__ w_out,
    const float* __restrict__ b_out, const float* __restrict__ b_comb)
{
    int i = blockIdx.x;
    int j = threadIdx.x;
    float s = 0.f;
    #pragma unroll 8
    for (int k = 0; k < E_; k++)
        s = fmaf(w_comb[i * E_ + k], w_out[k * E_ + j], s);
    g_Wf[i * E_ + j] = s;

    __shared__ float red[256];
    red[j] = w_comb[i * E_ + j] * b_out[j];
    __syncthreads();
    #pragma unroll
    for (int off = 128; off > 0; off >>= 1) {
        if (j < off) red[j] += red[j + off];
        __syncthreads();
    }
    if (j == 0) g_bf[i] = red[0] + b_comb[i];
}

// ---------------- f32x2 SGEMM, double-buffered: C = A @ Bw^T + bias --------
// BM=128, BN=64, BK=16, 256 threads, 8x4 microtile, ONE sync per k-iter.
__global__ __launch_bounds__(256) void sgemm2_kernel(
    const float* __restrict__ A, const float* __restrict__ Bw,
    const float* __restrict__ bias, float* __restrict__ C,
    int M, int N, int K)
{
    __shared__ float As[2][16][132];
    __shared__ float Bs[2][16][68];

    int tid = threadIdx.x;
    int bm = blockIdx.y * 128;
    int bn = blockIdx.x * 64;
    int ty = tid >> 4;
    int tx = tid & 15;

    int alr = tid >> 1;
    int alc = (tid & 1) * 8;
    int blr = tid >> 2;
    int blc = (tid & 3) * 4;

    const float* Aptr = A  + (size_t)(bm + alr) * K + alc;
    const float* Bptr = Bw + (size_t)(bn + blr) * K + blc;

    float4 a0 = *(const float4*)(Aptr);
    float4 a1 = *(const float4*)(Aptr + 4);
    float4 b0 = *(const float4*)(Bptr);

    ULL acc[4][4];
    #pragma unroll
    for (int r = 0; r < 4; r++)
        #pragma unroll
        for (int j = 0; j < 4; j++) acc[r][j] = 0ULL;

    As[0][alc + 0][alr] = a0.x; As[0][alc + 1][alr] = a0.y;
    As[0][alc + 2][alr] = a0.z; As[0][alc + 3][alr] = a0.w;
    As[0][alc + 4][alr] = a1.x; As[0][alc + 5][alr] = a1.y;
    As[0][alc + 6][alr] = a1.z; As[0][alc + 7][alr] = a1.w;
    Bs[0][blc + 0][blr] = b0.x; Bs[0][blc + 1][blr] = b0.y;
    Bs[0][blc + 2][blr] = b0.z; Bs[0][blc + 3][blr] = b0.w;
    __syncthreads();

    int buf = 0;
    for (int k0 = 0; ; k0 += 16) {
        bool last = (k0 + 16 >= K);
        if (!last) {
            Aptr += 16; Bptr += 16;
            a0 = *(const float4*)(Aptr);
            a1 = *(const float4*)(Aptr + 4);
            b0 = *(const float4*)(Bptr);
        }

        #pragma unroll
        for (int kk = 0; kk < 16; kk++) {
            ulonglong2 am0 = *(const ulonglong2*)&As[buf][kk][ty * 8];
            ulonglong2 am1 = *(const ulonglong2*)&As[buf][kk][ty * 8 + 4];
            float4 b4 = *(const float4*)&Bs[buf][kk][tx * 4];
            ULL bb0 = pk(b4.x, b4.x), bb1 = pk(b4.y, b4.y);
            ULL bb2 = pk(b4.z, b4.z), bb3 = pk(b4.w, b4.w);
            ULL am[4] = {am0.x, am0.y, am1.x, am1.y};
            #pragma unroll
            for (int r = 0; r < 4; r++) {
                acc[r][0] = fma2(am[r], bb0, acc[r][0]);
                acc[r][1] = fma2(am[r], bb1, acc[r][1]);
                acc[r][2] = fma2(am[r], bb2, acc[r][2]);
                acc[r][3] = fma2(am[r], bb3, acc[r][3]);
            }
        }
        if (last) break;

        int nb = buf ^ 1;
        As[nb][alc + 0][alr] = a0.x; As[nb][alc + 1][alr] = a0.y;
        As[nb][alc + 2][alr] = a0.z; As[nb][alc + 3][alr] = a0.w;
        As[nb][alc + 4][alr] = a1.x; As[nb][alc + 5][alr] = a1.y;
        As[nb][alc + 6][alr] = a1.z; As[nb][alc + 7][alr] = a1.w;
        Bs[nb][blc + 0][blr] = b0.x; Bs[nb][blc + 1][blr] = b0.y;
        Bs[nb][blc + 2][blr] = b0.z; Bs[nb][blc + 3][blr] = b0.w;
        buf = nb;
        __syncthreads();
    }

    int col = bn + tx * 4;
    float4 bb = *(const float4*)(bias + col);
    #pragma unroll
    for (int r = 0; r < 4; r++) {
        float lo0, hi0, lo1, hi1, lo2v, hi2, lo3, hi3;
        unpk(acc[r][0], lo0, hi0);
        unpk(acc[r][1], lo1, hi1);
        unpk(acc[r][2], lo2v, hi2);
        unpk(acc[r][3], lo3, hi3);
        int row0 = bm + ty * 8 + 2 * r;
        *(float4*)(C + (size_t)row0 * N + col) =
            make_float4(lo0 + bb.x, lo1 + bb.y, lo2v + bb.z, lo3 + bb.w);
        *(float4*)(C + (size_t)(row0 + 1) * N + col) =
            make_float4(hi0 + bb.x, hi1 + bb.y, hi2 + bb.z, hi3 + bb.w);
    }
}

// ---------------- split-K SGEMM: z-th CTA layer does K-half z ---------------
// Writes partial products: z=0 -> C0 (+bias), z=1 -> C1 (no bias).
// lda = full K of A/B rows; Khalf = K/2. grid (N/64, M/128, 2).
__global__ __launch_bounds__(256) void sgemm2s_kernel(
    const float* __restrict__ A, const float* __restrict__ Bw,
    const float* __restrict__ bias,
    float* __restrict__ C0, float* __restrict__ C1,
    int M, int N, int Khalf, int lda)
{
    __shared__ float As[2][16][132];
    __shared__ float Bs[2][16][68];

    int tid = threadIdx.x;
    int bm = blockIdx.y * 128;
    int bn = blockIdx.x * 64;
    int z  = blockIdx.z;
    int ty = tid >> 4;
    int tx = tid & 15;

    int alr = tid >> 1;
    int alc = (tid & 1) * 8;
    int blr = tid >> 2;
    int blc = (tid & 3) * 4;

    const float* Aptr = A  + (size_t)(bm + alr) * lda + z * Khalf + alc;
    const float* Bptr = Bw + (size_t)(bn + blr) * lda + z * Khalf + blc;

    float4 a0 = *(const float4*)(Aptr);
    float4 a1 = *(const float4*)(Aptr + 4);
    float4 b0 = *(const float4*)(Bptr);

    ULL acc[4][4];
    #pragma unroll
    for (int r = 0; r < 4; r++)
        #pragma unroll
        for (int j = 0; j < 4; j++) acc[r][j] = 0ULL;

    As[0][alc + 0][alr] = a0.x; As[0][alc + 1][alr] = a0.y;
    As[0][alc + 2][alr] = a0.z; As[0][alc + 3][alr] = a0.w;
    As[0][alc + 4][alr] = a1.x; As[0][alc + 5][alr] = a1.y;
    As[0][alc + 6][alr] = a1.z; As[0][alc + 7][alr] = a1.w;
    Bs[0][blc + 0][blr] = b0.x; Bs[0][blc + 1][blr] = b0.y;
    Bs[0][blc + 2][blr] = b0.z; Bs[0][blc + 3][blr] = b0.w;
    __syncthreads();

    int buf = 0;
    for (int k0 = 0; ; k0 += 16) {
        bool last = (k0 + 16 >= Khalf);
        if (!last) {
            Aptr += 16; Bptr += 16;
            a0 = *(const float4*)(Aptr);
            a1 = *(const float4*)(Aptr + 4);
            b0 = *(const float4*)(Bptr);
        }

        #pragma unroll
        for (int kk = 0; kk < 16; kk++) {
            ulonglong2 am0 = *(const ulonglong2*)&As[buf][kk][ty * 8];
            ulonglong2 am1 = *(const ulonglong2*)&As[buf][kk][ty * 8 + 4];
            float4 b4 = *(const float4*)&Bs[buf][kk][tx * 4];
            ULL bb0 = pk(b4.x, b4.x), bb1 = pk(b4.y, b4.y);
            ULL bb2 = pk(b4.z, b4.z), bb3 = pk(b4.w, b4.w);
            ULL am[4] = {am0.x, am0.y, am1.x, am1.y};
            #pragma unroll
            for (int r = 0; r < 4; r++) {
                acc[r][0] = fma2(am[r], bb0, acc[r][0]);
                acc[r][1] = fma2(am[r], bb1, acc[r][1]);
                acc[r][2] = fma2(am[r], bb2, acc[r][2]);
                acc[r][3] = fma2(am[r], bb3, acc[r][3]);
            }
        }
        if (last) break;

        int nb = buf ^ 1;
        As[nb][alc + 0][alr] = a0.x; As[nb][alc + 1][alr] = a0.y;
        As[nb][alc + 2][alr] = a0.z; As[nb][alc + 3][alr] = a0.w;
        As[nb][alc + 4][alr] = a1.x; As[nb][alc + 5][alr] = a1.y;
        As[nb][alc + 6][alr] = a1.z; As[nb][alc + 7][alr] = a1.w;
        Bs[nb][blc + 0][blr] = b0.x; Bs[nb][blc + 1][blr] = b0.y;
        Bs[nb][blc + 2][blr] = b0.z; Bs[nb][blc + 3][blr] = b0.w;
        buf = nb;
        __syncthreads();
    }

    int col = bn + tx * 4;
    float bsel = (z == 0) ? 1.f : 0.f;
    float4 bb = *(const float4*)(bias + col);
    bb.x *= bsel; bb.y *= bsel; bb.z *= bsel; bb.w *= bsel;
    float* C = (z == 0) ? C0 : C1;
    #pragma unroll
    for (int r = 0; r < 4; r++) {
        float lo0, hi0, lo1, hi1, lo2v, hi2, lo3, hi3;
        unpk(acc[r][0], lo0, hi0);
        unpk(acc[r][1], lo1, hi1);
        unpk(acc[r][2], lo2v, hi2);
        unpk(acc[r][3], lo3, hi3);
        int row0 = bm + ty * 8 + 2 * r;
        *(float4*)(C + (size_t)row0 * N + col) =
            make_float4(lo0 + bb.x, lo1 + bb.y, lo2v + bb.z, lo3 + bb.w);
        *(float4*)(C + (size_t)(row0 + 1) * N + col) =
            make_float4(hi0 + bb.x, hi1 + bb.y, hi2 + bb.z, hi3 + bb.w);
    }
}

// ---------------- attention pass 1 (R8 exact): keys-packed, no-max softmax --
__global__ __launch_bounds__(128) void attn_p1_kernel()
{
    __shared__ ULL Kp[128 * 8];
    __shared__ ULL Vp[128 * 8];

    int kq = blockIdx.x;
    int qh = blockIdx.y;
    int bh = blockIdx.z;
    int b = bh >> 5;
    int h = bh & 31;
    int t = threadIdx.x;
    const float* base = g_qkv + (size_t)b * S_ * (3 * E_) + h * DK_;

    {
        const float* ra = base + (size_t)(kq * 256 + 2 * t) * (3 * E_);
        const float* rb = ra + 3 * E_;
        float4 ka0 = *(const float4*)(ra + E_);
        float4 ka1 = *(const float4*)(ra + E_ + 4);
        float4 kb0 = *(const float4*)(rb + E_);
        float4 kb1 = *(const float4*)(rb + E_ + 4);
        ulonglong2* kw = (ulonglong2*)(Kp + t * 8);
        kw[0] = make_ulonglong2(pk(ka0.x, kb0.x), pk(ka0.y, kb0.y));
        kw[1] = make_ulonglong2(pk(ka0.z, kb0.z), pk(ka0.w, kb0.w));
        kw[2] = make_ulonglong2(pk(ka1.x, kb1.x), pk(ka1.y, kb1.y));
        kw[3] = make_ulonglong2(pk(ka1.z, kb1.z), pk(ka1.w, kb1.w));
        float4 va0 = *(const float4*)(ra + 2 * E_);
        float4 va1 = *(const float4*)(ra + 2 * E_ + 4);
        float4 vb0 = *(const float4*)(rb + 2 * E_);
        float4 vb1 = *(const float4*)(rb + 2 * E_ + 4);
        ulonglong2* vw = (ulonglong2*)(Vp + t * 8);
        vw[0] = make_ulonglong2(pk(va0.x, vb0.x), pk(va0.y, vb0.y));
        vw[1] = make_ulonglong2(pk(va0.z, vb0.z), pk(va0.w, vb0.w));
        vw[2] = make_ulonglong2(pk(va1.x, vb1.x), pk(va1.y, vb1.y));
        vw[3] = make_ulonglong2(pk(va1.z, vb1.z), pk(va1.w, vb1.w));
    }
    __syncthreads();

    const float qscale = 0.35355339059327373f * 1.4426950408889634f;

    ULL qd[4][8];
    #pragma unroll
    for (int i = 0; i < 4; i++) {
        const float* r = base + (size_t)(qh * 512 + t + i * 128) * (3 * E_);
        float4 q0 = *(const float4*)(r);
        float4 q1 = *(const float4*)(r + 4);
        float s;
        s = q0.x * qscale; qd[i][0] = pk(s, s);
        s = q0.y * qscale; qd[i][1] = pk(s, s);
        s = q0.z * qscale; qd[i][2] = pk(s, s);
        s = q0.w * qscale; qd[i][3] = pk(s, s);
        s = q1.x * qscale; qd[i][4] = pk(s, s);
        s = q1.y * qscale; qd[i][5] = pk(s, s);
        s = q1.z * qscale; qd[i][6] = pk(s, s);
        s = q1.w * qscale; qd[i][7] = pk(s, s);
    }

    ULL l[4] = {0ULL, 0ULL, 0ULL, 0ULL};
    ULL acc[4][8];
    #pragma unroll
    for (int i = 0; i < 4; i++)
        #pragma unroll
        for (int c = 0; c < 8; c++) acc[i][c] = 0ULL;

    #pragma unroll 1
    for (int sp = 0; sp < 128; sp++) {
        const ulonglong2* kr = (const ulonglong2*)(Kp + sp * 8);
        ulonglong2 k01 = kr[0], k23 = kr[1], k45 = kr[2], k67 = kr[3];

        ULL t0 = mul2(qd[0][0], k01.x);
        ULL t1 = mul2(qd[1][0], k01.x);
        ULL t2 = mul2(qd[2][0], k01.x);
        ULL t3 = mul2(qd[3][0], k01.x);
        t0 = fma2(qd[0][1], k01.y, t0);
        t1 = fma2(qd[1][1], k01.y, t1);
        t2 = fma2(qd[2][1], k01.y, t2);
        t3 = fma2(qd[3][1], k01.y, t3);
        t0 = fma2(qd[0][2], k23.x, t0);
        t1 = fma2(qd[1][2], k23.x, t1);
        t2 = fma2(qd[2][2], k23.x, t2);
        t3 = fma2(qd[3][2], k23.x, t3);
        t0 = fma2(qd[0][3], k23.y, t0);
        t1 = fma2(qd[1][3], k23.y, t1);
        t2 = fma2(qd[2][3], k23.y, t2);
        t3 = fma2(qd[3][3], k23.y, t3);
        t0 = fma2(qd[0][4], k45.x, t0);
        t1 = fma2(qd[1][4], k45.x, t1);
        t2 = fma2(qd[2][4], k45.x, t2);
        t3 = fma2(qd[3][4], k45.x, t3);
        t0 = fma2(qd[0][5], k45.y, t0);
        t1 = fma2(qd[1][5], k45.y, t1);
        t2 = fma2(qd[2][5], k45.y, t2);
        t3 = fma2(qd[3][5], k45.y, t3);
        t0 = fma2(qd[0][6], k67.x, t0);
        t1 = fma2(qd[1][6], k67.x, t1);
        t2 = fma2(qd[2][6], k67.x, t2);
        t3 = fma2(qd[3][6], k67.x, t3);
        t0 = fma2(qd[0][7], k67.y, t0);
        t1 = fma2(qd[1][7], k67.y, t1);
        t2 = fma2(qd[2][7], k67.y, t2);
        t3 = fma2(qd[3][7], k67.y, t3);

        float d0, d1;
        unpk(t0, d0, d1);
        ULL pp0 = pk(ex2f_(d0), ex2f_(d1));
        unpk(t1, d0, d1);
        ULL pp1 = pk(ex2f_(d0), ex2f_(d1));
        unpk(t2, d0, d1);
        ULL pp2 = pk(ex2f_(d0), ex2f_(d1));
        unpk(t3, d0, d1);
        ULL pp3 = pk(ex2f_(d0), ex2f_(d1));
        l[0] = add2(l[0], pp0);
        l[1] = add2(l[1], pp1);
        l[2] = add2(l[2], pp2);
        l[3] = add2(l[3], pp3);

        const ulonglong2* vr = (const ulonglong2*)(Vp + sp * 8);
        ulonglong2 v01 = vr[0], v23 = vr[1], v45 = vr[2], v67 = vr[3];
        acc[0][0] = fma2(pp0, v01.x, acc[0][0]);
        acc[1][0] = fma2(pp1, v01.x, acc[1][0]);
        acc[2][0] = fma2(pp2, v01.x, acc[2][0]);
        acc[3][0] = fma2(pp3, v01.x, acc[3][0]);
        acc[0][1] = fma2(pp0, v01.y, acc[0][1]);
        acc[1][1] = fma2(pp1, v01.y, acc[1][1]);
        acc[2][1] = fma2(pp2, v01.y, acc[2][1]);
        acc[3][1] = fma2(pp3, v01.y, acc[3][1]);
        acc[0][2] = fma2(pp0, v23.x, acc[0][2]);
        acc[1][2] = fma2(pp1, v23.x, acc[1][2]);
        acc[2][2] = fma2(pp2, v23.x, acc[2][2]);
        acc[3][2] = fma2(pp3, v23.x, acc[3][2]);
        acc[0][3] = fma2(pp0, v23.y, acc[0][3]);
        acc[1][3] = fma2(pp1, v23.y, acc[1][3]);
        acc[2][3] = fma2(pp2, v23.y, acc[2][3]);
        acc[3][3] = fma2(pp3, v23.y, acc[3][3]);
        acc[0][4] = fma2(pp0, v45.x, acc[0][4]);
        acc[1][4] = fma2(pp1, v45.x, acc[1][4]);
        acc[2][4] = fma2(pp2, v45.x, acc[2][4]);
        acc[3][4] = fma2(pp3, v45.x, acc[3][4]);
        acc[0][5] = fma2(pp0, v45.y, acc[0][5]);
        acc[1][5] = fma2(pp1, v45.y, acc[1][5]);
        acc[2][5] = fma2(pp2, v45.y, acc[2][5]);
        acc[3][5] = fma2(pp3, v45.y, acc[3][5]);
        acc[0][6] = fma2(pp0, v67.x, acc[0][6]);
        acc[1][6] = fma2(pp1, v67.x, acc[1][6]);
        acc[2][6] = fma2(pp2, v67.x, acc[2][6]);
        acc[3][6] = fma2(pp3, v67.x, acc[3][6]);
        acc[0][7] = fma2(pp0, v67.y, acc[0][7]);
        acc[1][7] = fma2(pp1, v67.y, acc[1][7]);
        acc[2][7] = fma2(pp2, v67.y, acc[2][7]);
        acc[3][7] = fma2(pp3, v67.y, acc[3][7]);
    }

    int pidx = ((bh * 4 + kq) * 2 + qh) * 128 + t;
    {
        float lo, hi;
        float lv[4];
        #pragma unroll
        for (int i = 0; i < 4; i++) { unpk(l[i], lo, hi); lv[i] = lo + hi; }
        *(float4*)(g_plf + pidx * 4) = make_float4(lv[0], lv[1], lv[2], lv[3]);
        float* pa = g_paccf + (size_t)pidx * 32;
        #pragma unroll
        for (int i = 0; i < 4; i++) {
            float av[8];
            #pragma unroll
            for (int c = 0; c < 8; c++) { unpk(acc[i][c], lo, hi); av[c] = lo + hi; }
            *(float4*)(pa + i * 8)     = make_float4(av[0], av[1], av[2], av[3]);
            *(float4*)(pa + i * 8 + 4) = make_float4(av[4], av[5], av[6], av[7]);
        }
    }
}

// ---------------- attention pass 2: sum 4 partials, normalize ---------------
__global__ __launch_bounds__(256) void attn_p2_kernel()
{
    int idx = blockIdx.x * 256 + threadIdx.x;
    int bh = idx >> 8;
    int r  = idx & 255;
    int qh = r >> 7;
    int t  = r & 127;
    int b = bh >> 5;
    int h = bh & 31;

    float L[4] = {0.f, 0.f, 0.f, 0.f};
    float c[4][8];
    #pragma unroll
    for (int i = 0; i < 4; i++)
        #pragma unroll
        for (int j = 0; j < 8; j++) c[i][j] = 0.f;

    #pragma unroll
    for (int kq = 0; kq < 4; kq++) {
        int pidx = ((bh * 4 + kq) * 2 + qh) * 128 + t;
        float4 lv = *(const float4*)(g_plf + pidx * 4);
        L[0] += lv.x; L[1] += lv.y; L[2] += lv.z; L[3] += lv.w;
        const float4* pa = (const float4*)(g_paccf + (size_t)pidx * 32);
        #pragma unroll
        for (int i = 0; i < 4; i++) {
            float4 a0 = pa[2 * i], a1 = pa[2 * i + 1];
            c[i][0] += a0.x; c[i][1] += a0.y; c[i][2] += a0.z; c[i][3] += a0.w;
            c[i][4] += a1.x; c[i][5] += a1.y; c[i][6] += a1.z; c[i][7] += a1.w;
        }
    }

    #pragma unroll
    for (int i = 0; i < 4; i++) {
        float rr = 1.f / L[i];
        int q = qh * 512 + t + i * 128;
        float* o = g_ctx + ((size_t)b * S_ + q) * E_ + h * DK_;
        *(float4*)(o)     = make_float4(c[i][0] * rr, c[i][1] * rr, c[i][2] * rr, c[i][3] * rr);
        *(float4*)(o + 4) = make_float4(c[i][4] * rr, c[i][5] * rr, c[i][6] * rr, c[i][7] * rr);
    }
}

// ---------------- layernorm3: out = LN(a + b0 + b1) * g + beta --------------
__global__ __launch_bounds__(256) void ln3_kernel(
    const float* __restrict__ a, const float* __restrict__ bsrc0,
    const float* __restrict__ bsrc1,
    const float* __restrict__ g, const float* __restrict__ beta,
    float* __restrict__ out)
{
    int row  = (blockIdx.x * 256 + threadIdx.x) >> 5;
    int lane = threadIdx.x & 31;
    size_t off = (size_t)row * E_ + lane * 8;

    const float4* ap = (const float4*)(a + off);
    const float4* bp = (const float4*)(bsrc0 + off);
    const float4* cp = (const float4*)(bsrc1 + off);
    float4 a0 = ap[0], a1 = ap[1], b0 = bp[0], b1 = bp[1];
    float4 c0 = cp[0], c1 = cp[1];
    float v[8];
    v[0] = a0.x + b0.x + c0.x; v[1] = a0.y + b0.y + c0.y;
    v[2] = a0.z + b0.z + c0.z; v[3] = a0.w + b0.w + c0.w;
    v[4] = a1.x + b1.x + c1.x; v[5] = a1.y + b1.y + c1.y;
    v[6] = a1.z + b1.z + c1.z; v[7] = a1.w + b1.w + c1.w;

    float s = 0.f, ss = 0.f;
    #pragma unroll
    for (int i = 0; i < 8; i++) { s += v[i]; ss = fmaf(v[i], v[i], ss); }
    #pragma unroll
    for (int o = 16; o > 0; o >>= 1) {
        s  += __shfl_xor_sync(0xFFFFFFFFu, s,  o);
        ss += __shfl_xor_sync(0xFFFFFFFFu, ss, o);
    }
    float mu  = s * (1.f / E_);
    float var = ss * (1.f / E_) - mu * mu;
    float rs  = rsqrtf(var + 1e-5f);

    const float4* gp  = (const float4*)(g    + lane * 8);
    const float4* bep = (const float4*)(beta + lane * 8);
    float4 g0 = gp[0], g1v = gp[1], e0 = bep[0], e1 = bep[1];

    float4 w;
    w.x = (v[0]-mu)*rs*g0.x + e0.x; w.y = (v[1]-mu)*rs*g0.y + e0.y;
    w.z = (v[2]-mu)*rs*g0.z + e0.z; w.w = (v[3]-mu)*rs*g0.w + e0.w;
    *(float4*)(out + off) = w;
    w.x = (v[4]-mu)*rs*g1v.x + e1.x; w.y = (v[5]-mu)*rs*g1v.y + e1.y;
    w.z = (v[6]-mu)*rs*g1v.z + e1.z; w.w = (v[7]-mu)*rs*g1v.w + e1.w;
    *(float4*)(out + off + 4) = w;
}

// ---------------- qf = cos(theta)*cos(h @ w_ip^T + b_ip), warp per row ------
__global__ __launch_bounds__(256) void qf_kernel(
    const float* __restrict__ w_ip, const float* __restrict__ b_ip,
    const float* __restrict__ theta_ffn)
{
    int tid = threadIdx.x;
    int m = blockIdx.x * 8 + (tid >> 5);
    int lane = tid & 31;
    int j = lane >> 2, p = lane & 3;
    const float* hr = g_h + (size_t)m * E_ + p * 64;
    const float* wr = w_ip + (size_t)j * E_ + p * 64;
    ULL acc = 0ULL;
    #pragma unroll
    for (int i = 0; i < 64; i += 8) {
        float4 hA = *(const float4*)(hr + i);
        float4 hB = *(const float4*)(hr + i + 4);
        float4 wA = *(const float4*)(wr + i);
        float4 wB = *(const float4*)(wr + i + 4);
        acc = fma2(pk(hA.x, hA.y), pk(wA.x, wA.y), acc);
        acc = fma2(pk(hA.z, hA.w), pk(wA.z, wA.w), acc);
        acc = fma2(pk(hB.x, hB.y), pk(wB.x, wB.y), acc);
        acc = fma2(pk(hB.z, hB.w), pk(wB.z, wB.w), acc);
    }
    float s0, s1;
    unpk(acc, s0, s1);
    float s = s0 + s1;
    s += __shfl_xor_sync(0xFFFFFFFFu, s, 1);
    s += __shfl_xor_sync(0xFFFFFFFFu, s, 2);
    if (p == 0)
        g_qf[m * NQ_ + j] = __cosf(theta_ffn[j]) * __cosf(s + b_ip[j]);
}

// ---------------- hidden = relu(qf @ w1^T + b1), 4 outputs/thread -----------
__global__ __launch_bounds__(256) void hidden_kernel(
    const float* __restrict__ w1, const float* __restrict__ b1)
{
    int m = blockIdx.x;
    int f = threadIdx.x * 4;
    const float4* qp = (const float4*)(g_qf + (size_t)m * NQ_);
    float4 q0 = qp[0], q1 = qp[1];

    float4 outv;
    float* op = &outv.x;
    #pragma unroll
    for (int j = 0; j < 4; j++) {
        const float4* wr = (const float4*)(w1 + (size_t)(f + j) * NQ_);
        float4 w0 = wr[0], w1v = wr[1];
        float s = b1[f + j];
        s = fmaf(q0.x, w0.x, s);
        s = fmaf(q0.y, w0.y, s);
        s = fmaf(q0.z, w0.z, s);
        s = fmaf(q0.w, w0.w, s);
        s = fmaf(q1.x, w1v.x, s);
        s = fmaf(q1.y, w1v.y, s);
        s = fmaf(q1.z, w1v.z, s);
        s = fmaf(q1.w, w1v.w, s);
        op[j] = fmaxf(s, 0.f);
    }
    *(float4*)(g_hidden + (size_t)m * FF_ + f) = outv;
}

// ---------------- launch ----------------------------------------------------
extern "C" void kernel_launch(void* const* d_in, const int* in_sizes, int n_in,
                              void* d_out, int out_size)
{
    (void)in_sizes; (void)n_in; (void)out_size;

    const float* x          = (const float*)d_in[0];
    const float* theta_attn = (const float*)d_in[1];
    const float* w_in       = (const float*)d_in[2];
    const float* b_in       = (const float*)d_in[3];
    const float* w_out      = (const float*)d_in[4];
    const float* b_out      = (const float*)d_in[5];
    const float* w_comb     = (const float*)d_in[6];
    const float* b_comb     = (const float*)d_in[7];
    const float* g1         = (const float*)d_in[8];
    const float* be1        = (const float*)d_in[9];
    const float* g2         = (const float*)d_in[10];
    const float* be2        = (const float*)d_in[11];
    const float* w_ip       = (const float*)d_in[12];
    const float* b_ip       = (const float*)d_in[13];
    const float* theta_ffn  = (const float*)d_in[14];
    const float* w1         = (const float*)d_in[15];
    const float* b1         = (const float*)d_in[16];
    const float* w2         = (const float*)d_in[17];
    const float* b2         = (const float*)d_in[18];
    float* out = (float*)d_out;

    float *p_qout, *p_qkv, *p_ctx, *p_Wf, *p_bf, *p_tmp, *p_tmp2, *p_h, *p_hidden;
    cudaGetSymbolAddress((void**)&p_qout,   g_qout);
    cudaGetSymbolAddress((void**)&p_qkv,    g_qkv);
    cudaGetSymbolAddress((void**)&p_ctx,    g_ctx);
    cudaGetSymbolAddress((void**)&p_Wf,     g_Wf);
    cudaGetSymbolAddress((void**)&p_bf,     g_bf);
    cudaGetSymbolAddress((void**)&p_tmp,    g_tmp);
    cudaGetSymbolAddress((void**)&p_tmp2,   g_tmp2);
    cudaGetSymbolAddress((void**)&p_h,      g_h);
    cudaGetSymbolAddress((void**)&p_hidden, g_hidden);

    // 1. q_out = cos(x + theta)
    cos_encode_kernel<<<(M_ * E_) / 1024, 256>>>(x, theta_attn);

    // 2. fold w_comb @ w_out
    fold_w_kernel<<<E_, 256>>>(w_comb, w_out, b_out, b_comb);

    // 3. qkv = q_out @ w_in^T + b_in      [4096 x 768]
    {
        dim3 grid((3 * E_) / 64, M_ / 128);
        sgemm2_kernel<<<grid, 256>>>(p_qout, w_in, b_in, p_qkv, M_, 3 * E_, E_);
    }

    // 4a. attention pass 1 (split-K=4 partials, keys-packed)
    {
        dim3 grid(4, 2, B_ * H_);
        attn_p1_kernel<<<grid, 128>>>();
    }
    // 4b. attention pass 2 (sum + normalize) -> ctx
    attn_p2_kernel<<<128, 256>>>();

    // 5. attn_out partials = ctx @ Wf^T (+bf), split-K=2   [4096 x 256]
    {
        dim3 grid(E_ / 64, M_ / 128, 2);
        sgemm2s_kernel<<<grid, 256>>>(p_ctx, p_Wf, p_bf, p_tmp, p_tmp2,
                                      M_, E_, E_ / 2, E_);
    }

    // 6. h = LN(x + tmp + tmp2) * g1 + be1
    ln3_kernel<<<M_ / 8, 256>>>(x, p_tmp, p_tmp2, g1, be1, p_h);

    // 7. qf = cos(theta_ffn) * cos(h @ w_ip^T + b_ip)
    qf_kernel<<<M_ / 8, 256>>>(w_ip, b_ip, theta_ffn);

    // 8. hidden = relu(qf @ w1^T + b1)    [4096 x 1024]
    hidden_kernel<<<M_, 256>>>(w1, b1);

    // 9. ffn_out partials = hidden @ w2^T (+b2), split-K=2  [4096 x 256]
    {
        dim3 grid(E_ / 64, M_ / 128, 2);
        sgemm2s_kernel<<<grid, 256>>>(p_hidden, w2, b2, p_tmp, p_tmp2,
                                      M_, E_, FF_ / 2, FF_);
    }

    // 10. out = LN(h + tmp + tmp2) * g2 + be2
    ln3_kernel<<<M_ / 8, 256>>>(p_h, p_tmp, p_tmp2, g2, be2, out);
}

// round 14
// speedup vs baseline: 1.1494x; 1.0122x over previous
#include <cuda_runtime.h>
#include <math.h>
#include <stdint.h>

// Problem constants
#define B_   4
#define S_   1024
#define E_   256
#define H_   32
#define DK_  8
#define NQ_  8
#define FF_  1024
#define M_   (B_ * S_)   // 4096

typedef unsigned long long ULL;

// ---------------- f32x2 packed math helpers (PTX-only on sm_103a) ----------
__device__ __forceinline__ ULL fma2(ULL a, ULL b, ULL c) {
    ULL d; asm("fma.rn.f32x2 %0, %1, %2, %3;" : "=l"(d) : "l"(a), "l"(b), "l"(c)); return d;
}
__device__ __forceinline__ ULL mul2(ULL a, ULL b) {
    ULL d; asm("mul.rn.f32x2 %0, %1, %2;" : "=l"(d) : "l"(a), "l"(b)); return d;
}
__device__ __forceinline__ ULL add2(ULL a, ULL b) {
    ULL d; asm("add.rn.f32x2 %0, %1, %2;" : "=l"(d) : "l"(a), "l"(b)); return d;
}
__device__ __forceinline__ ULL pk(float lo, float hi) {
    ULL r; asm("mov.b64 %0, {%1, %2};" : "=l"(r) : "f"(lo), "f"(hi)); return r;
}
__device__ __forceinline__ void unpk(ULL v, float& lo, float& hi) {
    asm("mov.b64 {%0, %1}, %2;" : "=f"(lo), "=f"(hi) : "l"(v));
}
__device__ __forceinline__ float ex2f_(float x) {
    float y; asm("ex2.approx.f32 %0, %1;" : "=f"(y) : "f"(x)); return y;
}

// ---------------- scratch (device globals; no runtime allocation) ----------
__device__ __align__(16) float g_qout[M_ * E_];
__device__ __align__(16) float g_qkv[M_ * 3 * E_];
__device__ __align__(16) float g_qkv2[M_ * 3 * E_];   // split-K partial
__device__ __align__(16) float g_ctx[M_ * E_];
__device__ __align__(16) float g_Wf[E_ * E_];
__device__ __align__(16) float g_bf[E_];
__device__ __align__(16) float g_tmp[M_ * E_];
__device__ __align__(16) float g_tmp2[M_ * E_];
__device__ __align__(16) float g_h[M_ * E_];
__device__ __align__(16) float g_qf[M_ * NQ_];
__device__ __align__(16) float g_hidden[M_ * FF_];
// split-K attention partials (plain floats; lo/hi combined in pass 1)
__device__ __align__(16) float g_plf[131072 * 4];
__device__ __align__(16) float g_paccf[(size_t)131072 * 32];

// ---------------- q_out = cos(x + theta[e % 8]), float4 --------------------
__global__ __launch_bounds__(256) void cos_encode_kernel(
    const float* __restrict__ x, const float* __restrict__ theta)
{
    int i = (blockIdx.x * 256 + threadIdx.x) * 4;
    float4 v = *(const float4*)(x + i);
    int j = i & 7;
    v.x = __cosf(v.x + theta[j + 0]);
    v.y = __cosf(v.y + theta[j + 1]);
    v.z = __cosf(v.z + theta[j + 2]);
    v.w = __cosf(v.w + theta[j + 3]);
    *(float4*)(g_qout + i) = v;
}

// ---------------- fold: Wf = w_comb @ w_out, bf = w_comb@b_out + b_comb -----
__global__ __launch_bounds__(256) void fold_w_kernel(
    const float* __restrict__ w_comb, const float* __restrict__ w_out,
    const float* __restrict__ b_out, const float* __restrict__ b_comb)
{
    int i = blockIdx.x;
    int j = threadIdx.x;
    float s = 0.f;
    #pragma unroll 8
    for (int k = 0; k < E_; k++)
        s = fmaf(w_comb[i * E_ + k], w_out[k * E_ + j], s);
    g_Wf[i * E_ + j] = s;

    __shared__ float red[256];
    red[j] = w_comb[i * E_ + j] * b_out[j];
    __syncthreads();
    #pragma unroll
    for (int off = 128; off > 0; off >>= 1) {
        if (j < off) red[j] += red[j + off];
        __syncthreads();
    }
    if (j == 0) g_bf[i] = red[0] + b_comb[i];
}

// ---------------- split-K SGEMM: z-th CTA layer does K-half z ---------------
// Writes partial products: z=0 -> C0 (+bias), z=1 -> C1 (no bias).
__global__ __launch_bounds__(256) void sgemm2s_kernel(
    const float* __restrict__ A, const float* __restrict__ Bw,
    const float* __restrict__ bias,
    float* __restrict__ C0, float* __restrict__ C1,
    int M, int N, int Khalf, int lda)
{
    __shared__ float As[2][16][132];
    __shared__ float Bs[2][16][68];

    int tid = threadIdx.x;
    int bm = blockIdx.y * 128;
    int bn = blockIdx.x * 64;
    int z  = blockIdx.z;
    int ty = tid >> 4;
    int tx = tid & 15;

    int alr = tid >> 1;
    int alc = (tid & 1) * 8;
    int blr = tid >> 2;
    int blc = (tid & 3) * 4;

    const float* Aptr = A  + (size_t)(bm + alr) * lda + z * Khalf + alc;
    const float* Bptr = Bw + (size_t)(bn + blr) * lda + z * Khalf + blc;

    float4 a0 = *(const float4*)(Aptr);
    float4 a1 = *(const float4*)(Aptr + 4);
    float4 b0 = *(const float4*)(Bptr);

    ULL acc[4][4];
    #pragma unroll
    for (int r = 0; r < 4; r++)
        #pragma unroll
        for (int j = 0; j < 4; j++) acc[r][j] = 0ULL;

    As[0][alc + 0][alr] = a0.x; As[0][alc + 1][alr] = a0.y;
    As[0][alc + 2][alr] = a0.z; As[0][alc + 3][alr] = a0.w;
    As[0][alc + 4][alr] = a1.x; As[0][alc + 5][alr] = a1.y;
    As[0][alc + 6][alr] = a1.z; As[0][alc + 7][alr] = a1.w;
    Bs[0][blc + 0][blr] = b0.x; Bs[0][blc + 1][blr] = b0.y;
    Bs[0][blc + 2][blr] = b0.z; Bs[0][blc + 3][blr] = b0.w;
    __syncthreads();

    int buf = 0;
    for (int k0 = 0; ; k0 += 16) {
        bool last = (k0 + 16 >= Khalf);
        if (!last) {
            Aptr += 16; Bptr += 16;
            a0 = *(const float4*)(Aptr);
            a1 = *(const float4*)(Aptr + 4);
            b0 = *(const float4*)(Bptr);
        }

        #pragma unroll
        for (int kk = 0; kk < 16; kk++) {
            ulonglong2 am0 = *(const ulonglong2*)&As[buf][kk][ty * 8];
            ulonglong2 am1 = *(const ulonglong2*)&As[buf][kk][ty * 8 + 4];
            float4 b4 = *(const float4*)&Bs[buf][kk][tx * 4];
            ULL bb0 = pk(b4.x, b4.x), bb1 = pk(b4.y, b4.y);
            ULL bb2 = pk(b4.z, b4.z), bb3 = pk(b4.w, b4.w);
            ULL am[4] = {am0.x, am0.y, am1.x, am1.y};
            #pragma unroll
            for (int r = 0; r < 4; r++) {
                acc[r][0] = fma2(am[r], bb0, acc[r][0]);
                acc[r][1] = fma2(am[r], bb1, acc[r][1]);
                acc[r][2] = fma2(am[r], bb2, acc[r][2]);
                acc[r][3] = fma2(am[r], bb3, acc[r][3]);
            }
        }
        if (last) break;

        int nb = buf ^ 1;
        As[nb][alc + 0][alr] = a0.x; As[nb][alc + 1][alr] = a0.y;
        As[nb][alc + 2][alr] = a0.z; As[nb][alc + 3][alr] = a0.w;
        As[nb][alc + 4][alr] = a1.x; As[nb][alc + 5][alr] = a1.y;
        As[nb][alc + 6][alr] = a1.z; As[nb][alc + 7][alr] = a1.w;
        Bs[nb][blc + 0][blr] = b0.x; Bs[nb][blc + 1][blr] = b0.y;
        Bs[nb][blc + 2][blr] = b0.z; Bs[nb][blc + 3][blr] = b0.w;
        buf = nb;
        __syncthreads();
    }

    int col = bn + tx * 4;
    float bsel = (z == 0) ? 1.f : 0.f;
    float4 bb = *(const float4*)(bias + col);
    bb.x *= bsel; bb.y *= bsel; bb.z *= bsel; bb.w *= bsel;
    float* C = (z == 0) ? C0 : C1;
    #pragma unroll
    for (int r = 0; r < 4; r++) {
        float lo0, hi0, lo1, hi1, lo2v, hi2, lo3, hi3;
        unpk(acc[r][0], lo0, hi0);
        unpk(acc[r][1], lo1, hi1);
        unpk(acc[r][2], lo2v, hi2);
        unpk(acc[r][3], lo3, hi3);
        int row0 = bm + ty * 8 + 2 * r;
        *(float4*)(C + (size_t)row0 * N + col) =
            make_float4(lo0 + bb.x, lo1 + bb.y, lo2v + bb.z, lo3 + bb.w);
        *(float4*)(C + (size_t)(row0 + 1) * N + col) =
            make_float4(hi0 + bb.x, hi1 + bb.y, hi2 + bb.z, hi3 + bb.w);
    }
}

// ---------------- attention pass 1: keys-packed, sums qkv partials ----------
// grid = (4 key-quarters, 2 query-halves, 128 bh), 128 threads.
__global__ __launch_bounds__(128) void attn_p1_kernel()
{
    __shared__ ULL Kp[128 * 8];
    __shared__ ULL Vp[128 * 8];

    int kq = blockIdx.x;
    int qh = blockIdx.y;
    int bh = blockIdx.z;
    int b = bh >> 5;
    int h = bh & 31;
    int t = threadIdx.x;
    size_t boff = (size_t)b * S_ * (3 * E_) + h * DK_;
    const float* base  = g_qkv  + boff;
    const float* base2 = g_qkv2 + boff;

    // stage: thread t packs keys (2t, 2t+1); sum the two qkv partials
    {
        size_t ro = (size_t)(kq * 256 + 2 * t) * (3 * E_);
        const float* ra  = base  + ro;
        const float* ra2 = base2 + ro;
        const float* rb  = ra  + 3 * E_;
        const float* rb2 = ra2 + 3 * E_;
        float4 ka0 = *(const float4*)(ra + E_);
        float4 ka1 = *(const float4*)(ra + E_ + 4);
        float4 kb0 = *(const float4*)(rb + E_);
        float4 kb1 = *(const float4*)(rb + E_ + 4);
        float4 p;
        p = *(const float4*)(ra2 + E_);      ka0.x += p.x; ka0.y += p.y; ka0.z += p.z; ka0.w += p.w;
        p = *(const float4*)(ra2 + E_ + 4);  ka1.x += p.x; ka1.y += p.y; ka1.z += p.z; ka1.w += p.w;
        p = *(const float4*)(rb2 + E_);      kb0.x += p.x; kb0.y += p.y; kb0.z += p.z; kb0.w += p.w;
        p = *(const float4*)(rb2 + E_ + 4);  kb1.x += p.x; kb1.y += p.y; kb1.z += p.z; kb1.w += p.w;
        ulonglong2* kw = (ulonglong2*)(Kp + t * 8);
        kw[0] = make_ulonglong2(pk(ka0.x, kb0.x), pk(ka0.y, kb0.y));
        kw[1] = make_ulonglong2(pk(ka0.z, kb0.z), pk(ka0.w, kb0.w));
        kw[2] = make_ulonglong2(pk(ka1.x, kb1.x), pk(ka1.y, kb1.y));
        kw[3] = make_ulonglong2(pk(ka1.z, kb1.z), pk(ka1.w, kb1.w));
        float4 va0 = *(const float4*)(ra + 2 * E_);
        float4 va1 = *(const float4*)(ra + 2 * E_ + 4);
        float4 vb0 = *(const float4*)(rb + 2 * E_);
        float4 vb1 = *(const float4*)(rb + 2 * E_ + 4);
        p = *(const float4*)(ra2 + 2 * E_);      va0.x += p.x; va0.y += p.y; va0.z += p.z; va0.w += p.w;
        p = *(const float4*)(ra2 + 2 * E_ + 4);  va1.x += p.x; va1.y += p.y; va1.z += p.z; va1.w += p.w;
        p = *(const float4*)(rb2 + 2 * E_);      vb0.x += p.x; vb0.y += p.y; vb0.z += p.z; vb0.w += p.w;
        p = *(const float4*)(rb2 + 2 * E_ + 4);  vb1.x += p.x; vb1.y += p.y; vb1.z += p.z; vb1.w += p.w;
        ulonglong2* vw = (ulonglong2*)(Vp + t * 8);
        vw[0] = make_ulonglong2(pk(va0.x, vb0.x), pk(va0.y, vb0.y));
        vw[1] = make_ulonglong2(pk(va0.z, vb0.z), pk(va0.w, vb0.w));
        vw[2] = make_ulonglong2(pk(va1.x, vb1.x), pk(va1.y, vb1.y));
        vw[3] = make_ulonglong2(pk(va1.z, vb1.z), pk(va1.w, vb1.w));
    }
    __syncthreads();

    const float qscale = 0.35355339059327373f * 1.4426950408889634f;

    ULL qd[4][8];
    #pragma unroll
    for (int i = 0; i < 4; i++) {
        size_t ro = (size_t)(qh * 512 + t + i * 128) * (3 * E_);
        float4 q0 = *(const float4*)(base + ro);
        float4 q1 = *(const float4*)(base + ro + 4);
        float4 p0 = *(const float4*)(base2 + ro);
        float4 p1 = *(const float4*)(base2 + ro + 4);
        q0.x += p0.x; q0.y += p0.y; q0.z += p0.z; q0.w += p0.w;
        q1.x += p1.x; q1.y += p1.y; q1.z += p1.z; q1.w += p1.w;
        float s;
        s = q0.x * qscale; qd[i][0] = pk(s, s);
        s = q0.y * qscale; qd[i][1] = pk(s, s);
        s = q0.z * qscale; qd[i][2] = pk(s, s);
        s = q0.w * qscale; qd[i][3] = pk(s, s);
        s = q1.x * qscale; qd[i][4] = pk(s, s);
        s = q1.y * qscale; qd[i][5] = pk(s, s);
        s = q1.z * qscale; qd[i][6] = pk(s, s);
        s = q1.w * qscale; qd[i][7] = pk(s, s);
    }

    ULL l[4] = {0ULL, 0ULL, 0ULL, 0ULL};
    ULL acc[4][8];
    #pragma unroll
    for (int i = 0; i < 4; i++)
        #pragma unroll
        for (int c = 0; c < 8; c++) acc[i][c] = 0ULL;

    #pragma unroll 1
    for (int sp = 0; sp < 128; sp++) {
        const ulonglong2* kr = (const ulonglong2*)(Kp + sp * 8);
        ulonglong2 k01 = kr[0], k23 = kr[1], k45 = kr[2], k67 = kr[3];

        ULL t0 = mul2(qd[0][0], k01.x);
        ULL t1 = mul2(qd[1][0], k01.x);
        ULL t2 = mul2(qd[2][0], k01.x);
        ULL t3 = mul2(qd[3][0], k01.x);
        t0 = fma2(qd[0][1], k01.y, t0);
        t1 = fma2(qd[1][1], k01.y, t1);
        t2 = fma2(qd[2][1], k01.y, t2);
        t3 = fma2(qd[3][1], k01.y, t3);
        t0 = fma2(qd[0][2], k23.x, t0);
        t1 = fma2(qd[1][2], k23.x, t1);
        t2 = fma2(qd[2][2], k23.x, t2);
        t3 = fma2(qd[3][2], k23.x, t3);
        t0 = fma2(qd[0][3], k23.y, t0);
        t1 = fma2(qd[1][3], k23.y, t1);
        t2 = fma2(qd[2][3], k23.y, t2);
        t3 = fma2(qd[3][3], k23.y, t3);
        t0 = fma2(qd[0][4], k45.x, t0);
        t1 = fma2(qd[1][4], k45.x, t1);
        t2 = fma2(qd[2][4], k45.x, t2);
        t3 = fma2(qd[3][4], k45.x, t3);
        t0 = fma2(qd[0][5], k45.y, t0);
        t1 = fma2(qd[1][5], k45.y, t1);
        t2 = fma2(qd[2][5], k45.y, t2);
        t3 = fma2(qd[3][5], k45.y, t3);
        t0 = fma2(qd[0][6], k67.x, t0);
        t1 = fma2(qd[1][6], k67.x, t1);
        t2 = fma2(qd[2][6], k67.x, t2);
        t3 = fma2(qd[3][6], k67.x, t3);
        t0 = fma2(qd[0][7], k67.y, t0);
        t1 = fma2(qd[1][7], k67.y, t1);
        t2 = fma2(qd[2][7], k67.y, t2);
        t3 = fma2(qd[3][7], k67.y, t3);

        float d0, d1;
        unpk(t0, d0, d1);
        ULL pp0 = pk(ex2f_(d0), ex2f_(d1));
        unpk(t1, d0, d1);
        ULL pp1 = pk(ex2f_(d0), ex2f_(d1));
        unpk(t2, d0, d1);
        ULL pp2 = pk(ex2f_(d0), ex2f_(d1));
        unpk(t3, d0, d1);
        ULL pp3 = pk(ex2f_(d0), ex2f_(d1));
        l[0] = add2(l[0], pp0);
        l[1] = add2(l[1], pp1);
        l[2] = add2(l[2], pp2);
        l[3] = add2(l[3], pp3);

        const ulonglong2* vr = (const ulonglong2*)(Vp + sp * 8);
        ulonglong2 v01 = vr[0], v23 = vr[1], v45 = vr[2], v67 = vr[3];
        acc[0][0] = fma2(pp0, v01.x, acc[0][0]);
        acc[1][0] = fma2(pp1, v01.x, acc[1][0]);
        acc[2][0] = fma2(pp2, v01.x, acc[2][0]);
        acc[3][0] = fma2(pp3, v01.x, acc[3][0]);
        acc[0][1] = fma2(pp0, v01.y, acc[0][1]);
        acc[1][1] = fma2(pp1, v01.y, acc[1][1]);
        acc[2][1] = fma2(pp2, v01.y, acc[2][1]);
        acc[3][1] = fma2(pp3, v01.y, acc[3][1]);
        acc[0][2] = fma2(pp0, v23.x, acc[0][2]);
        acc[1][2] = fma2(pp1, v23.x, acc[1][2]);
        acc[2][2] = fma2(pp2, v23.x, acc[2][2]);
        acc[3][2] = fma2(pp3, v23.x, acc[3][2]);
        acc[0][3] = fma2(pp0, v23.y, acc[0][3]);
        acc[1][3] = fma2(pp1, v23.y, acc[1][3]);
        acc[2][3] = fma2(pp2, v23.y, acc[2][3]);
        acc[3][3] = fma2(pp3, v23.y, acc[3][3]);
        acc[0][4] = fma2(pp0, v45.x, acc[0][4]);
        acc[1][4] = fma2(pp1, v45.x, acc[1][4]);
        acc[2][4] = fma2(pp2, v45.x, acc[2][4]);
        acc[3][4] = fma2(pp3, v45.x, acc[3][4]);
        acc[0][5] = fma2(pp0, v45.y, acc[0][5]);
        acc[1][5] = fma2(pp1, v45.y, acc[1][5]);
        acc[2][5] = fma2(pp2, v45.y, acc[2][5]);
        acc[3][5] = fma2(pp3, v45.y, acc[3][5]);
        acc[0][6] = fma2(pp0, v67.x, acc[0][6]);
        acc[1][6] = fma2(pp1, v67.x, acc[1][6]);
        acc[2][6] = fma2(pp2, v67.x, acc[2][6]);
        acc[3][6] = fma2(pp3, v67.x, acc[3][6]);
        acc[0][7] = fma2(pp0, v67.y, acc[0][7]);
        acc[1][7] = fma2(pp1, v67.y, acc[1][7]);
        acc[2][7] = fma2(pp2, v67.y, acc[2][7]);
        acc[3][7] = fma2(pp3, v67.y, acc[3][7]);
    }

    int pidx = ((bh * 4 + kq) * 2 + qh) * 128 + t;
    {
        float lo, hi;
        float lv[4];
        #pragma unroll
        for (int i = 0; i < 4; i++) { unpk(l[i], lo, hi); lv[i] = lo + hi; }
        *(float4*)(g_plf + pidx * 4) = make_float4(lv[0], lv[1], lv[2], lv[3]);
        float* pa = g_paccf + (size_t)pidx * 32;
        #pragma unroll
        for (int i = 0; i < 4; i++) {
            float av[8];
            #pragma unroll
            for (int c = 0; c < 8; c++) { unpk(acc[i][c], lo, hi); av[c] = lo + hi; }
            *(float4*)(pa + i * 8)     = make_float4(av[0], av[1], av[2], av[3]);
            *(float4*)(pa + i * 8 + 4) = make_float4(av[4], av[5], av[6], av[7]);
        }
    }
}

// ---------------- attention pass 2: sum 4 partials, normalize ---------------
__global__ __launch_bounds__(256) void attn_p2_kernel()
{
    int idx = blockIdx.x * 256 + threadIdx.x;
    int bh = idx >> 8;
    int r  = idx & 255;
    int qh = r >> 7;
    int t  = r & 127;
    int b = bh >> 5;
    int h = bh & 31;

    float L[4] = {0.f, 0.f, 0.f, 0.f};
    float c[4][8];
    #pragma unroll
    for (int i = 0; i < 4; i++)
        #pragma unroll
        for (int j = 0; j < 8; j++) c[i][j] = 0.f;

    #pragma unroll
    for (int kq = 0; kq < 4; kq++) {
        int pidx = ((bh * 4 + kq) * 2 + qh) * 128 + t;
        float4 lv = *(const float4*)(g_plf + pidx * 4);
        L[0] += lv.x; L[1] += lv.y; L[2] += lv.z; L[3] += lv.w;
        const float4* pa = (const float4*)(g_paccf + (size_t)pidx * 32);
        #pragma unroll
        for (int i = 0; i < 4; i++) {
            float4 a0 = pa[2 * i], a1 = pa[2 * i + 1];
            c[i][0] += a0.x; c[i][1] += a0.y; c[i][2] += a0.z; c[i][3] += a0.w;
            c[i][4] += a1.x; c[i][5] += a1.y; c[i][6] += a1.z; c[i][7] += a1.w;
        }
    }

    #pragma unroll
    for (int i = 0; i < 4; i++) {
        float rr = 1.f / L[i];
        int q = qh * 512 + t + i * 128;
        float* o = g_ctx + ((size_t)b * S_ + q) * E_ + h * DK_;
        *(float4*)(o)     = make_float4(c[i][0] * rr, c[i][1] * rr, c[i][2] * rr, c[i][3] * rr);
        *(float4*)(o + 4) = make_float4(c[i][4] * rr, c[i][5] * rr, c[i][6] * rr, c[i][7] * rr);
    }
}

// ---------------- LN1 fused with qf: h = LN(a+b0+b1), qf from h row ---------
__global__ __launch_bounds__(256) void ln3q_kernel(
    const float* __restrict__ a, const float* __restrict__ bsrc0,
    const float* __restrict__ bsrc1,
    const float* __restrict__ g, const float* __restrict__ beta,
    const float* __restrict__ w_ip, const float* __restrict__ b_ip,
    const float* __restrict__ theta_ffn,
    float* __restrict__ out)
{
    int row  = (blockIdx.x * 256 + threadIdx.x) >> 5;
    int lane = threadIdx.x & 31;
    size_t off = (size_t)row * E_ + lane * 8;

    const float4* ap = (const float4*)(a + off);
    const float4* bp = (const float4*)(bsrc0 + off);
    const float4* cp = (const float4*)(bsrc1 + off);
    float4 a0 = ap[0], a1 = ap[1], b0 = bp[0], b1 = bp[1];
    float4 c0 = cp[0], c1 = cp[1];
    float v[8];
    v[0] = a0.x + b0.x + c0.x; v[1] = a0.y + b0.y + c0.y;
    v[2] = a0.z + b0.z + c0.z; v[3] = a0.w + b0.w + c0.w;
    v[4] = a1.x + b1.x + c1.x; v[5] = a1.y + b1.y + c1.y;
    v[6] = a1.z + b1.z + c1.z; v[7] = a1.w + b1.w + c1.w;

    float s = 0.f, ss = 0.f;
    #pragma unroll
    for (int i = 0; i < 8; i++) { s += v[i]; ss = fmaf(v[i], v[i], ss); }
    #pragma unroll
    for (int o = 16; o > 0; o >>= 1) {
        s  += __shfl_xor_sync(0xFFFFFFFFu, s,  o);
        ss += __shfl_xor_sync(0xFFFFFFFFu, ss, o);
    }
    float mu  = s * (1.f / E_);
    float var = ss * (1.f / E_) - mu * mu;
    float rs  = rsqrtf(var + 1e-5f);

    const float4* gp  = (const float4*)(g    + lane * 8);
    const float4* bep = (const float4*)(beta + lane * 8);
    float4 g0 = gp[0], g1v = gp[1], e0 = bep[0], e1 = bep[1];

    float hv[8];
    hv[0] = (v[0]-mu)*rs*g0.x + e0.x;  hv[1] = (v[1]-mu)*rs*g0.y + e0.y;
    hv[2] = (v[2]-mu)*rs*g0.z + e0.z;  hv[3] = (v[3]-mu)*rs*g0.w + e0.w;
    hv[4] = (v[4]-mu)*rs*g1v.x + e1.x; hv[5] = (v[5]-mu)*rs*g1v.y + e1.y;
    hv[6] = (v[6]-mu)*rs*g1v.z + e1.z; hv[7] = (v[7]-mu)*rs*g1v.w + e1.w;

    *(float4*)(out + off)     = make_float4(hv[0], hv[1], hv[2], hv[3]);
    *(float4*)(out + off + 4) = make_float4(hv[4], hv[5], hv[6], hv[7]);

    // qf: 8 dot products of h-row with w_ip rows (packed fma2 over e)
    ULL hp[4];
    hp[0] = pk(hv[0], hv[1]); hp[1] = pk(hv[2], hv[3]);
    hp[2] = pk(hv[4], hv[5]); hp[3] = pk(hv[6], hv[7]);

    ULL d[4];   // d[jj] = (dot_{2jj}, dot_{2jj+1}) partial per lane
    #pragma unroll
    for (int jj = 0; jj < 4; jj++) {
        const float* w0 = w_ip + (size_t)(2 * jj)     * E_ + lane * 8;
        const float* w1 = w_ip + (size_t)(2 * jj + 1) * E_ + lane * 8;
        float4 wa0 = *(const float4*)(w0);
        float4 wa1 = *(const float4*)(w0 + 4);
        float4 wb0 = *(const float4*)(w1);
        float4 wb1 = *(const float4*)(w1 + 4);
        ULL acc = mul2(hp[0], pk(wa0.x, wb0.x));
        acc = fma2(pk(hv[1], hv[1]), pk(wa0.y, wb0.y), acc);
        acc = fma2(pk(hv[2], hv[2]), pk(wa0.z, wb0.z), acc);
        acc = fma2(pk(hv[3], hv[3]), pk(wa0.w, wb0.w), acc);
        acc = fma2(pk(hv[4], hv[4]), pk(wa1.x, wb1.x), acc);
        acc = fma2(pk(hv[5], hv[5]), pk(wa1.y, wb1.y), acc);
        acc = fma2(pk(hv[6], hv[6]), pk(wa1.z, wb1.z), acc);
        acc = fma2(pk(hv[7], hv[7]), pk(wa1.w, wb1.w), acc);
        // note: first term must be hv[0] on both halves:
        // mul2(hp[0],...) used (hv0,hv1) x (wa0.x,wb0.x) -> wrong for hi half; fix:
        ULL corr = mul2(pk(hv[0], hv[0]), pk(wa0.x, wb0.x));
        // recompute cleanly:
        acc = corr;
        acc = fma2(pk(hv[1], hv[1]), pk(wa0.y, wb0.y), acc);
        acc = fma2(pk(hv[2], hv[2]), pk(wa0.z, wb0.z), acc);
        acc = fma2(pk(hv[3], hv[3]), pk(wa0.w, wb0.w), acc);
        acc = fma2(pk(hv[4], hv[4]), pk(wa1.x, wb1.x), acc);
        acc = fma2(pk(hv[5], hv[5]), pk(wa1.y, wb1.y), acc);
        acc = fma2(pk(hv[6], hv[6]), pk(wa1.z, wb1.z), acc);
        acc = fma2(pk(hv[7], hv[7]), pk(wa1.w, wb1.w), acc);
        d[jj] = acc;
    }

    // butterfly reduce the 4 packed sums across the warp
    #pragma unroll
    for (int o = 16; o > 0; o >>= 1) {
        #pragma unroll
        for (int jj = 0; jj < 4; jj++) {
            ULL other = __shfl_xor_sync(0xFFFFFFFFu, d[jj], o);
            d[jj] = add2(d[jj], other);
        }
    }

    if (lane < 8) {
        float lo, hi;
        unpk(d[lane >> 1], lo, hi);
        float sj = (lane & 1) ? hi : lo;
        g_qf[row * NQ_ + lane] =
            __cosf(theta_ffn[lane]) * __cosf(sj + b_ip[lane]);
    }
}

// ---------------- layernorm3: out = LN(a + b0 + b1) * g + beta --------------
__global__ __launch_bounds__(256) void ln3_kernel(
    const float* __restrict__ a, const float* __restrict__ bsrc0,
    const float* __restrict__ bsrc1,
    const float* __restrict__ g, const float* __restrict__ beta,
    float* __restrict__ out)
{
    int row  = (blockIdx.x * 256 + threadIdx.x) >> 5;
    int lane = threadIdx.x & 31;
    size_t off = (size_t)row * E_ + lane * 8;

    const float4* ap = (const float4*)(a + off);
    const float4* bp = (const float4*)(bsrc0 + off);
    const float4* cp = (const float4*)(bsrc1 + off);
    float4 a0 = ap[0], a1 = ap[1], b0 = bp[0], b1 = bp[1];
    float4 c0 = cp[0], c1 = cp[1];
    float v[8];
    v[0] = a0.x + b0.x + c0.x; v[1] = a0.y + b0.y + c0.y;
    v[2] = a0.z + b0.z + c0.z; v[3] = a0.w + b0.w + c0.w;
    v[4] = a1.x + b1.x + c1.x; v[5] = a1.y + b1.y + c1.y;
    v[6] = a1.z + b1.z + c1.z; v[7] = a1.w + b1.w + c1.w;

    float s = 0.f, ss = 0.f;
    #pragma unroll
    for (int i = 0; i < 8; i++) { s += v[i]; ss = fmaf(v[i], v[i], ss); }
    #pragma unroll
    for (int o = 16; o > 0; o >>= 1) {
        s  += __shfl_xor_sync(0xFFFFFFFFu, s,  o);
        ss += __shfl_xor_sync(0xFFFFFFFFu, ss, o);
    }
    float mu  = s * (1.f / E_);
    float var = ss * (1.f / E_) - mu * mu;
    float rs  = rsqrtf(var + 1e-5f);

    const float4* gp  = (const float4*)(g    + lane * 8);
    const float4* bep = (const float4*)(beta + lane * 8);
    float4 g0 = gp[0], g1v = gp[1], e0 = bep[0], e1 = bep[1];

    float4 w;
    w.x = (v[0]-mu)*rs*g0.x + e0.x; w.y = (v[1]-mu)*rs*g0.y + e0.y;
    w.z = (v[2]-mu)*rs*g0.z + e0.z; w.w = (v[3]-mu)*rs*g0.w + e0.w;
    *(float4*)(out + off) = w;
    w.x = (v[4]-mu)*rs*g1v.x + e1.x; w.y = (v[5]-mu)*rs*g1v.y + e1.y;
    w.z = (v[6]-mu)*rs*g1v.z + e1.z; w.w = (v[7]-mu)*rs*g1v.w + e1.w;
    *(float4*)(out + off + 4) = w;
}

// ---------------- hidden = relu(qf @ w1^T + b1), 4 outputs/thread -----------
__global__ __launch_bounds__(256) void hidden_kernel(
    const float* __restrict__ w1, const float* __restrict__ b1)
{
    int m = blockIdx.x;
    int f = threadIdx.x * 4;
    const float4* qp = (const float4*)(g_qf + (size_t)m * NQ_);
    float4 q0 = qp[0], q1 = qp[1];

    float4 outv;
    float* op = &outv.x;
    #pragma unroll
    for (int j = 0; j < 4; j++) {
        const float4* wr = (const float4*)(w1 + (size_t)(f + j) * NQ_);
        float4 w0 = wr[0], w1v = wr[1];
        float s = b1[f + j];
        s = fmaf(q0.x, w0.x, s);
        s = fmaf(q0.y, w0.y, s);
        s = fmaf(q0.z, w0.z, s);
        s = fmaf(q0.w, w0.w, s);
        s = fmaf(q1.x, w1v.x, s);
        s = fmaf(q1.y, w1v.y, s);
        s = fmaf(q1.z, w1v.z, s);
        s = fmaf(q1.w, w1v.w, s);
        op[j] = fmaxf(s, 0.f);
    }
    *(float4*)(g_hidden + (size_t)m * FF_ + f) = outv;
}

// ---------------- launch ----------------------------------------------------
extern "C" void kernel_launch(void* const* d_in, const int* in_sizes, int n_in,
                              void* d_out, int out_size)
{
    (void)in_sizes; (void)n_in; (void)out_size;

    const float* x          = (const float*)d_in[0];
    const float* theta_attn = (const float*)d_in[1];
    const float* w_in       = (const float*)d_in[2];
    const float* b_in       = (const float*)d_in[3];
    const float* w_out      = (const float*)d_in[4];
    const float* b_out      = (const float*)d_in[5];
    const float* w_comb     = (const float*)d_in[6];
    const float* b_comb     = (const float*)d_in[7];
    const float* g1         = (const float*)d_in[8];
    const float* be1        = (const float*)d_in[9];
    const float* g2         = (const float*)d_in[10];
    const float* be2        = (const float*)d_in[11];
    const float* w_ip       = (const float*)d_in[12];
    const float* b_ip       = (const float*)d_in[13];
    const float* theta_ffn  = (const float*)d_in[14];
    const float* w1         = (const float*)d_in[15];
    const float* b1         = (const float*)d_in[16];
    const float* w2         = (const float*)d_in[17];
    const float* b2         = (const float*)d_in[18];
    float* out = (float*)d_out;

    float *p_qout, *p_qkv, *p_qkv2, *p_ctx, *p_Wf, *p_bf, *p_tmp, *p_tmp2, *p_h, *p_hidden;
    cudaGetSymbolAddress((void**)&p_qout,   g_qout);
    cudaGetSymbolAddress((void**)&p_qkv,    g_qkv);
    cudaGetSymbolAddress((void**)&p_qkv2,   g_qkv2);
    cudaGetSymbolAddress((void**)&p_ctx,    g_ctx);
    cudaGetSymbolAddress((void**)&p_Wf,     g_Wf);
    cudaGetSymbolAddress((void**)&p_bf,     g_bf);
    cudaGetSymbolAddress((void**)&p_tmp,    g_tmp);
    cudaGetSymbolAddress((void**)&p_tmp2,   g_tmp2);
    cudaGetSymbolAddress((void**)&p_h,      g_h);
    cudaGetSymbolAddress((void**)&p_hidden, g_hidden);

    // 1. q_out = cos(x + theta)
    cos_encode_kernel<<<(M_ * E_) / 1024, 256>>>(x, theta_attn);

    // 2. fold w_comb @ w_out
    fold_w_kernel<<<E_, 256>>>(w_comb, w_out, b_out, b_comb);

    // 3. qkv partials = q_out @ w_in^T (+b_in), split-K=2  [4096 x 768]
    {
        dim3 grid((3 * E_) / 64, M_ / 128, 2);
        sgemm2s_kernel<<<grid, 256>>>(p_qout, w_in, b_in, p_qkv, p_qkv2,
                                      M_, 3 * E_, E_ / 2, E_);
    }

    // 4a. attention pass 1 (sums qkv partials during staging)
    {
        dim3 grid(4, 2, B_ * H_);
        attn_p1_kernel<<<grid, 128>>>();
    }
    // 4b. attention pass 2 (sum + normalize) -> ctx
    attn_p2_kernel<<<128, 256>>>();

    // 5. attn_out partials = ctx @ Wf^T (+bf), split-K=2   [4096 x 256]
    {
        dim3 grid(E_ / 64, M_ / 128, 2);
        sgemm2s_kernel<<<grid, 256>>>(p_ctx, p_Wf, p_bf, p_tmp, p_tmp2,
                                      M_, E_, E_ / 2, E_);
    }

    // 6. h = LN(x + tmp + tmp2) * g1 + be1 ; qf fused
    ln3q_kernel<<<M_ / 8, 256>>>(x, p_tmp, p_tmp2, g1, be1,
                                 w_ip, b_ip, theta_ffn, p_h);

    // 7. hidden = relu(qf @ w1^T + b1)    [4096 x 1024]
    hidden_kernel<<<M_, 256>>>(w1, b1);

    // 8. ffn_out partials = hidden @ w2^T (+b2), split-K=2  [4096 x 256]
    {
        dim3 grid(E_ / 64, M_ / 128, 2);
        sgemm2s_kernel<<<grid, 256>>>(p_hidden, w2, b2, p_tmp, p_tmp2,
                                      M_, E_, FF_ / 2, FF_);
    }

    // 9. out = LN(h + tmp + tmp2) * g2 + be2
    ln3_kernel<<<M_ / 8, 256>>>(p_h, p_tmp, p_tmp2, g2, be2, out);
}

// round 15
// speedup vs baseline: 1.1562x; 1.0059x over previous
#include <cuda_runtime.h>
#include <math.h>
#include <stdint.h>

// Problem constants
#define B_   4
#define S_   1024
#define E_   256
#define H_   32
#define DK_  8
#define NQ_  8
#define FF_  1024
#define M_   (B_ * S_)   // 4096

typedef unsigned long long ULL;

// ---------------- f32x2 packed math helpers (PTX-only on sm_103a) ----------
__device__ __forceinline__ ULL fma2(ULL a, ULL b, ULL c) {
    ULL d; asm("fma.rn.f32x2 %0, %1, %2, %3;" : "=l"(d) : "l"(a), "l"(b), "l"(c)); return d;
}
__device__ __forceinline__ ULL mul2(ULL a, ULL b) {
    ULL d; asm("mul.rn.f32x2 %0, %1, %2;" : "=l"(d) : "l"(a), "l"(b)); return d;
}
__device__ __forceinline__ ULL add2(ULL a, ULL b) {
    ULL d; asm("add.rn.f32x2 %0, %1, %2;" : "=l"(d) : "l"(a), "l"(b)); return d;
}
__device__ __forceinline__ ULL pk(float lo, float hi) {
    ULL r; asm("mov.b64 %0, {%1, %2};" : "=l"(r) : "f"(lo), "f"(hi)); return r;
}
__device__ __forceinline__ void unpk(ULL v, float& lo, float& hi) {
    asm("mov.b64 {%0, %1}, %2;" : "=f"(lo), "=f"(hi) : "l"(v));
}
__device__ __forceinline__ float ex2f_(float x) {
    float y; asm("ex2.approx.f32 %0, %1;" : "=f"(y) : "f"(x)); return y;
}

// ---------------- scratch (device globals; no runtime allocation) ----------
__device__ __align__(16) float g_qout[M_ * E_];
__device__ __align__(16) float g_qkv[M_ * 3 * E_];
__device__ __align__(16) float g_qkv2[M_ * 3 * E_];   // split-K partial
__device__ __align__(16) float g_ctx[M_ * E_];
__device__ __align__(16) float g_Wf[E_ * E_];
__device__ __align__(16) float g_bf[E_];
__device__ __align__(16) float g_tmp[M_ * E_];
__device__ __align__(16) float g_tmp2[M_ * E_];
__device__ __align__(16) float g_h[M_ * E_];
__device__ __align__(16) float g_qf[M_ * NQ_];
__device__ __align__(16) float g_hidden[M_ * FF_];
// split-K attention partials (plain floats; lo/hi combined in pass 1)
__device__ __align__(16) float g_plf[131072 * 4];
__device__ __align__(16) float g_paccf[(size_t)131072 * 32];

// ---------------- q_out = cos(x + theta[e % 8]), float4 --------------------
__global__ __launch_bounds__(256) void cos_encode_kernel(
    const float* __restrict__ x, const float* __restrict__ theta)
{
    int i = (blockIdx.x * 256 + threadIdx.x) * 4;
    float4 v = *(const float4*)(x + i);
    int j = i & 7;
    v.x = __cosf(v.x + theta[j + 0]);
    v.y = __cosf(v.y + theta[j + 1]);
    v.z = __cosf(v.z + theta[j + 2]);
    v.w = __cosf(v.w + theta[j + 3]);
    *(float4*)(g_qout + i) = v;
}

// ---------------- qkv = qkv + qkv2 (merge split-K partials) -----------------
__global__ __launch_bounds__(256) void qkv_sum_kernel()
{
    int i = (blockIdx.x * 256 + threadIdx.x) * 4;
    float4 a = *(const float4*)(g_qkv + i);
    float4 b = *(const float4*)(g_qkv2 + i);
    a.x += b.x; a.y += b.y; a.z += b.z; a.w += b.w;
    *(float4*)(g_qkv + i) = a;
}

// ---------------- fold: Wf = w_comb @ w_out, bf = w_comb@b_out + b_comb -----
__global__ __launch_bounds__(256) void fold_w_kernel(
    const float* __restrict__ w_comb, const float* __restrict__ w_out,
    const float* __restrict__ b_out, const float* __restrict__ b_comb)
{
    int i = blockIdx.x;
    int j = threadIdx.x;
    float s = 0.f;
    #pragma unroll 8
    for (int k = 0; k < E_; k++)
        s = fmaf(w_comb[i * E_ + k], w_out[k * E_ + j], s);
    g_Wf[i * E_ + j] = s;

    __shared__ float red[256];
    red[j] = w_comb[i * E_ + j] * b_out[j];
    __syncthreads();
    #pragma unroll
    for (int off = 128; off > 0; off >>= 1) {
        if (j < off) red[j] += red[j + off];
        __syncthreads();
    }
    if (j == 0) g_bf[i] = red[0] + b_comb[i];
}

// ---------------- split-K SGEMM: z-th CTA layer does K-half z ---------------
// Writes partial products: z=0 -> C0 (+bias), z=1 -> C1 (no bias).
__global__ __launch_bounds__(256) void sgemm2s_kernel(
    const float* __restrict__ A, const float* __restrict__ Bw,
    const float* __restrict__ bias,
    float* __restrict__ C0, float* __restrict__ C1,
    int M, int N, int Khalf, int lda)
{
    __shared__ float As[2][16][132];
    __shared__ float Bs[2][16][68];

    int tid = threadIdx.x;
    int bm = blockIdx.y * 128;
    int bn = blockIdx.x * 64;
    int z  = blockIdx.z;
    int ty = tid >> 4;
    int tx = tid & 15;

    int alr = tid >> 1;
    int alc = (tid & 1) * 8;
    int blr = tid >> 2;
    int blc = (tid & 3) * 4;

    const float* Aptr = A  + (size_t)(bm + alr) * lda + z * Khalf + alc;
    const float* Bptr = Bw + (size_t)(bn + blr) * lda + z * Khalf + blc;

    float4 a0 = *(const float4*)(Aptr);
    float4 a1 = *(const float4*)(Aptr + 4);
    float4 b0 = *(const float4*)(Bptr);

    ULL acc[4][4];
    #pragma unroll
    for (int r = 0; r < 4; r++)
        #pragma unroll
        for (int j = 0; j < 4; j++) acc[r][j] = 0ULL;

    As[0][alc + 0][alr] = a0.x; As[0][alc + 1][alr] = a0.y;
    As[0][alc + 2][alr] = a0.z; As[0][alc + 3][alr] = a0.w;
    As[0][alc + 4][alr] = a1.x; As[0][alc + 5][alr] = a1.y;
    As[0][alc + 6][alr] = a1.z; As[0][alc + 7][alr] = a1.w;
    Bs[0][blc + 0][blr] = b0.x; Bs[0][blc + 1][blr] = b0.y;
    Bs[0][blc + 2][blr] = b0.z; Bs[0][blc + 3][blr] = b0.w;
    __syncthreads();

    int buf = 0;
    for (int k0 = 0; ; k0 += 16) {
        bool last = (k0 + 16 >= Khalf);
        if (!last) {
            Aptr += 16; Bptr += 16;
            a0 = *(const float4*)(Aptr);
            a1 = *(const float4*)(Aptr + 4);
            b0 = *(const float4*)(Bptr);
        }

        #pragma unroll
        for (int kk = 0; kk < 16; kk++) {
            ulonglong2 am0 = *(const ulonglong2*)&As[buf][kk][ty * 8];
            ulonglong2 am1 = *(const ulonglong2*)&As[buf][kk][ty * 8 + 4];
            float4 b4 = *(const float4*)&Bs[buf][kk][tx * 4];
            ULL bb0 = pk(b4.x, b4.x), bb1 = pk(b4.y, b4.y);
            ULL bb2 = pk(b4.z, b4.z), bb3 = pk(b4.w, b4.w);
            ULL am[4] = {am0.x, am0.y, am1.x, am1.y};
            #pragma unroll
            for (int r = 0; r < 4; r++) {
                acc[r][0] = fma2(am[r], bb0, acc[r][0]);
                acc[r][1] = fma2(am[r], bb1, acc[r][1]);
                acc[r][2] = fma2(am[r], bb2, acc[r][2]);
                acc[r][3] = fma2(am[r], bb3, acc[r][3]);
            }
        }
        if (last) break;

        int nb = buf ^ 1;
        As[nb][alc + 0][alr] = a0.x; As[nb][alc + 1][alr] = a0.y;
        As[nb][alc + 2][alr] = a0.z; As[nb][alc + 3][alr] = a0.w;
        As[nb][alc + 4][alr] = a1.x; As[nb][alc + 5][alr] = a1.y;
        As[nb][alc + 6][alr] = a1.z; As[nb][alc + 7][alr] = a1.w;
        Bs[nb][blc + 0][blr] = b0.x; Bs[nb][blc + 1][blr] = b0.y;
        Bs[nb][blc + 2][blr] = b0.z; Bs[nb][blc + 3][blr] = b0.w;
        buf = nb;
        __syncthreads();
    }

    int col = bn + tx * 4;
    float bsel = (z == 0) ? 1.f : 0.f;
    float4 bb = *(const float4*)(bias + col);
    bb.x *= bsel; bb.y *= bsel; bb.z *= bsel; bb.w *= bsel;
    float* C = (z == 0) ? C0 : C1;
    #pragma unroll
    for (int r = 0; r < 4; r++) {
        float lo0, hi0, lo1, hi1, lo2v, hi2, lo3, hi3;
        unpk(acc[r][0], lo0, hi0);
        unpk(acc[r][1], lo1, hi1);
        unpk(acc[r][2], lo2v, hi2);
        unpk(acc[r][3], lo3, hi3);
        int row0 = bm + ty * 8 + 2 * r;
        *(float4*)(C + (size_t)row0 * N + col) =
            make_float4(lo0 + bb.x, lo1 + bb.y, lo2v + bb.z, lo3 + bb.w);
        *(float4*)(C + (size_t)(row0 + 1) * N + col) =
            make_float4(hi0 + bb.x, hi1 + bb.y, hi2 + bb.z, hi3 + bb.w);
    }
}

// ---------------- attention pass 1 (R13): keys-packed, no-max softmax -------
// grid = (4 key-quarters, 2 query-halves, 128 bh), 128 threads.
__global__ __launch_bounds__(128) void attn_p1_kernel()
{
    __shared__ ULL Kp[128 * 8];
    __shared__ ULL Vp[128 * 8];

    int kq = blockIdx.x;
    int qh = blockIdx.y;
    int bh = blockIdx.z;
    int b = bh >> 5;
    int h = bh & 31;
    int t = threadIdx.x;
    const float* base = g_qkv + (size_t)b * S_ * (3 * E_) + h * DK_;

    {
        const float* ra = base + (size_t)(kq * 256 + 2 * t) * (3 * E_);
        const float* rb = ra + 3 * E_;
        float4 ka0 = *(const float4*)(ra + E_);
        float4 ka1 = *(const float4*)(ra + E_ + 4);
        float4 kb0 = *(const float4*)(rb + E_);
        float4 kb1 = *(const float4*)(rb + E_ + 4);
        ulonglong2* kw = (ulonglong2*)(Kp + t * 8);
        kw[0] = make_ulonglong2(pk(ka0.x, kb0.x), pk(ka0.y, kb0.y));
        kw[1] = make_ulonglong2(pk(ka0.z, kb0.z), pk(ka0.w, kb0.w));
        kw[2] = make_ulonglong2(pk(ka1.x, kb1.x), pk(ka1.y, kb1.y));
        kw[3] = make_ulonglong2(pk(ka1.z, kb1.z), pk(ka1.w, kb1.w));
        float4 va0 = *(const float4*)(ra + 2 * E_);
        float4 va1 = *(const float4*)(ra + 2 * E_ + 4);
        float4 vb0 = *(const float4*)(rb + 2 * E_);
        float4 vb1 = *(const float4*)(rb + 2 * E_ + 4);
        ulonglong2* vw = (ulonglong2*)(Vp + t * 8);
        vw[0] = make_ulonglong2(pk(va0.x, vb0.x), pk(va0.y, vb0.y));
        vw[1] = make_ulonglong2(pk(va0.z, vb0.z), pk(va0.w, vb0.w));
        vw[2] = make_ulonglong2(pk(va1.x, vb1.x), pk(va1.y, vb1.y));
        vw[3] = make_ulonglong2(pk(va1.z, vb1.z), pk(va1.w, vb1.w));
    }
    __syncthreads();

    const float qscale = 0.35355339059327373f * 1.4426950408889634f;

    ULL qd[4][8];
    #pragma unroll
    for (int i = 0; i < 4; i++) {
        const float* r = base + (size_t)(qh * 512 + t + i * 128) * (3 * E_);
        float4 q0 = *(const float4*)(r);
        float4 q1 = *(const float4*)(r + 4);
        float s;
        s = q0.x * qscale; qd[i][0] = pk(s, s);
        s = q0.y * qscale; qd[i][1] = pk(s, s);
        s = q0.z * qscale; qd[i][2] = pk(s, s);
        s = q0.w * qscale; qd[i][3] = pk(s, s);
        s = q1.x * qscale; qd[i][4] = pk(s, s);
        s = q1.y * qscale; qd[i][5] = pk(s, s);
        s = q1.z * qscale; qd[i][6] = pk(s, s);
        s = q1.w * qscale; qd[i][7] = pk(s, s);
    }

    ULL l[4] = {0ULL, 0ULL, 0ULL, 0ULL};
    ULL acc[4][8];
    #pragma unroll
    for (int i = 0; i < 4; i++)
        #pragma unroll
        for (int c = 0; c < 8; c++) acc[i][c] = 0ULL;

    #pragma unroll 1
    for (int sp = 0; sp < 128; sp++) {
        const ulonglong2* kr = (const ulonglong2*)(Kp + sp * 8);
        ulonglong2 k01 = kr[0], k23 = kr[1], k45 = kr[2], k67 = kr[3];

        ULL t0 = mul2(qd[0][0], k01.x);
        ULL t1 = mul2(qd[1][0], k01.x);
        ULL t2 = mul2(qd[2][0], k01.x);
        ULL t3 = mul2(qd[3][0], k01.x);
        t0 = fma2(qd[0][1], k01.y, t0);
        t1 = fma2(qd[1][1], k01.y, t1);
        t2 = fma2(qd[2][1], k01.y, t2);
        t3 = fma2(qd[3][1], k01.y, t3);
        t0 = fma2(qd[0][2], k23.x, t0);
        t1 = fma2(qd[1][2], k23.x, t1);
        t2 = fma2(qd[2][2], k23.x, t2);
        t3 = fma2(qd[3][2], k23.x, t3);
        t0 = fma2(qd[0][3], k23.y, t0);
        t1 = fma2(qd[1][3], k23.y, t1);
        t2 = fma2(qd[2][3], k23.y, t2);
        t3 = fma2(qd[3][3], k23.y, t3);
        t0 = fma2(qd[0][4], k45.x, t0);
        t1 = fma2(qd[1][4], k45.x, t1);
        t2 = fma2(qd[2][4], k45.x, t2);
        t3 = fma2(qd[3][4], k45.x, t3);
        t0 = fma2(qd[0][5], k45.y, t0);
        t1 = fma2(qd[1][5], k45.y, t1);
        t2 = fma2(qd[2][5], k45.y, t2);
        t3 = fma2(qd[3][5], k45.y, t3);
        t0 = fma2(qd[0][6], k67.x, t0);
        t1 = fma2(qd[1][6], k67.x, t1);
        t2 = fma2(qd[2][6], k67.x, t2);
        t3 = fma2(qd[3][6], k67.x, t3);
        t0 = fma2(qd[0][7], k67.y, t0);
        t1 = fma2(qd[1][7], k67.y, t1);
        t2 = fma2(qd[2][7], k67.y, t2);
        t3 = fma2(qd[3][7], k67.y, t3);

        float d0, d1;
        unpk(t0, d0, d1);
        ULL pp0 = pk(ex2f_(d0), ex2f_(d1));
        unpk(t1, d0, d1);
        ULL pp1 = pk(ex2f_(d0), ex2f_(d1));
        unpk(t2, d0, d1);
        ULL pp2 = pk(ex2f_(d0), ex2f_(d1));
        unpk(t3, d0, d1);
        ULL pp3 = pk(ex2f_(d0), ex2f_(d1));
        l[0] = add2(l[0], pp0);
        l[1] = add2(l[1], pp1);
        l[2] = add2(l[2], pp2);
        l[3] = add2(l[3], pp3);

        const ulonglong2* vr = (const ulonglong2*)(Vp + sp * 8);
        ulonglong2 v01 = vr[0], v23 = vr[1], v45 = vr[2], v67 = vr[3];
        acc[0][0] = fma2(pp0, v01.x, acc[0][0]);
        acc[1][0] = fma2(pp1, v01.x, acc[1][0]);
        acc[2][0] = fma2(pp2, v01.x, acc[2][0]);
        acc[3][0] = fma2(pp3, v01.x, acc[3][0]);
        acc[0][1] = fma2(pp0, v01.y, acc[0][1]);
        acc[1][1] = fma2(pp1, v01.y, acc[1][1]);
        acc[2][1] = fma2(pp2, v01.y, acc[2][1]);
        acc[3][1] = fma2(pp3, v01.y, acc[3][1]);
        acc[0][2] = fma2(pp0, v23.x, acc[0][2]);
        acc[1][2] = fma2(pp1, v23.x, acc[1][2]);
        acc[2][2] = fma2(pp2, v23.x, acc[2][2]);
        acc[3][2] = fma2(pp3, v23.x, acc[3][2]);
        acc[0][3] = fma2(pp0, v23.y, acc[0][3]);
        acc[1][3] = fma2(pp1, v23.y, acc[1][3]);
        acc[2][3] = fma2(pp2, v23.y, acc[2][3]);
        acc[3][3] = fma2(pp3, v23.y, acc[3][3]);
        acc[0][4] = fma2(pp0, v45.x, acc[0][4]);
        acc[1][4] = fma2(pp1, v45.x, acc[1][4]);
        acc[2][4] = fma2(pp2, v45.x, acc[2][4]);
        acc[3][4] = fma2(pp3, v45.x, acc[3][4]);
        acc[0][5] = fma2(pp0, v45.y, acc[0][5]);
        acc[1][5] = fma2(pp1, v45.y, acc[1][5]);
        acc[2][5] = fma2(pp2, v45.y, acc[2][5]);
        acc[3][5] = fma2(pp3, v45.y, acc[3][5]);
        acc[0][6] = fma2(pp0, v67.x, acc[0][6]);
        acc[1][6] = fma2(pp1, v67.x, acc[1][6]);
        acc[2][6] = fma2(pp2, v67.x, acc[2][6]);
        acc[3][6] = fma2(pp3, v67.x, acc[3][6]);
        acc[0][7] = fma2(pp0, v67.y, acc[0][7]);
        acc[1][7] = fma2(pp1, v67.y, acc[1][7]);
        acc[2][7] = fma2(pp2, v67.y, acc[2][7]);
        acc[3][7] = fma2(pp3, v67.y, acc[3][7]);
    }

    int pidx = ((bh * 4 + kq) * 2 + qh) * 128 + t;
    {
        float lo, hi;
        float lv[4];
        #pragma unroll
        for (int i = 0; i < 4; i++) { unpk(l[i], lo, hi); lv[i] = lo + hi; }
        *(float4*)(g_plf + pidx * 4) = make_float4(lv[0], lv[1], lv[2], lv[3]);
        float* pa = g_paccf + (size_t)pidx * 32;
        #pragma unroll
        for (int i = 0; i < 4; i++) {
            float av[8];
            #pragma unroll
            for (int c = 0; c < 8; c++) { unpk(acc[i][c], lo, hi); av[c] = lo + hi; }
            *(float4*)(pa + i * 8)     = make_float4(av[0], av[1], av[2], av[3]);
            *(float4*)(pa + i * 8 + 4) = make_float4(av[4], av[5], av[6], av[7]);
        }
    }
}

// ---------------- attention pass 2: sum 4 partials, normalize ---------------
__global__ __launch_bounds__(256) void attn_p2_kernel()
{
    int idx = blockIdx.x * 256 + threadIdx.x;
    int bh = idx >> 8;
    int r  = idx & 255;
    int qh = r >> 7;
    int t  = r & 127;
    int b = bh >> 5;
    int h = bh & 31;

    float L[4] = {0.f, 0.f, 0.f, 0.f};
    float c[4][8];
    #pragma unroll
    for (int i = 0; i < 4; i++)
        #pragma unroll
        for (int j = 0; j < 8; j++) c[i][j] = 0.f;

    #pragma unroll
    for (int kq = 0; kq < 4; kq++) {
        int pidx = ((bh * 4 + kq) * 2 + qh) * 128 + t;
        float4 lv = *(const float4*)(g_plf + pidx * 4);
        L[0] += lv.x; L[1] += lv.y; L[2] += lv.z; L[3] += lv.w;
        const float4* pa = (const float4*)(g_paccf + (size_t)pidx * 32);
        #pragma unroll
        for (int i = 0; i < 4; i++) {
            float4 a0 = pa[2 * i], a1 = pa[2 * i + 1];
            c[i][0] += a0.x; c[i][1] += a0.y; c[i][2] += a0.z; c[i][3] += a0.w;
            c[i][4] += a1.x; c[i][5] += a1.y; c[i][6] += a1.z; c[i][7] += a1.w;
        }
    }

    #pragma unroll
    for (int i = 0; i < 4; i++) {
        float rr = 1.f / L[i];
        int q = qh * 512 + t + i * 128;
        float* o = g_ctx + ((size_t)b * S_ + q) * E_ + h * DK_;
        *(float4*)(o)     = make_float4(c[i][0] * rr, c[i][1] * rr, c[i][2] * rr, c[i][3] * rr);
        *(float4*)(o + 4) = make_float4(c[i][4] * rr, c[i][5] * rr, c[i][6] * rr, c[i][7] * rr);
    }
}

// ---------------- LN1 fused with qf: h = LN(a+b0+b1), qf from h row ---------
__global__ __launch_bounds__(256) void ln3q_kernel(
    const float* __restrict__ a, const float* __restrict__ bsrc0,
    const float* __restrict__ bsrc1,
    const float* __restrict__ g, const float* __restrict__ beta,
    const float* __restrict__ w_ip, const float* __restrict__ b_ip,
    const float* __restrict__ theta_ffn,
    float* __restrict__ out)
{
    int row  = (blockIdx.x * 256 + threadIdx.x) >> 5;
    int lane = threadIdx.x & 31;
    size_t off = (size_t)row * E_ + lane * 8;

    const float4* ap = (const float4*)(a + off);
    const float4* bp = (const float4*)(bsrc0 + off);
    const float4* cp = (const float4*)(bsrc1 + off);
    float4 a0 = ap[0], a1 = ap[1], b0 = bp[0], b1 = bp[1];
    float4 c0 = cp[0], c1 = cp[1];
    float v[8];
    v[0] = a0.x + b0.x + c0.x; v[1] = a0.y + b0.y + c0.y;
    v[2] = a0.z + b0.z + c0.z; v[3] = a0.w + b0.w + c0.w;
    v[4] = a1.x + b1.x + c1.x; v[5] = a1.y + b1.y + c1.y;
    v[6] = a1.z + b1.z + c1.z; v[7] = a1.w + b1.w + c1.w;

    float s = 0.f, ss = 0.f;
    #pragma unroll
    for (int i = 0; i < 8; i++) { s += v[i]; ss = fmaf(v[i], v[i], ss); }
    #pragma unroll
    for (int o = 16; o > 0; o >>= 1) {
        s  += __shfl_xor_sync(0xFFFFFFFFu, s,  o);
        ss += __shfl_xor_sync(0xFFFFFFFFu, ss, o);
    }
    float mu  = s * (1.f / E_);
    float var = ss * (1.f / E_) - mu * mu;
    float rs  = rsqrtf(var + 1e-5f);

    const float4* gp  = (const float4*)(g    + lane * 8);
    const float4* bep = (const float4*)(beta + lane * 8);
    float4 g0 = gp[0], g1v = gp[1], e0 = bep[0], e1 = bep[1];

    float hv[8];
    hv[0] = (v[0]-mu)*rs*g0.x + e0.x;  hv[1] = (v[1]-mu)*rs*g0.y + e0.y;
    hv[2] = (v[2]-mu)*rs*g0.z + e0.z;  hv[3] = (v[3]-mu)*rs*g0.w + e0.w;
    hv[4] = (v[4]-mu)*rs*g1v.x + e1.x; hv[5] = (v[5]-mu)*rs*g1v.y + e1.y;
    hv[6] = (v[6]-mu)*rs*g1v.z + e1.z; hv[7] = (v[7]-mu)*rs*g1v.w + e1.w;

    *(float4*)(out + off)     = make_float4(hv[0], hv[1], hv[2], hv[3]);
    *(float4*)(out + off + 4) = make_float4(hv[4], hv[5], hv[6], hv[7]);

    // qf: 8 dot products of h-row with w_ip rows (packed fma2 over e)
    ULL d[4];   // d[jj] = (dot_{2jj}, dot_{2jj+1}) partial per lane
    #pragma unroll
    for (int jj = 0; jj < 4; jj++) {
        const float* w0 = w_ip + (size_t)(2 * jj)     * E_ + lane * 8;
        const float* w1 = w_ip + (size_t)(2 * jj + 1) * E_ + lane * 8;
        float4 wa0 = *(const float4*)(w0);
        float4 wa1 = *(const float4*)(w0 + 4);
        float4 wb0 = *(const float4*)(w1);
        float4 wb1 = *(const float4*)(w1 + 4);
        ULL acc = mul2(pk(hv[0], hv[0]), pk(wa0.x, wb0.x));
        acc = fma2(pk(hv[1], hv[1]), pk(wa0.y, wb0.y), acc);
        acc = fma2(pk(hv[2], hv[2]), pk(wa0.z, wb0.z), acc);
        acc = fma2(pk(hv[3], hv[3]), pk(wa0.w, wb0.w), acc);
        acc = fma2(pk(hv[4], hv[4]), pk(wa1.x, wb1.x), acc);
        acc = fma2(pk(hv[5], hv[5]), pk(wa1.y, wb1.y), acc);
        acc = fma2(pk(hv[6], hv[6]), pk(wa1.z, wb1.z), acc);
        acc = fma2(pk(hv[7], hv[7]), pk(wa1.w, wb1.w), acc);
        d[jj] = acc;
    }

    #pragma unroll
    for (int o = 16; o > 0; o >>= 1) {
        #pragma unroll
        for (int jj = 0; jj < 4; jj++) {
            ULL other = __shfl_xor_sync(0xFFFFFFFFu, d[jj], o);
            d[jj] = add2(d[jj], other);
        }
    }

    if (lane < 8) {
        float lo, hi;
        unpk(d[lane >> 1], lo, hi);
        float sj = (lane & 1) ? hi : lo;
        g_qf[row * NQ_ + lane] =
            __cosf(theta_ffn[lane]) * __cosf(sj + b_ip[lane]);
    }
}

// ---------------- layernorm3: out = LN(a + b0 + b1) * g + beta --------------
__global__ __launch_bounds__(256) void ln3_kernel(
    const float* __restrict__ a, const float* __restrict__ bsrc0,
    const float* __restrict__ bsrc1,
    const float* __restrict__ g, const float* __restrict__ beta,
    float* __restrict__ out)
{
    int row  = (blockIdx.x * 256 + threadIdx.x) >> 5;
    int lane = threadIdx.x & 31;
    size_t off = (size_t)row * E_ + lane * 8;

    const float4* ap = (const float4*)(a + off);
    const float4* bp = (const float4*)(bsrc0 + off);
    const float4* cp = (const float4*)(bsrc1 + off);
    float4 a0 = ap[0], a1 = ap[1], b0 = bp[0], b1 = bp[1];
    float4 c0 = cp[0], c1 = cp[1];
    float v[8];
    v[0] = a0.x + b0.x + c0.x; v[1] = a0.y + b0.y + c0.y;
    v[2] = a0.z + b0.z + c0.z; v[3] = a0.w + b0.w + c0.w;
    v[4] = a1.x + b1.x + c1.x; v[5] = a1.y + b1.y + c1.y;
    v[6] = a1.z + b1.z + c1.z; v[7] = a1.w + b1.w + c1.w;

    float s = 0.f, ss = 0.f;
    #pragma unroll
    for (int i = 0; i < 8; i++) { s += v[i]; ss = fmaf(v[i], v[i], ss); }
    #pragma unroll
    for (int o = 16; o > 0; o >>= 1) {
        s  += __shfl_xor_sync(0xFFFFFFFFu, s,  o);
        ss += __shfl_xor_sync(0xFFFFFFFFu, ss, o);
    }
    float mu  = s * (1.f / E_);
    float var = ss * (1.f / E_) - mu * mu;
    float rs  = rsqrtf(var + 1e-5f);

    const float4* gp  = (const float4*)(g    + lane * 8);
    const float4* bep = (const float4*)(beta + lane * 8);
    float4 g0 = gp[0], g1v = gp[1], e0 = bep[0], e1 = bep[1];

    float4 w;
    w.x = (v[0]-mu)*rs*g0.x + e0.x; w.y = (v[1]-mu)*rs*g0.y + e0.y;
    w.z = (v[2]-mu)*rs*g0.z + e0.z; w.w = (v[3]-mu)*rs*g0.w + e0.w;
    *(float4*)(out + off) = w;
    w.x = (v[4]-mu)*rs*g1v.x + e1.x; w.y = (v[5]-mu)*rs*g1v.y + e1.y;
    w.z = (v[6]-mu)*rs*g1v.z + e1.z; w.w = (v[7]-mu)*rs*g1v.w + e1.w;
    *(float4*)(out + off + 4) = w;
}

// ---------------- hidden = relu(qf @ w1^T + b1), 4 outputs/thread -----------
__global__ __launch_bounds__(256) void hidden_kernel(
    const float* __restrict__ w1, const float* __restrict__ b1)
{
    int m = blockIdx.x;
    int f = threadIdx.x * 4;
    const float4* qp = (const float4*)(g_qf + (size_t)m * NQ_);
    float4 q0 = qp[0], q1 = qp[1];

    float4 outv;
    float* op = &outv.x;
    #pragma unroll
    for (int j = 0; j < 4; j++) {
        const float4* wr = (const float4*)(w1 + (size_t)(f + j) * NQ_);
        float4 w0 = wr[0], w1v = wr[1];
        float s = b1[f + j];
        s = fmaf(q0.x, w0.x, s);
        s = fmaf(q0.y, w0.y, s);
        s = fmaf(q0.z, w0.z, s);
        s = fmaf(q0.w, w0.w, s);
        s = fmaf(q1.x, w1v.x, s);
        s = fmaf(q1.y, w1v.y, s);
        s = fmaf(q1.z, w1v.z, s);
        s = fmaf(q1.w, w1v.w, s);
        op[j] = fmaxf(s, 0.f);
    }
    *(float4*)(g_hidden + (size_t)m * FF_ + f) = outv;
}

// ---------------- launch ----------------------------------------------------
extern "C" void kernel_launch(void* const* d_in, const int* in_sizes, int n_in,
                              void* d_out, int out_size)
{
    (void)in_sizes; (void)n_in; (void)out_size;

    const float* x          = (const float*)d_in[0];
    const float* theta_attn = (const float*)d_in[1];
    const float* w_in       = (const float*)d_in[2];
    const float* b_in       = (const float*)d_in[3];
    const float* w_out      = (const float*)d_in[4];
    const float* b_out      = (const float*)d_in[5];
    const float* w_comb     = (const float*)d_in[6];
    const float* b_comb     = (const float*)d_in[7];
    const float* g1         = (const float*)d_in[8];
    const float* be1        = (const float*)d_in[9];
    const float* g2         = (const float*)d_in[10];
    const float* be2        = (const float*)d_in[11];
    const float* w_ip       = (const float*)d_in[12];
    const float* b_ip       = (const float*)d_in[13];
    const float* theta_ffn  = (const float*)d_in[14];
    const float* w1         = (const float*)d_in[15];
    const float* b1         = (const float*)d_in[16];
    const float* w2         = (const float*)d_in[17];
    const float* b2         = (const float*)d_in[18];
    float* out = (float*)d_out;

    float *p_qout, *p_qkv, *p_qkv2, *p_ctx, *p_Wf, *p_bf, *p_tmp, *p_tmp2, *p_h, *p_hidden;
    cudaGetSymbolAddress((void**)&p_qout,   g_qout);
    cudaGetSymbolAddress((void**)&p_qkv,    g_qkv);
    cudaGetSymbolAddress((void**)&p_qkv2,   g_qkv2);
    cudaGetSymbolAddress((void**)&p_ctx,    g_ctx);
    cudaGetSymbolAddress((void**)&p_Wf,     g_Wf);
    cudaGetSymbolAddress((void**)&p_bf,     g_bf);
    cudaGetSymbolAddress((void**)&p_tmp,    g_tmp);
    cudaGetSymbolAddress((void**)&p_tmp2,   g_tmp2);
    cudaGetSymbolAddress((void**)&p_h,      g_h);
    cudaGetSymbolAddress((void**)&p_hidden, g_hidden);

    // 1. q_out = cos(x + theta)
    cos_encode_kernel<<<(M_ * E_) / 1024, 256>>>(x, theta_attn);

    // 2. fold w_comb @ w_out
    fold_w_kernel<<<E_, 256>>>(w_comb, w_out, b_out, b_comb);

    // 3. qkv partials = q_out @ w_in^T (+b_in), split-K=2  [4096 x 768]
    {
        dim3 grid((3 * E_) / 64, M_ / 128, 2);
        sgemm2s_kernel<<<grid, 256>>>(p_qout, w_in, b_in, p_qkv, p_qkv2,
                                      M_, 3 * E_, E_ / 2, E_);
    }
    // 3b. merge partials once (dedups the per-CTA summing in attn_p1)
    qkv_sum_kernel<<<(M_ * 3 * E_) / 1024, 256>>>();

    // 4a. attention pass 1 (split-K=4 partials, keys-packed)
    {
        dim3 grid(4, 2, B_ * H_);
        attn_p1_kernel<<<grid, 128>>>();
    }
    // 4b. attention pass 2 (sum + normalize) -> ctx
    attn_p2_kernel<<<128, 256>>>();

    // 5. attn_out partials = ctx @ Wf^T (+bf), split-K=2   [4096 x 256]
    {
        dim3 grid(E_ / 64, M_ / 128, 2);
        sgemm2s_kernel<<<grid, 256>>>(p_ctx, p_Wf, p_bf, p_tmp, p_tmp2,
                                      M_, E_, E_ / 2, E_);
    }

    // 6. h = LN(x + tmp + tmp2) * g1 + be1 ; qf fused
    ln3q_kernel<<<M_ / 8, 256>>>(x, p_tmp, p_tmp2, g1, be1,
                                 w_ip, b_ip, theta_ffn, p_h);

    // 7. hidden = relu(qf @ w1^T + b1)    [4096 x 1024]
    hidden_kernel<<<M_, 256>>>(w1, b1);

    // 8. ffn_out partials = hidden @ w2^T (+b2), split-K=2  [4096 x 256]
    {
        dim3 grid(E_ / 64, M_ / 128, 2);
        sgemm2s_kernel<<<grid, 256>>>(p_hidden, w2, b2, p_tmp, p_tmp2,
                                      M_, E_, FF_ / 2, FF_);
    }

    // 9. out = LN(h + tmp + tmp2) * g2 + be2
    ln3_kernel<<<M_ / 8, 256>>>(p_h, p_tmp, p_tmp2, g2, be2, out);
}

// round 16
// speedup vs baseline: 1.2353x; 1.0684x over previous
#include <cuda_runtime.h>
#include <math.h>
#include <stdint.h>

// Problem constants
#define B_   4
#define S_   1024
#define E_   256
#define H_   32
#define DK_  8
#define NQ_  8
#define FF_  1024
#define M_   (B_ * S_)   // 4096

typedef unsigned long long ULL;

// ---------------- f32x2 packed math helpers (PTX-only on sm_103a) ----------
__device__ __forceinline__ ULL fma2(ULL a, ULL b, ULL c) {
    ULL d; asm("fma.rn.f32x2 %0, %1, %2, %3;" : "=l"(d) : "l"(a), "l"(b), "l"(c)); return d;
}
__device__ __forceinline__ ULL mul2(ULL a, ULL b) {
    ULL d; asm("mul.rn.f32x2 %0, %1, %2;" : "=l"(d) : "l"(a), "l"(b)); return d;
}
__device__ __forceinline__ ULL add2(ULL a, ULL b) {
    ULL d; asm("add.rn.f32x2 %0, %1, %2;" : "=l"(d) : "l"(a), "l"(b)); return d;
}
__device__ __forceinline__ ULL pk(float lo, float hi) {
    ULL r; asm("mov.b64 %0, {%1, %2};" : "=l"(r) : "f"(lo), "f"(hi)); return r;
}
__device__ __forceinline__ void unpk(ULL v, float& lo, float& hi) {
    asm("mov.b64 {%0, %1}, %2;" : "=f"(lo), "=f"(hi) : "l"(v));
}
__device__ __forceinline__ float ex2f_(float x) {
    float y; asm("ex2.approx.f32 %0, %1;" : "=f"(y) : "f"(x)); return y;
}

// ---------------- scratch (device globals; no runtime allocation) ----------
__device__ __align__(16) float g_qout[M_ * E_];
__device__ __align__(16) float g_qkv[M_ * 3 * E_];
__device__ __align__(16) float g_qkv2[M_ * 3 * E_];   // split-K partial
__device__ __align__(16) float g_ctx[M_ * E_];
__device__ __align__(16) float g_Wf[E_ * E_];
__device__ __align__(16) float g_bf[E_];
__device__ __align__(16) float g_tmp[M_ * E_];
__device__ __align__(16) float g_tmp2[M_ * E_];
__device__ __align__(16) float g_h[M_ * E_];
__device__ __align__(16) float g_qf[M_ * NQ_];
__device__ __align__(16) float g_hidden[M_ * FF_];
// split-K attention partials (plain floats; lo/hi combined in pass 1)
__device__ __align__(16) float g_plf[131072 * 4];
__device__ __align__(16) float g_paccf[(size_t)131072 * 32];

// ---------------- q_out = cos(x + theta[e % 8]), float4 --------------------
__global__ __launch_bounds__(256) void cos_encode_kernel(
    const float* __restrict__ x, const float* __restrict__ theta)
{
    int i = (blockIdx.x * 256 + threadIdx.x) * 4;
    float4 v = *(const float4*)(x + i);
    int j = i & 7;
    v.x = __cosf(v.x + theta[j + 0]);
    v.y = __cosf(v.y + theta[j + 1]);
    v.z = __cosf(v.z + theta[j + 2]);
    v.w = __cosf(v.w + theta[j + 3]);
    *(float4*)(g_qout + i) = v;
}

// ---------------- qkv = qkv + qkv2 (merge split-K partials) -----------------
__global__ __launch_bounds__(256) void qkv_sum_kernel()
{
    int i = (blockIdx.x * 256 + threadIdx.x) * 4;
    float4 a = *(const float4*)(g_qkv + i);
    float4 b = *(const float4*)(g_qkv2 + i);
    a.x += b.x; a.y += b.y; a.z += b.z; a.w += b.w;
    *(float4*)(g_qkv + i) = a;
}

// ---------------- fold: Wf = w_comb @ w_out, bf = w_comb@b_out + b_comb -----
__global__ __launch_bounds__(256) void fold_w_kernel(
    const float* __restrict__ w_comb, const float* __restrict__ w_out,
    const float* __restrict__ b_out, const float* __restrict__ b_comb)
{
    int i = blockIdx.x;
    int j = threadIdx.x;
    float s = 0.f;
    #pragma unroll 8
    for (int k = 0; k < E_; k++)
        s = fmaf(w_comb[i * E_ + k], w_out[k * E_ + j], s);
    g_Wf[i * E_ + j] = s;

    __shared__ float red[256];
    red[j] = w_comb[i * E_ + j] * b_out[j];
    __syncthreads();
    #pragma unroll
    for (int off = 128; off > 0; off >>= 1) {
        if (j < off) red[j] += red[j + off];
        __syncthreads();
    }
    if (j == 0) g_bf[i] = red[0] + b_comb[i];
}

// ---------------- split-K SGEMM: z-th CTA layer does K-half z ---------------
// Writes partial products: z=0 -> C0 (+bias), z=1 -> C1 (no bias).
__global__ __launch_bounds__(256) void sgemm2s_kernel(
    const float* __restrict__ A, const float* __restrict__ Bw,
    const float* __restrict__ bias,
    float* __restrict__ C0, float* __restrict__ C1,
    int M, int N, int Khalf, int lda)
{
    __shared__ float As[2][16][132];
    __shared__ float Bs[2][16][68];

    int tid = threadIdx.x;
    int bm = blockIdx.y * 128;
    int bn = blockIdx.x * 64;
    int z  = blockIdx.z;
    int ty = tid >> 4;
    int tx = tid & 15;

    int alr = tid >> 1;
    int alc = (tid & 1) * 8;
    int blr = tid >> 2;
    int blc = (tid & 3) * 4;

    const float* Aptr = A  + (size_t)(bm + alr) * lda + z * Khalf + alc;
    const float* Bptr = Bw + (size_t)(bn + blr) * lda + z * Khalf + blc;

    float4 a0 = *(const float4*)(Aptr);
    float4 a1 = *(const float4*)(Aptr + 4);
    float4 b0 = *(const float4*)(Bptr);

    ULL acc[4][4];
    #pragma unroll
    for (int r = 0; r < 4; r++)
        #pragma unroll
        for (int j = 0; j < 4; j++) acc[r][j] = 0ULL;

    As[0][alc + 0][alr] = a0.x; As[0][alc + 1][alr] = a0.y;
    As[0][alc + 2][alr] = a0.z; As[0][alc + 3][alr] = a0.w;
    As[0][alc + 4][alr] = a1.x; As[0][alc + 5][alr] = a1.y;
    As[0][alc + 6][alr] = a1.z; As[0][alc + 7][alr] = a1.w;
    Bs[0][blc + 0][blr] = b0.x; Bs[0][blc + 1][blr] = b0.y;
    Bs[0][blc + 2][blr] = b0.z; Bs[0][blc + 3][blr] = b0.w;
    __syncthreads();

    int buf = 0;
    for (int k0 = 0; ; k0 += 16) {
        bool last = (k0 + 16 >= Khalf);
        if (!last) {
            Aptr += 16; Bptr += 16;
            a0 = *(const float4*)(Aptr);
            a1 = *(const float4*)(Aptr + 4);
            b0 = *(const float4*)(Bptr);
        }

        #pragma unroll
        for (int kk = 0; kk < 16; kk++) {
            ulonglong2 am0 = *(const ulonglong2*)&As[buf][kk][ty * 8];
            ulonglong2 am1 = *(const ulonglong2*)&As[buf][kk][ty * 8 + 4];
            float4 b4 = *(const float4*)&Bs[buf][kk][tx * 4];
            ULL bb0 = pk(b4.x, b4.x), bb1 = pk(b4.y, b4.y);
            ULL bb2 = pk(b4.z, b4.z), bb3 = pk(b4.w, b4.w);
            ULL am[4] = {am0.x, am0.y, am1.x, am1.y};
            #pragma unroll
            for (int r = 0; r < 4; r++) {
                acc[r][0] = fma2(am[r], bb0, acc[r][0]);
                acc[r][1] = fma2(am[r], bb1, acc[r][1]);
                acc[r][2] = fma2(am[r], bb2, acc[r][2]);
                acc[r][3] = fma2(am[r], bb3, acc[r][3]);
            }
        }
        if (last) break;

        int nb = buf ^ 1;
        As[nb][alc + 0][alr] = a0.x; As[nb][alc + 1][alr] = a0.y;
        As[nb][alc + 2][alr] = a0.z; As[nb][alc + 3][alr] = a0.w;
        As[nb][alc + 4][alr] = a1.x; As[nb][alc + 5][alr] = a1.y;
        As[nb][alc + 6][alr] = a1.z; As[nb][alc + 7][alr] = a1.w;
        Bs[nb][blc + 0][blr] = b0.x; Bs[nb][blc + 1][blr] = b0.y;
        Bs[nb][blc + 2][blr] = b0.z; Bs[nb][blc + 3][blr] = b0.w;
        buf = nb;
        __syncthreads();
    }

    int col = bn + tx * 4;
    float bsel = (z == 0) ? 1.f : 0.f;
    float4 bb = *(const float4*)(bias + col);
    bb.x *= bsel; bb.y *= bsel; bb.z *= bsel; bb.w *= bsel;
    float* C = (z == 0) ? C0 : C1;
    #pragma unroll
    for (int r = 0; r < 4; r++) {
        float lo0, hi0, lo1, hi1, lo2v, hi2, lo3, hi3;
        unpk(acc[r][0], lo0, hi0);
        unpk(acc[r][1], lo1, hi1);
        unpk(acc[r][2], lo2v, hi2);
        unpk(acc[r][3], lo3, hi3);
        int row0 = bm + ty * 8 + 2 * r;
        *(float4*)(C + (size_t)row0 * N + col) =
            make_float4(lo0 + bb.x, lo1 + bb.y, lo2v + bb.z, lo3 + bb.w);
        *(float4*)(C + (size_t)(row0 + 1) * N + col) =
            make_float4(hi0 + bb.x, hi1 + bb.y, hi2 + bb.z, hi3 + bb.w);
    }
}

// ---------------- attention pass 1: keys-packed, no-max softmax -------------
// grid = (4 key-quarters, 2 query-halves, 128 bh), 128 threads.
// q-row LDGs hoisted above staging so their latency hides under the barrier.
__global__ __launch_bounds__(128) void attn_p1_kernel()
{
    __shared__ ULL Kp[128 * 8];
    __shared__ ULL Vp[128 * 8];

    int kq = blockIdx.x;
    int qh = blockIdx.y;
    int bh = blockIdx.z;
    int b = bh >> 5;
    int h = bh & 31;
    int t = threadIdx.x;
    const float* base = g_qkv + (size_t)b * S_ * (3 * E_) + h * DK_;

    // issue q loads FIRST (independent of smem staging)
    float4 qr0[4], qr1[4];
    #pragma unroll
    for (int i = 0; i < 4; i++) {
        const float* r = base + (size_t)(qh * 512 + t + i * 128) * (3 * E_);
        qr0[i] = *(const float4*)(r);
        qr1[i] = *(const float4*)(r + 4);
    }

    // stage: thread t packs keys (2t, 2t+1)
    {
        const float* ra = base + (size_t)(kq * 256 + 2 * t) * (3 * E_);
        const float* rb = ra + 3 * E_;
        float4 ka0 = *(const float4*)(ra + E_);
        float4 ka1 = *(const float4*)(ra + E_ + 4);
        float4 kb0 = *(const float4*)(rb + E_);
        float4 kb1 = *(const float4*)(rb + E_ + 4);
        ulonglong2* kw = (ulonglong2*)(Kp + t * 8);
        kw[0] = make_ulonglong2(pk(ka0.x, kb0.x), pk(ka0.y, kb0.y));
        kw[1] = make_ulonglong2(pk(ka0.z, kb0.z), pk(ka0.w, kb0.w));
        kw[2] = make_ulonglong2(pk(ka1.x, kb1.x), pk(ka1.y, kb1.y));
        kw[3] = make_ulonglong2(pk(ka1.z, kb1.z), pk(ka1.w, kb1.w));
        float4 va0 = *(const float4*)(ra + 2 * E_);
        float4 va1 = *(const float4*)(ra + 2 * E_ + 4);
        float4 vb0 = *(const float4*)(rb + 2 * E_);
        float4 vb1 = *(const float4*)(rb + 2 * E_ + 4);
        ulonglong2* vw = (ulonglong2*)(Vp + t * 8);
        vw[0] = make_ulonglong2(pk(va0.x, vb0.x), pk(va0.y, vb0.y));
        vw[1] = make_ulonglong2(pk(va0.z, vb0.z), pk(va0.w, vb0.w));
        vw[2] = make_ulonglong2(pk(va1.x, vb1.x), pk(va1.y, vb1.y));
        vw[3] = make_ulonglong2(pk(va1.z, vb1.z), pk(va1.w, vb1.w));
    }
    __syncthreads();

    const float qscale = 0.35355339059327373f * 1.4426950408889634f;

    ULL qd[4][8];
    #pragma unroll
    for (int i = 0; i < 4; i++) {
        float s;
        s = qr0[i].x * qscale; qd[i][0] = pk(s, s);
        s = qr0[i].y * qscale; qd[i][1] = pk(s, s);
        s = qr0[i].z * qscale; qd[i][2] = pk(s, s);
        s = qr0[i].w * qscale; qd[i][3] = pk(s, s);
        s = qr1[i].x * qscale; qd[i][4] = pk(s, s);
        s = qr1[i].y * qscale; qd[i][5] = pk(s, s);
        s = qr1[i].z * qscale; qd[i][6] = pk(s, s);
        s = qr1[i].w * qscale; qd[i][7] = pk(s, s);
    }

    ULL l[4] = {0ULL, 0ULL, 0ULL, 0ULL};
    ULL acc[4][8];
    #pragma unroll
    for (int i = 0; i < 4; i++)
        #pragma unroll
        for (int c = 0; c < 8; c++) acc[i][c] = 0ULL;

    #pragma unroll 1
    for (int sp = 0; sp < 128; sp++) {
        const ulonglong2* kr = (const ulonglong2*)(Kp + sp * 8);
        ulonglong2 k01 = kr[0], k23 = kr[1], k45 = kr[2], k67 = kr[3];

        ULL t0 = mul2(qd[0][0], k01.x);
        ULL t1 = mul2(qd[1][0], k01.x);
        ULL t2 = mul2(qd[2][0], k01.x);
        ULL t3 = mul2(qd[3][0], k01.x);
        t0 = fma2(qd[0][1], k01.y, t0);
        t1 = fma2(qd[1][1], k01.y, t1);
        t2 = fma2(qd[2][1], k01.y, t2);
        t3 = fma2(qd[3][1], k01.y, t3);
        t0 = fma2(qd[0][2], k23.x, t0);
        t1 = fma2(qd[1][2], k23.x, t1);
        t2 = fma2(qd[2][2], k23.x, t2);
        t3 = fma2(qd[3][2], k23.x, t3);
        t0 = fma2(qd[0][3], k23.y, t0);
        t1 = fma2(qd[1][3], k23.y, t1);
        t2 = fma2(qd[2][3], k23.y, t2);
        t3 = fma2(qd[3][3], k23.y, t3);
        t0 = fma2(qd[0][4], k45.x, t0);
        t1 = fma2(qd[1][4], k45.x, t1);
        t2 = fma2(qd[2][4], k45.x, t2);
        t3 = fma2(qd[3][4], k45.x, t3);
        t0 = fma2(qd[0][5], k45.y, t0);
        t1 = fma2(qd[1][5], k45.y, t1);
        t2 = fma2(qd[2][5], k45.y, t2);
        t3 = fma2(qd[3][5], k45.y, t3);
        t0 = fma2(qd[0][6], k67.x, t0);
        t1 = fma2(qd[1][6], k67.x, t1);
        t2 = fma2(qd[2][6], k67.x, t2);
        t3 = fma2(qd[3][6], k67.x, t3);
        t0 = fma2(qd[0][7], k67.y, t0);
        t1 = fma2(qd[1][7], k67.y, t1);
        t2 = fma2(qd[2][7], k67.y, t2);
        t3 = fma2(qd[3][7], k67.y, t3);

        float d0, d1;
        unpk(t0, d0, d1);
        ULL pp0 = pk(ex2f_(d0), ex2f_(d1));
        unpk(t1, d0, d1);
        ULL pp1 = pk(ex2f_(d0), ex2f_(d1));
        unpk(t2, d0, d1);
        ULL pp2 = pk(ex2f_(d0), ex2f_(d1));
        unpk(t3, d0, d1);
        ULL pp3 = pk(ex2f_(d0), ex2f_(d1));
        l[0] = add2(l[0], pp0);
        l[1] = add2(l[1], pp1);
        l[2] = add2(l[2], pp2);
        l[3] = add2(l[3], pp3);

        const ulonglong2* vr = (const ulonglong2*)(Vp + sp * 8);
        ulonglong2 v01 = vr[0], v23 = vr[1], v45 = vr[2], v67 = vr[3];
        acc[0][0] = fma2(pp0, v01.x, acc[0][0]);
        acc[1][0] = fma2(pp1, v01.x, acc[1][0]);
        acc[2][0] = fma2(pp2, v01.x, acc[2][0]);
        acc[3][0] = fma2(pp3, v01.x, acc[3][0]);
        acc[0][1] = fma2(pp0, v01.y, acc[0][1]);
        acc[1][1] = fma2(pp1, v01.y, acc[1][1]);
        acc[2][1] = fma2(pp2, v01.y, acc[2][1]);
        acc[3][1] = fma2(pp3, v01.y, acc[3][1]);
        acc[0][2] = fma2(pp0, v23.x, acc[0][2]);
        acc[1][2] = fma2(pp1, v23.x, acc[1][2]);
        acc[2][2] = fma2(pp2, v23.x, acc[2][2]);
        acc[3][2] = fma2(pp3, v23.x, acc[3][2]);
        acc[0][3] = fma2(pp0, v23.y, acc[0][3]);
        acc[1][3] = fma2(pp1, v23.y, acc[1][3]);
        acc[2][3] = fma2(pp2, v23.y, acc[2][3]);
        acc[3][3] = fma2(pp3, v23.y, acc[3][3]);
        acc[0][4] = fma2(pp0, v45.x, acc[0][4]);
        acc[1][4] = fma2(pp1, v45.x, acc[1][4]);
        acc[2][4] = fma2(pp2, v45.x, acc[2][4]);
        acc[3][4] = fma2(pp3, v45.x, acc[3][4]);
        acc[0][5] = fma2(pp0, v45.y, acc[0][5]);
        acc[1][5] = fma2(pp1, v45.y, acc[1][5]);
        acc[2][5] = fma2(pp2, v45.y, acc[2][5]);
        acc[3][5] = fma2(pp3, v45.y, acc[3][5]);
        acc[0][6] = fma2(pp0, v67.x, acc[0][6]);
        acc[1][6] = fma2(pp1, v67.x, acc[1][6]);
        acc[2][6] = fma2(pp2, v67.x, acc[2][6]);
        acc[3][6] = fma2(pp3, v67.x, acc[3][6]);
        acc[0][7] = fma2(pp0, v67.y, acc[0][7]);
        acc[1][7] = fma2(pp1, v67.y, acc[1][7]);
        acc[2][7] = fma2(pp2, v67.y, acc[2][7]);
        acc[3][7] = fma2(pp3, v67.y, acc[3][7]);
    }

    int pidx = ((bh * 4 + kq) * 2 + qh) * 128 + t;
    {
        float lo, hi;
        float lv[4];
        #pragma unroll
        for (int i = 0; i < 4; i++) { unpk(l[i], lo, hi); lv[i] = lo + hi; }
        *(float4*)(g_plf + pidx * 4) = make_float4(lv[0], lv[1], lv[2], lv[3]);
        float* pa = g_paccf + (size_t)pidx * 32;
        #pragma unroll
        for (int i = 0; i < 4; i++) {
            float av[8];
            #pragma unroll
            for (int c = 0; c < 8; c++) { unpk(acc[i][c], lo, hi); av[c] = lo + hi; }
            *(float4*)(pa + i * 8)     = make_float4(av[0], av[1], av[2], av[3]);
            *(float4*)(pa + i * 8 + 4) = make_float4(av[4], av[5], av[6], av[7]);
        }
    }
}

// ---------------- attention pass 2: sum 4 partials, normalize ---------------
// 256 CTAs x 128 threads (finer grain for 148 SMs).
__global__ __launch_bounds__(128) void attn_p2_kernel()
{
    int idx = blockIdx.x * 128 + threadIdx.x;
    int bh = idx >> 8;
    int r  = idx & 255;
    int qh = r >> 7;
    int t  = r & 127;
    int b = bh >> 5;
    int h = bh & 31;

    float L[4] = {0.f, 0.f, 0.f, 0.f};
    float c[4][8];
    #pragma unroll
    for (int i = 0; i < 4; i++)
        #pragma unroll
        for (int j = 0; j < 8; j++) c[i][j] = 0.f;

    #pragma unroll
    for (int kq = 0; kq < 4; kq++) {
        int pidx = ((bh * 4 + kq) * 2 + qh) * 128 + t;
        float4 lv = *(const float4*)(g_plf + pidx * 4);
        L[0] += lv.x; L[1] += lv.y; L[2] += lv.z; L[3] += lv.w;
        const float4* pa = (const float4*)(g_paccf + (size_t)pidx * 32);
        #pragma unroll
        for (int i = 0; i < 4; i++) {
            float4 a0 = pa[2 * i], a1 = pa[2 * i + 1];
            c[i][0] += a0.x; c[i][1] += a0.y; c[i][2] += a0.z; c[i][3] += a0.w;
            c[i][4] += a1.x; c[i][5] += a1.y; c[i][6] += a1.z; c[i][7] += a1.w;
        }
    }

    #pragma unroll
    for (int i = 0; i < 4; i++) {
        float rr = 1.f / L[i];
        int q = qh * 512 + t + i * 128;
        float* o = g_ctx + ((size_t)b * S_ + q) * E_ + h * DK_;
        *(float4*)(o)     = make_float4(c[i][0] * rr, c[i][1] * rr, c[i][2] * rr, c[i][3] * rr);
        *(float4*)(o + 4) = make_float4(c[i][4] * rr, c[i][5] * rr, c[i][6] * rr, c[i][7] * rr);
    }
}

// ---------------- LN1 fused with qf: h = LN(a+b0+b1), qf from h row ---------
__global__ __launch_bounds__(256) void ln3q_kernel(
    const float* __restrict__ a, const float* __restrict__ bsrc0,
    const float* __restrict__ bsrc1,
    const float* __restrict__ g, const float* __restrict__ beta,
    const float* __restrict__ w_ip, const float* __restrict__ b_ip,
    const float* __restrict__ theta_ffn,
    float* __restrict__ out)
{
    int row  = (blockIdx.x * 256 + threadIdx.x) >> 5;
    int lane = threadIdx.x & 31;
    size_t off = (size_t)row * E_ + lane * 8;

    const float4* ap = (const float4*)(a + off);
    const float4* bp = (const float4*)(bsrc0 + off);
    const float4* cp = (const float4*)(bsrc1 + off);
    float4 a0 = ap[0], a1 = ap[1], b0 = bp[0], b1 = bp[1];
    float4 c0 = cp[0], c1 = cp[1];
    float v[8];
    v[0] = a0.x + b0.x + c0.x; v[1] = a0.y + b0.y + c0.y;
    v[2] = a0.z + b0.z + c0.z; v[3] = a0.w + b0.w + c0.w;
    v[4] = a1.x + b1.x + c1.x; v[5] = a1.y + b1.y + c1.y;
    v[6] = a1.z + b1.z + c1.z; v[7] = a1.w + b1.w + c1.w;

    float s = 0.f, ss = 0.f;
    #pragma unroll
    for (int i = 0; i < 8; i++) { s += v[i]; ss = fmaf(v[i], v[i], ss); }
    #pragma unroll
    for (int o = 16; o > 0; o >>= 1) {
        s  += __shfl_xor_sync(0xFFFFFFFFu, s,  o);
        ss += __shfl_xor_sync(0xFFFFFFFFu, ss, o);
    }
    float mu  = s * (1.f / E_);
    float var = ss * (1.f / E_) - mu * mu;
    float rs  = rsqrtf(var + 1e-5f);

    const float4* gp  = (const float4*)(g    + lane * 8);
    const float4* bep = (const float4*)(beta + lane * 8);
    float4 g0 = gp[0], g1v = gp[1], e0 = bep[0], e1 = bep[1];

    float hv[8];
    hv[0] = (v[0]-mu)*rs*g0.x + e0.x;  hv[1] = (v[1]-mu)*rs*g0.y + e0.y;
    hv[2] = (v[2]-mu)*rs*g0.z + e0.z;  hv[3] = (v[3]-mu)*rs*g0.w + e0.w;
    hv[4] = (v[4]-mu)*rs*g1v.x + e1.x; hv[5] = (v[5]-mu)*rs*g1v.y + e1.y;
    hv[6] = (v[6]-mu)*rs*g1v.z + e1.z; hv[7] = (v[7]-mu)*rs*g1v.w + e1.w;

    *(float4*)(out + off)     = make_float4(hv[0], hv[1], hv[2], hv[3]);
    *(float4*)(out + off + 4) = make_float4(hv[4], hv[5], hv[6], hv[7]);

    // qf: 8 dot products of h-row with w_ip rows (packed fma2 over e)
    ULL d[4];
    #pragma unroll
    for (int jj = 0; jj < 4; jj++) {
        const float* w0 = w_ip + (size_t)(2 * jj)     * E_ + lane * 8;
        const float* w1 = w_ip + (size_t)(2 * jj + 1) * E_ + lane * 8;
        float4 wa0 = *(const float4*)(w0);
        float4 wa1 = *(const float4*)(w0 + 4);
        float4 wb0 = *(const float4*)(w1);
        float4 wb1 = *(const float4*)(w1 + 4);
        ULL acc = mul2(pk(hv[0], hv[0]), pk(wa0.x, wb0.x));
        acc = fma2(pk(hv[1], hv[1]), pk(wa0.y, wb0.y), acc);
        acc = fma2(pk(hv[2], hv[2]), pk(wa0.z, wb0.z), acc);
        acc = fma2(pk(hv[3], hv[3]), pk(wa0.w, wb0.w), acc);
        acc = fma2(pk(hv[4], hv[4]), pk(wa1.x, wb1.x), acc);
        acc = fma2(pk(hv[5], hv[5]), pk(wa1.y, wb1.y), acc);
        acc = fma2(pk(hv[6], hv[6]), pk(wa1.z, wb1.z), acc);
        acc = fma2(pk(hv[7], hv[7]), pk(wa1.w, wb1.w), acc);
        d[jj] = acc;
    }

    #pragma unroll
    for (int o = 16; o > 0; o >>= 1) {
        #pragma unroll
        for (int jj = 0; jj < 4; jj++) {
            ULL other = __shfl_xor_sync(0xFFFFFFFFu, d[jj], o);
            d[jj] = add2(d[jj], other);
        }
    }

    if (lane < 8) {
        float lo, hi;
        unpk(d[lane >> 1], lo, hi);
        float sj = (lane & 1) ? hi : lo;
        g_qf[row * NQ_ + lane] =
            __cosf(theta_ffn[lane]) * __cosf(sj + b_ip[lane]);
    }
}

// ---------------- layernorm3: out = LN(a + b0 + b1) * g + beta --------------
__global__ __launch_bounds__(256) void ln3_kernel(
    const float* __restrict__ a, const float* __restrict__ bsrc0,
    const float* __restrict__ bsrc1,
    const float* __restrict__ g, const float* __restrict__ beta,
    float* __restrict__ out)
{
    int row  = (blockIdx.x * 256 + threadIdx.x) >> 5;
    int lane = threadIdx.x & 31;
    size_t off = (size_t)row * E_ + lane * 8;

    const float4* ap = (const float4*)(a + off);
    const float4* bp = (const float4*)(bsrc0 + off);
    const float4* cp = (const float4*)(bsrc1 + off);
    float4 a0 = ap[0], a1 = ap[1], b0 = bp[0], b1 = bp[1];
    float4 c0 = cp[0], c1 = cp[1];
    float v[8];
    v[0] = a0.x + b0.x + c0.x; v[1] = a0.y + b0.y + c0.y;
    v[2] = a0.z + b0.z + c0.z; v[3] = a0.w + b0.w + c0.w;
    v[4] = a1.x + b1.x + c1.x; v[5] = a1.y + b1.y + c1.y;
    v[6] = a1.z + b1.z + c1.z; v[7] = a1.w + b1.w + c1.w;

    float s = 0.f, ss = 0.f;
    #pragma unroll
    for (int i = 0; i < 8; i++) { s += v[i]; ss = fmaf(v[i], v[i], ss); }
    #pragma unroll
    for (int o = 16; o > 0; o >>= 1) {
        s  += __shfl_xor_sync(0xFFFFFFFFu, s,  o);
        ss += __shfl_xor_sync(0xFFFFFFFFu, ss, o);
    }
    float mu  = s * (1.f / E_);
    float var = ss * (1.f / E_) - mu * mu;
    float rs  = rsqrtf(var + 1e-5f);

    const float4* gp  = (const float4*)(g    + lane * 8);
    const float4* bep = (const float4*)(beta + lane * 8);
    float4 g0 = gp[0], g1v = gp[1], e0 = bep[0], e1 = bep[1];

    float4 w;
    w.x = (v[0]-mu)*rs*g0.x + e0.x; w.y = (v[1]-mu)*rs*g0.y + e0.y;
    w.z = (v[2]-mu)*rs*g0.z + e0.z; w.w = (v[3]-mu)*rs*g0.w + e0.w;
    *(float4*)(out + off) = w;
    w.x = (v[4]-mu)*rs*g1v.x + e1.x; w.y = (v[5]-mu)*rs*g1v.y + e1.y;
    w.z = (v[6]-mu)*rs*g1v.z + e1.z; w.w = (v[7]-mu)*rs*g1v.w + e1.w;
    *(float4*)(out + off + 4) = w;
}

// ---------------- hidden = relu(qf @ w1^T + b1): w1 in regs, 4 m/thread -----
// grid = M/4 CTAs x 256 threads. Thread owns 4 w1 rows (f..f+3), loops 4 m.
__global__ __launch_bounds__(256) void hidden_kernel(
    const float* __restrict__ w1, const float* __restrict__ b1)
{
    int m0 = blockIdx.x * 4;
    int f = threadIdx.x * 4;

    float4 w0[4], w1v[4];
    float bb[4];
    #pragma unroll
    for (int j = 0; j < 4; j++) {
        const float4* wr = (const float4*)(w1 + (size_t)(f + j) * NQ_);
        w0[j] = wr[0]; w1v[j] = wr[1];
        bb[j] = b1[f + j];
    }

    #pragma unroll
    for (int mi = 0; mi < 4; mi++) {
        const float4* qp = (const float4*)(g_qf + (size_t)(m0 + mi) * NQ_);
        float4 q0 = qp[0], q1 = qp[1];
        float4 outv;
        float* op = &outv.x;
        #pragma unroll
        for (int j = 0; j < 4; j++) {
            float s = bb[j];
            s = fmaf(q0.x, w0[j].x, s);
            s = fmaf(q0.y, w0[j].y, s);
            s = fmaf(q0.z, w0[j].z, s);
            s = fmaf(q0.w, w0[j].w, s);
            s = fmaf(q1.x, w1v[j].x, s);
            s = fmaf(q1.y, w1v[j].y, s);
            s = fmaf(q1.z, w1v[j].z, s);
            s = fmaf(q1.w, w1v[j].w, s);
            op[j] = fmaxf(s, 0.f);
        }
        *(float4*)(g_hidden + (size_t)(m0 + mi) * FF_ + f) = outv;
    }
}

// ---------------- launch ----------------------------------------------------
extern "C" void kernel_launch(void* const* d_in, const int* in_sizes, int n_in,
                              void* d_out, int out_size)
{
    (void)in_sizes; (void)n_in; (void)out_size;

    const float* x          = (const float*)d_in[0];
    const float* theta_attn = (const float*)d_in[1];
    const float* w_in       = (const float*)d_in[2];
    const float* b_in       = (const float*)d_in[3];
    const float* w_out      = (const float*)d_in[4];
    const float* b_out      = (const float*)d_in[5];
    const float* w_comb     = (const float*)d_in[6];
    const float* b_comb     = (const float*)d_in[7];
    const float* g1         = (const float*)d_in[8];
    const float* be1        = (const float*)d_in[9];
    const float* g2         = (const float*)d_in[10];
    const float* be2        = (const float*)d_in[11];
    const float* w_ip       = (const float*)d_in[12];
    const float* b_ip       = (const float*)d_in[13];
    const float* theta_ffn  = (const float*)d_in[14];
    const float* w1         = (const float*)d_in[15];
    const float* b1         = (const float*)d_in[16];
    const float* w2         = (const float*)d_in[17];
    const float* b2         = (const float*)d_in[18];
    float* out = (float*)d_out;

    float *p_qout, *p_qkv, *p_qkv2, *p_ctx, *p_Wf, *p_bf, *p_tmp, *p_tmp2, *p_h, *p_hidden;
    cudaGetSymbolAddress((void**)&p_qout,   g_qout);
    cudaGetSymbolAddress((void**)&p_qkv,    g_qkv);
    cudaGetSymbolAddress((void**)&p_qkv2,   g_qkv2);
    cudaGetSymbolAddress((void**)&p_ctx,    g_ctx);
    cudaGetSymbolAddress((void**)&p_Wf,     g_Wf);
    cudaGetSymbolAddress((void**)&p_bf,     g_bf);
    cudaGetSymbolAddress((void**)&p_tmp,    g_tmp);
    cudaGetSymbolAddress((void**)&p_tmp2,   g_tmp2);
    cudaGetSymbolAddress((void**)&p_h,      g_h);
    cudaGetSymbolAddress((void**)&p_hidden, g_hidden);

    // 1. q_out = cos(x + theta)
    cos_encode_kernel<<<(M_ * E_) / 1024, 256>>>(x, theta_attn);

    // 2. fold w_comb @ w_out
    fold_w_kernel<<<E_, 256>>>(w_comb, w_out, b_out, b_comb);

    // 3. qkv partials = q_out @ w_in^T (+b_in), split-K=2  [4096 x 768]
    {
        dim3 grid((3 * E_) / 64, M_ / 128, 2);
        sgemm2s_kernel<<<grid, 256>>>(p_qout, w_in, b_in, p_qkv, p_qkv2,
                                      M_, 3 * E_, E_ / 2, E_);
    }
    // 3b. merge partials once
    qkv_sum_kernel<<<(M_ * 3 * E_) / 1024, 256>>>();

    // 4a. attention pass 1 (split-K=4 partials, keys-packed)
    {
        dim3 grid(4, 2, B_ * H_);
        attn_p1_kernel<<<grid, 128>>>();
    }
    // 4b. attention pass 2 (sum + normalize) -> ctx
    attn_p2_kernel<<<256, 128>>>();

    // 5. attn_out partials = ctx @ Wf^T (+bf), split-K=2   [4096 x 256]
    {
        dim3 grid(E_ / 64, M_ / 128, 2);
        sgemm2s_kernel<<<grid, 256>>>(p_ctx, p_Wf, p_bf, p_tmp, p_tmp2,
                                      M_, E_, E_ / 2, E_);
    }

    // 6. h = LN(x + tmp + tmp2) * g1 + be1 ; qf fused
    ln3q_kernel<<<M_ / 8, 256>>>(x, p_tmp, p_tmp2, g1, be1,
                                 w_ip, b_ip, theta_ffn, p_h);

    // 7. hidden = relu(qf @ w1^T + b1)    [4096 x 1024]
    hidden_kernel<<<M_ / 4, 256>>>(w1, b1);

    // 8. ffn_out partials = hidden @ w2^T (+b2), split-K=2  [4096 x 256]
    {
        dim3 grid(E_ / 64, M_ / 128, 2);
        sgemm2s_kernel<<<grid, 256>>>(p_hidden, w2, b2, p_tmp, p_tmp2,
                                      M_, E_, FF_ / 2, FF_);
    }

    // 9. out = LN(h + tmp + tmp2) * g2 + be2
    ln3_kernel<<<M_ / 8, 256>>>(p_h, p_tmp, p_tmp2, g2, be2, out);
}

// round 17
// speedup vs baseline: 1.2356x; 1.0002x over previous
#include <cuda_runtime.h>
#include <math.h>
#include <stdint.h>

// Problem constants
#define B_   4
#define S_   1024
#define E_   256
#define H_   32
#define DK_  8
#define NQ_  8
#define FF_  1024
#define M_   (B_ * S_)   // 4096

typedef unsigned long long ULL;

// ---------------- f32x2 packed math helpers (PTX-only on sm_103a) ----------
__device__ __forceinline__ ULL fma2(ULL a, ULL b, ULL c) {
    ULL d; asm("fma.rn.f32x2 %0, %1, %2, %3;" : "=l"(d) : "l"(a), "l"(b), "l"(c)); return d;
}
__device__ __forceinline__ ULL mul2(ULL a, ULL b) {
    ULL d; asm("mul.rn.f32x2 %0, %1, %2;" : "=l"(d) : "l"(a), "l"(b)); return d;
}
__device__ __forceinline__ ULL add2(ULL a, ULL b) {
    ULL d; asm("add.rn.f32x2 %0, %1, %2;" : "=l"(d) : "l"(a), "l"(b)); return d;
}
__device__ __forceinline__ ULL pk(float lo, float hi) {
    ULL r; asm("mov.b64 %0, {%1, %2};" : "=l"(r) : "f"(lo), "f"(hi)); return r;
}
__device__ __forceinline__ void unpk(ULL v, float& lo, float& hi) {
    asm("mov.b64 {%0, %1}, %2;" : "=f"(lo), "=f"(hi) : "l"(v));
}
__device__ __forceinline__ float ex2f_(float x) {
    float y; asm("ex2.approx.f32 %0, %1;" : "=f"(y) : "f"(x)); return y;
}

// ---------------- scratch (device globals; no runtime allocation) ----------
__device__ __align__(16) float g_qout[M_ * E_];
__device__ __align__(16) float g_qkv[M_ * 3 * E_];
__device__ __align__(16) float g_qkv2[M_ * 3 * E_];   // split-K partial
__device__ __align__(16) float g_ctx[M_ * E_];
__device__ __align__(16) float g_Wf[E_ * E_];
__device__ __align__(16) float g_bf[E_];
__device__ __align__(16) float g_tmp[M_ * E_];
__device__ __align__(16) float g_tmp2[M_ * E_];
__device__ __align__(16) float g_tmp3[M_ * E_];
__device__ __align__(16) float g_tmp4[M_ * E_];
__device__ __align__(16) float g_h[M_ * E_];
__device__ __align__(16) float g_qf[M_ * NQ_];
__device__ __align__(16) float g_hidden[M_ * FF_];
// split-K attention partials (plain floats; lo/hi combined in pass 1)
__device__ __align__(16) float g_plf[131072 * 4];
__device__ __align__(16) float g_paccf[(size_t)131072 * 32];

// ---------------- q_out = cos(x + theta[e % 8]), float4 --------------------
__global__ __launch_bounds__(256) void cos_encode_kernel(
    const float* __restrict__ x, const float* __restrict__ theta)
{
    int i = (blockIdx.x * 256 + threadIdx.x) * 4;
    float4 v = *(const float4*)(x + i);
    int j = i & 7;
    v.x = __cosf(v.x + theta[j + 0]);
    v.y = __cosf(v.y + theta[j + 1]);
    v.z = __cosf(v.z + theta[j + 2]);
    v.w = __cosf(v.w + theta[j + 3]);
    *(float4*)(g_qout + i) = v;
}

// ---------------- qkv = qkv + qkv2 (merge split-K partials) -----------------
__global__ __launch_bounds__(256) void qkv_sum_kernel()
{
    int i = (blockIdx.x * 256 + threadIdx.x) * 4;
    float4 a = *(const float4*)(g_qkv + i);
    float4 b = *(const float4*)(g_qkv2 + i);
    a.x += b.x; a.y += b.y; a.z += b.z; a.w += b.w;
    *(float4*)(g_qkv + i) = a;
}

// ---------------- fold: Wf = w_comb @ w_out, bf = w_comb@b_out + b_comb -----
__global__ __launch_bounds__(256) void fold_w_kernel(
    const float* __restrict__ w_comb, const float* __restrict__ w_out,
    const float* __restrict__ b_out, const float* __restrict__ b_comb)
{
    int i = blockIdx.x;
    int j = threadIdx.x;
    float s = 0.f;
    #pragma unroll 8
    for (int k = 0; k < E_; k++)
        s = fmaf(w_comb[i * E_ + k], w_out[k * E_ + j], s);
    g_Wf[i * E_ + j] = s;

    __shared__ float red[256];
    red[j] = w_comb[i * E_ + j] * b_out[j];
    __syncthreads();
    #pragma unroll
    for (int off = 128; off > 0; off >>= 1) {
        if (j < off) red[j] += red[j + off];
        __syncthreads();
    }
    if (j == 0) g_bf[i] = red[0] + b_comb[i];
}

// ---------------- split-K SGEMM (generic split count via pointer array) -----
// z-th CTA layer does K-slice z of length Kslice; writes partial to Cz.
// Bias added only by z==0.
__global__ __launch_bounds__(256) void sgemm2s_kernel(
    const float* __restrict__ A, const float* __restrict__ Bw,
    const float* __restrict__ bias,
    float* __restrict__ C0, float* __restrict__ C1,
    float* __restrict__ C2, float* __restrict__ C3,
    int M, int N, int Kslice, int lda)
{
    __shared__ float As[2][16][132];
    __shared__ float Bs[2][16][68];

    int tid = threadIdx.x;
    int bm = blockIdx.y * 128;
    int bn = blockIdx.x * 64;
    int z  = blockIdx.z;
    int ty = tid >> 4;
    int tx = tid & 15;

    int alr = tid >> 1;
    int alc = (tid & 1) * 8;
    int blr = tid >> 2;
    int blc = (tid & 3) * 4;

    const float* Aptr = A  + (size_t)(bm + alr) * lda + z * Kslice + alc;
    const float* Bptr = Bw + (size_t)(bn + blr) * lda + z * Kslice + blc;

    float4 a0 = *(const float4*)(Aptr);
    float4 a1 = *(const float4*)(Aptr + 4);
    float4 b0 = *(const float4*)(Bptr);

    ULL acc[4][4];
    #pragma unroll
    for (int r = 0; r < 4; r++)
        #pragma unroll
        for (int j = 0; j < 4; j++) acc[r][j] = 0ULL;

    As[0][alc + 0][alr] = a0.x; As[0][alc + 1][alr] = a0.y;
    As[0][alc + 2][alr] = a0.z; As[0][alc + 3][alr] = a0.w;
    As[0][alc + 4][alr] = a1.x; As[0][alc + 5][alr] = a1.y;
    As[0][alc + 6][alr] = a1.z; As[0][alc + 7][alr] = a1.w;
    Bs[0][blc + 0][blr] = b0.x; Bs[0][blc + 1][blr] = b0.y;
    Bs[0][blc + 2][blr] = b0.z; Bs[0][blc + 3][blr] = b0.w;
    __syncthreads();

    int buf = 0;
    for (int k0 = 0; ; k0 += 16) {
        bool last = (k0 + 16 >= Kslice);
        if (!last) {
            Aptr += 16; Bptr += 16;
            a0 = *(const float4*)(Aptr);
            a1 = *(const float4*)(Aptr + 4);
            b0 = *(const float4*)(Bptr);
        }

        #pragma unroll
        for (int kk = 0; kk < 16; kk++) {
            ulonglong2 am0 = *(const ulonglong2*)&As[buf][kk][ty * 8];
            ulonglong2 am1 = *(const ulonglong2*)&As[buf][kk][ty * 8 + 4];
            float4 b4 = *(const float4*)&Bs[buf][kk][tx * 4];
            ULL bb0 = pk(b4.x, b4.x), bb1 = pk(b4.y, b4.y);
            ULL bb2 = pk(b4.z, b4.z), bb3 = pk(b4.w, b4.w);
            ULL am[4] = {am0.x, am0.y, am1.x, am1.y};
            #pragma unroll
            for (int r = 0; r < 4; r++) {
                acc[r][0] = fma2(am[r], bb0, acc[r][0]);
                acc[r][1] = fma2(am[r], bb1, acc[r][1]);
                acc[r][2] = fma2(am[r], bb2, acc[r][2]);
                acc[r][3] = fma2(am[r], bb3, acc[r][3]);
            }
        }
        if (last) break;

        int nb = buf ^ 1;
        As[nb][alc + 0][alr] = a0.x; As[nb][alc + 1][alr] = a0.y;
        As[nb][alc + 2][alr] = a0.z; As[nb][alc + 3][alr] = a0.w;
        As[nb][alc + 4][alr] = a1.x; As[nb][alc + 5][alr] = a1.y;
        As[nb][alc + 6][alr] = a1.z; As[nb][alc + 7][alr] = a1.w;
        Bs[nb][blc + 0][blr] = b0.x; Bs[nb][blc + 1][blr] = b0.y;
        Bs[nb][blc + 2][blr] = b0.z; Bs[nb][blc + 3][blr] = b0.w;
        buf = nb;
        __syncthreads();
    }

    int col = bn + tx * 4;
    float bsel = (z == 0) ? 1.f : 0.f;
    float4 bb = *(const float4*)(bias + col);
    bb.x *= bsel; bb.y *= bsel; bb.z *= bsel; bb.w *= bsel;
    float* C = (z == 0) ? C0 : (z == 1) ? C1 : (z == 2) ? C2 : C3;
    #pragma unroll
    for (int r = 0; r < 4; r++) {
        float lo0, hi0, lo1, hi1, lo2v, hi2, lo3, hi3;
        unpk(acc[r][0], lo0, hi0);
        unpk(acc[r][1], lo1, hi1);
        unpk(acc[r][2], lo2v, hi2);
        unpk(acc[r][3], lo3, hi3);
        int row0 = bm + ty * 8 + 2 * r;
        *(float4*)(C + (size_t)row0 * N + col) =
            make_float4(lo0 + bb.x, lo1 + bb.y, lo2v + bb.z, lo3 + bb.w);
        *(float4*)(C + (size_t)(row0 + 1) * N + col) =
            make_float4(hi0 + bb.x, hi1 + bb.y, hi2 + bb.z, hi3 + bb.w);
    }
}

// ---------------- attention pass 1: keys-packed, no-max softmax -------------
// grid = (4 key-quarters, 2 query-halves, 128 bh), 128 threads.
// q-row LDGs hoisted above staging so their latency hides under the barrier.
__global__ __launch_bounds__(128) void attn_p1_kernel()
{
    __shared__ ULL Kp[128 * 8];
    __shared__ ULL Vp[128 * 8];

    int kq = blockIdx.x;
    int qh = blockIdx.y;
    int bh = blockIdx.z;
    int b = bh >> 5;
    int h = bh & 31;
    int t = threadIdx.x;
    const float* base = g_qkv + (size_t)b * S_ * (3 * E_) + h * DK_;

    // issue q loads FIRST (independent of smem staging)
    float4 qr0[4], qr1[4];
    #pragma unroll
    for (int i = 0; i < 4; i++) {
        const float* r = base + (size_t)(qh * 512 + t + i * 128) * (3 * E_);
        qr0[i] = *(const float4*)(r);
        qr1[i] = *(const float4*)(r + 4);
    }

    // stage: thread t packs keys (2t, 2t+1)
    {
        const float* ra = base + (size_t)(kq * 256 + 2 * t) * (3 * E_);
        const float* rb = ra + 3 * E_;
        float4 ka0 = *(const float4*)(ra + E_);
        float4 ka1 = *(const float4*)(ra + E_ + 4);
        float4 kb0 = *(const float4*)(rb + E_);
        float4 kb1 = *(const float4*)(rb + E_ + 4);
        ulonglong2* kw = (ulonglong2*)(Kp + t * 8);
        kw[0] = make_ulonglong2(pk(ka0.x, kb0.x), pk(ka0.y, kb0.y));
        kw[1] = make_ulonglong2(pk(ka0.z, kb0.z), pk(ka0.w, kb0.w));
        kw[2] = make_ulonglong2(pk(ka1.x, kb1.x), pk(ka1.y, kb1.y));
        kw[3] = make_ulonglong2(pk(ka1.z, kb1.z), pk(ka1.w, kb1.w));
        float4 va0 = *(const float4*)(ra + 2 * E_);
        float4 va1 = *(const float4*)(ra + 2 * E_ + 4);
        float4 vb0 = *(const float4*)(rb + 2 * E_);
        float4 vb1 = *(const float4*)(rb + 2 * E_ + 4);
        ulonglong2* vw = (ulonglong2*)(Vp + t * 8);
        vw[0] = make_ulonglong2(pk(va0.x, vb0.x), pk(va0.y, vb0.y));
        vw[1] = make_ulonglong2(pk(va0.z, vb0.z), pk(va0.w, vb0.w));
        vw[2] = make_ulonglong2(pk(va1.x, vb1.x), pk(va1.y, vb1.y));
        vw[3] = make_ulonglong2(pk(va1.z, vb1.z), pk(va1.w, vb1.w));
    }
    __syncthreads();

    const float qscale = 0.35355339059327373f * 1.4426950408889634f;

    ULL qd[4][8];
    #pragma unroll
    for (int i = 0; i < 4; i++) {
        float s;
        s = qr0[i].x * qscale; qd[i][0] = pk(s, s);
        s = qr0[i].y * qscale; qd[i][1] = pk(s, s);
        s = qr0[i].z * qscale; qd[i][2] = pk(s, s);
        s = qr0[i].w * qscale; qd[i][3] = pk(s, s);
        s = qr1[i].x * qscale; qd[i][4] = pk(s, s);
        s = qr1[i].y * qscale; qd[i][5] = pk(s, s);
        s = qr1[i].z * qscale; qd[i][6] = pk(s, s);
        s = qr1[i].w * qscale; qd[i][7] = pk(s, s);
    }

    ULL l[4] = {0ULL, 0ULL, 0ULL, 0ULL};
    ULL acc[4][8];
    #pragma unroll
    for (int i = 0; i < 4; i++)
        #pragma unroll
        for (int c = 0; c < 8; c++) acc[i][c] = 0ULL;

    #pragma unroll 1
    for (int sp = 0; sp < 128; sp++) {
        const ulonglong2* kr = (const ulonglong2*)(Kp + sp * 8);
        ulonglong2 k01 = kr[0], k23 = kr[1], k45 = kr[2], k67 = kr[3];

        ULL t0 = mul2(qd[0][0], k01.x);
        ULL t1 = mul2(qd[1][0], k01.x);
        ULL t2 = mul2(qd[2][0], k01.x);
        ULL t3 = mul2(qd[3][0], k01.x);
        t0 = fma2(qd[0][1], k01.y, t0);
        t1 = fma2(qd[1][1], k01.y, t1);
        t2 = fma2(qd[2][1], k01.y, t2);
        t3 = fma2(qd[3][1], k01.y, t3);
        t0 = fma2(qd[0][2], k23.x, t0);
        t1 = fma2(qd[1][2], k23.x, t1);
        t2 = fma2(qd[2][2], k23.x, t2);
        t3 = fma2(qd[3][2], k23.x, t3);
        t0 = fma2(qd[0][3], k23.y, t0);
        t1 = fma2(qd[1][3], k23.y, t1);
        t2 = fma2(qd[2][3], k23.y, t2);
        t3 = fma2(qd[3][3], k23.y, t3);
        t0 = fma2(qd[0][4], k45.x, t0);
        t1 = fma2(qd[1][4], k45.x, t1);
        t2 = fma2(qd[2][4], k45.x, t2);
        t3 = fma2(qd[3][4], k45.x, t3);
        t0 = fma2(qd[0][5], k45.y, t0);
        t1 = fma2(qd[1][5], k45.y, t1);
        t2 = fma2(qd[2][5], k45.y, t2);
        t3 = fma2(qd[3][5], k45.y, t3);
        t0 = fma2(qd[0][6], k67.x, t0);
        t1 = fma2(qd[1][6], k67.x, t1);
        t2 = fma2(qd[2][6], k67.x, t2);
        t3 = fma2(qd[3][6], k67.x, t3);
        t0 = fma2(qd[0][7], k67.y, t0);
        t1 = fma2(qd[1][7], k67.y, t1);
        t2 = fma2(qd[2][7], k67.y, t2);
        t3 = fma2(qd[3][7], k67.y, t3);

        float d0, d1;
        unpk(t0, d0, d1);
        ULL pp0 = pk(ex2f_(d0), ex2f_(d1));
        unpk(t1, d0, d1);
        ULL pp1 = pk(ex2f_(d0), ex2f_(d1));
        unpk(t2, d0, d1);
        ULL pp2 = pk(ex2f_(d0), ex2f_(d1));
        unpk(t3, d0, d1);
        ULL pp3 = pk(ex2f_(d0), ex2f_(d1));
        l[0] = add2(l[0], pp0);
        l[1] = add2(l[1], pp1);
        l[2] = add2(l[2], pp2);
        l[3] = add2(l[3], pp3);

        const ulonglong2* vr = (const ulonglong2*)(Vp + sp * 8);
        ulonglong2 v01 = vr[0], v23 = vr[1], v45 = vr[2], v67 = vr[3];
        acc[0][0] = fma2(pp0, v01.x, acc[0][0]);
        acc[1][0] = fma2(pp1, v01.x, acc[1][0]);
        acc[2][0] = fma2(pp2, v01.x, acc[2][0]);
        acc[3][0] = fma2(pp3, v01.x, acc[3][0]);
        acc[0][1] = fma2(pp0, v01.y, acc[0][1]);
        acc[1][1] = fma2(pp1, v01.y, acc[1][1]);
        acc[2][1] = fma2(pp2, v01.y, acc[2][1]);
        acc[3][1] = fma2(pp3, v01.y, acc[3][1]);
        acc[0][2] = fma2(pp0, v23.x, acc[0][2]);
        acc[1][2] = fma2(pp1, v23.x, acc[1][2]);
        acc[2][2] = fma2(pp2, v23.x, acc[2][2]);
        acc[3][2] = fma2(pp3, v23.x, acc[3][2]);
        acc[0][3] = fma2(pp0, v23.y, acc[0][3]);
        acc[1][3] = fma2(pp1, v23.y, acc[1][3]);
        acc[2][3] = fma2(pp2, v23.y, acc[2][3]);
        acc[3][3] = fma2(pp3, v23.y, acc[3][3]);
        acc[0][4] = fma2(pp0, v45.x, acc[0][4]);
        acc[1][4] = fma2(pp1, v45.x, acc[1][4]);
        acc[2][4] = fma2(pp2, v45.x, acc[2][4]);
        acc[3][4] = fma2(pp3, v45.x, acc[3][4]);
        acc[0][5] = fma2(pp0, v45.y, acc[0][5]);
        acc[1][5] = fma2(pp1, v45.y, acc[1][5]);
        acc[2][5] = fma2(pp2, v45.y, acc[2][5]);
        acc[3][5] = fma2(pp3, v45.y, acc[3][5]);
        acc[0][6] = fma2(pp0, v67.x, acc[0][6]);
        acc[1][6] = fma2(pp1, v67.x, acc[1][6]);
        acc[2][6] = fma2(pp2, v67.x, acc[2][6]);
        acc[3][6] = fma2(pp3, v67.x, acc[3][6]);
        acc[0][7] = fma2(pp0, v67.y, acc[0][7]);
        acc[1][7] = fma2(pp1, v67.y, acc[1][7]);
        acc[2][7] = fma2(pp2, v67.y, acc[2][7]);
        acc[3][7] = fma2(pp3, v67.y, acc[3][7]);
    }

    int pidx = ((bh * 4 + kq) * 2 + qh) * 128 + t;
    {
        float lo, hi;
        float lv[4];
        #pragma unroll
        for (int i = 0; i < 4; i++) { unpk(l[i], lo, hi); lv[i] = lo + hi; }
        *(float4*)(g_plf + pidx * 4) = make_float4(lv[0], lv[1], lv[2], lv[3]);
        float* pa = g_paccf + (size_t)pidx * 32;
        #pragma unroll
        for (int i = 0; i < 4; i++) {
            float av[8];
            #pragma unroll
            for (int c = 0; c < 8; c++) { unpk(acc[i][c], lo, hi); av[c] = lo + hi; }
            *(float4*)(pa + i * 8)     = make_float4(av[0], av[1], av[2], av[3]);
            *(float4*)(pa + i * 8 + 4) = make_float4(av[4], av[5], av[6], av[7]);
        }
    }
}

// ---------------- attention pass 2: sum 4 partials, normalize ---------------
// 256 CTAs x 128 threads.
__global__ __launch_bounds__(128) void attn_p2_kernel()
{
    int idx = blockIdx.x * 128 + threadIdx.x;
    int bh = idx >> 8;
    int r  = idx & 255;
    int qh = r >> 7;
    int t  = r & 127;
    int b = bh >> 5;
    int h = bh & 31;

    float L[4] = {0.f, 0.f, 0.f, 0.f};
    float c[4][8];
    #pragma unroll
    for (int i = 0; i < 4; i++)
        #pragma unroll
        for (int j = 0; j < 8; j++) c[i][j] = 0.f;

    #pragma unroll
    for (int kq = 0; kq < 4; kq++) {
        int pidx = ((bh * 4 + kq) * 2 + qh) * 128 + t;
        float4 lv = *(const float4*)(g_plf + pidx * 4);
        L[0] += lv.x; L[1] += lv.y; L[2] += lv.z; L[3] += lv.w;
        const float4* pa = (const float4*)(g_paccf + (size_t)pidx * 32);
        #pragma unroll
        for (int i = 0; i < 4; i++) {
            float4 a0 = pa[2 * i], a1 = pa[2 * i + 1];
            c[i][0] += a0.x; c[i][1] += a0.y; c[i][2] += a0.z; c[i][3] += a0.w;
            c[i][4] += a1.x; c[i][5] += a1.y; c[i][6] += a1.z; c[i][7] += a1.w;
        }
    }

    #pragma unroll
    for (int i = 0; i < 4; i++) {
        float rr = 1.f / L[i];
        int q = qh * 512 + t + i * 128;
        float* o = g_ctx + ((size_t)b * S_ + q) * E_ + h * DK_;
        *(float4*)(o)     = make_float4(c[i][0] * rr, c[i][1] * rr, c[i][2] * rr, c[i][3] * rr);
        *(float4*)(o + 4) = make_float4(c[i][4] * rr, c[i][5] * rr, c[i][6] * rr, c[i][7] * rr);
    }
}

// ---------------- LN1 fused with qf: h = LN(a+b0+b1), qf from h row ---------
__global__ __launch_bounds__(256) void ln3q_kernel(
    const float* __restrict__ a, const float* __restrict__ bsrc0,
    const float* __restrict__ bsrc1,
    const float* __restrict__ g, const float* __restrict__ beta,
    const float* __restrict__ w_ip, const float* __restrict__ b_ip,
    const float* __restrict__ theta_ffn,
    float* __restrict__ out)
{
    int row  = (blockIdx.x * 256 + threadIdx.x) >> 5;
    int lane = threadIdx.x & 31;
    size_t off = (size_t)row * E_ + lane * 8;

    const float4* ap = (const float4*)(a + off);
    const float4* bp = (const float4*)(bsrc0 + off);
    const float4* cp = (const float4*)(bsrc1 + off);
    float4 a0 = ap[0], a1 = ap[1], b0 = bp[0], b1 = bp[1];
    float4 c0 = cp[0], c1 = cp[1];
    float v[8];
    v[0] = a0.x + b0.x + c0.x; v[1] = a0.y + b0.y + c0.y;
    v[2] = a0.z + b0.z + c0.z; v[3] = a0.w + b0.w + c0.w;
    v[4] = a1.x + b1.x + c1.x; v[5] = a1.y + b1.y + c1.y;
    v[6] = a1.z + b1.z + c1.z; v[7] = a1.w + b1.w + c1.w;

    float s = 0.f, ss = 0.f;
    #pragma unroll
    for (int i = 0; i < 8; i++) { s += v[i]; ss = fmaf(v[i], v[i], ss); }
    #pragma unroll
    for (int o = 16; o > 0; o >>= 1) {
        s  += __shfl_xor_sync(0xFFFFFFFFu, s,  o);
        ss += __shfl_xor_sync(0xFFFFFFFFu, ss, o);
    }
    float mu  = s * (1.f / E_);
    float var = ss * (1.f / E_) - mu * mu;
    float rs  = rsqrtf(var + 1e-5f);

    const float4* gp  = (const float4*)(g    + lane * 8);
    const float4* bep = (const float4*)(beta + lane * 8);
    float4 g0 = gp[0], g1v = gp[1], e0 = bep[0], e1 = bep[1];

    float hv[8];
    hv[0] = (v[0]-mu)*rs*g0.x + e0.x;  hv[1] = (v[1]-mu)*rs*g0.y + e0.y;
    hv[2] = (v[2]-mu)*rs*g0.z + e0.z;  hv[3] = (v[3]-mu)*rs*g0.w + e0.w;
    hv[4] = (v[4]-mu)*rs*g1v.x + e1.x; hv[5] = (v[5]-mu)*rs*g1v.y + e1.y;
    hv[6] = (v[6]-mu)*rs*g1v.z + e1.z; hv[7] = (v[7]-mu)*rs*g1v.w + e1.w;

    *(float4*)(out + off)     = make_float4(hv[0], hv[1], hv[2], hv[3]);
    *(float4*)(out + off + 4) = make_float4(hv[4], hv[5], hv[6], hv[7]);

    // qf: 8 dot products of h-row with w_ip rows (packed fma2 over e)
    ULL d[4];
    #pragma unroll
    for (int jj = 0; jj < 4; jj++) {
        const float* w0 = w_ip + (size_t)(2 * jj)     * E_ + lane * 8;
        const float* w1 = w_ip + (size_t)(2 * jj + 1) * E_ + lane * 8;
        float4 wa0 = *(const float4*)(w0);
        float4 wa1 = *(const float4*)(w0 + 4);
        float4 wb0 = *(const float4*)(w1);
        float4 wb1 = *(const float4*)(w1 + 4);
        ULL acc = mul2(pk(hv[0], hv[0]), pk(wa0.x, wb0.x));
        acc = fma2(pk(hv[1], hv[1]), pk(wa0.y, wb0.y), acc);
        acc = fma2(pk(hv[2], hv[2]), pk(wa0.z, wb0.z), acc);
        acc = fma2(pk(hv[3], hv[3]), pk(wa0.w, wb0.w), acc);
        acc = fma2(pk(hv[4], hv[4]), pk(wa1.x, wb1.x), acc);
        acc = fma2(pk(hv[5], hv[5]), pk(wa1.y, wb1.y), acc);
        acc = fma2(pk(hv[6], hv[6]), pk(wa1.z, wb1.z), acc);
        acc = fma2(pk(hv[7], hv[7]), pk(wa1.w, wb1.w), acc);
        d[jj] = acc;
    }

    #pragma unroll
    for (int o = 16; o > 0; o >>= 1) {
        #pragma unroll
        for (int jj = 0; jj < 4; jj++) {
            ULL other = __shfl_xor_sync(0xFFFFFFFFu, d[jj], o);
            d[jj] = add2(d[jj], other);
        }
    }

    if (lane < 8) {
        float lo, hi;
        unpk(d[lane >> 1], lo, hi);
        float sj = (lane & 1) ? hi : lo;
        g_qf[row * NQ_ + lane] =
            __cosf(theta_ffn[lane]) * __cosf(sj + b_ip[lane]);
    }
}

// ---------------- layernorm5: out = LN(a + p0+p1+p2+p3) * g + beta ----------
__global__ __launch_bounds__(256) void ln5_kernel(
    const float* __restrict__ a,
    const float* __restrict__ p0src, const float* __restrict__ p1src,
    const float* __restrict__ p2src, const float* __restrict__ p3src,
    const float* __restrict__ g, const float* __restrict__ beta,
    float* __restrict__ out)
{
    int row  = (blockIdx.x * 256 + threadIdx.x) >> 5;
    int lane = threadIdx.x & 31;
    size_t off = (size_t)row * E_ + lane * 8;

    float4 a0 = ((const float4*)(a + off))[0];
    float4 a1 = ((const float4*)(a + off))[1];
    float v[8] = {a0.x, a0.y, a0.z, a0.w, a1.x, a1.y, a1.z, a1.w};
    const float* ps[4] = {p0src, p1src, p2src, p3src};
    #pragma unroll
    for (int k = 0; k < 4; k++) {
        float4 q0 = ((const float4*)(ps[k] + off))[0];
        float4 q1 = ((const float4*)(ps[k] + off))[1];
        v[0] += q0.x; v[1] += q0.y; v[2] += q0.z; v[3] += q0.w;
        v[4] += q1.x; v[5] += q1.y; v[6] += q1.z; v[7] += q1.w;
    }

    float s = 0.f, ss = 0.f;
    #pragma unroll
    for (int i = 0; i < 8; i++) { s += v[i]; ss = fmaf(v[i], v[i], ss); }
    #pragma unroll
    for (int o = 16; o > 0; o >>= 1) {
        s  += __shfl_xor_sync(0xFFFFFFFFu, s,  o);
        ss += __shfl_xor_sync(0xFFFFFFFFu, ss, o);
    }
    float mu  = s * (1.f / E_);
    float var = ss * (1.f / E_) - mu * mu;
    float rs  = rsqrtf(var + 1e-5f);

    const float4* gp  = (const float4*)(g    + lane * 8);
    const float4* bep = (const float4*)(beta + lane * 8);
    float4 g0 = gp[0], g1v = gp[1], e0 = bep[0], e1 = bep[1];

    float4 w;
    w.x = (v[0]-mu)*rs*g0.x + e0.x; w.y = (v[1]-mu)*rs*g0.y + e0.y;
    w.z = (v[2]-mu)*rs*g0.z + e0.z; w.w = (v[3]-mu)*rs*g0.w + e0.w;
    *(float4*)(out + off) = w;
    w.x = (v[4]-mu)*rs*g1v.x + e1.x; w.y = (v[5]-mu)*rs*g1v.y + e1.y;
    w.z = (v[6]-mu)*rs*g1v.z + e1.z; w.w = (v[7]-mu)*rs*g1v.w + e1.w;
    *(float4*)(out + off + 4) = w;
}

// ---------------- hidden = relu(qf @ w1^T + b1): w1 in regs, 4 m/thread -----
__global__ __launch_bounds__(256) void hidden_kernel(
    const float* __restrict__ w1, const float* __restrict__ b1)
{
    int m0 = blockIdx.x * 4;
    int f = threadIdx.x * 4;

    float4 w0[4], w1v[4];
    float bb[4];
    #pragma unroll
    for (int j = 0; j < 4; j++) {
        const float4* wr = (const float4*)(w1 + (size_t)(f + j) * NQ_);
        w0[j] = wr[0]; w1v[j] = wr[1];
        bb[j] = b1[f + j];
    }

    #pragma unroll
    for (int mi = 0; mi < 4; mi++) {
        const float4* qp = (const float4*)(g_qf + (size_t)(m0 + mi) * NQ_);
        float4 q0 = qp[0], q1 = qp[1];
        float4 outv;
        float* op = &outv.x;
        #pragma unroll
        for (int j = 0; j < 4; j++) {
            float s = bb[j];
            s = fmaf(q0.x, w0[j].x, s);
            s = fmaf(q0.y, w0[j].y, s);
            s = fmaf(q0.z, w0[j].z, s);
            s = fmaf(q0.w, w0[j].w, s);
            s = fmaf(q1.x, w1v[j].x, s);
            s = fmaf(q1.y, w1v[j].y, s);
            s = fmaf(q1.z, w1v[j].z, s);
            s = fmaf(q1.w, w1v[j].w, s);
            op[j] = fmaxf(s, 0.f);
        }
        *(float4*)(g_hidden + (size_t)(m0 + mi) * FF_ + f) = outv;
    }
}

// ---------------- launch ----------------------------------------------------
extern "C" void kernel_launch(void* const* d_in, const int* in_sizes, int n_in,
                              void* d_out, int out_size)
{
    (void)in_sizes; (void)n_in; (void)out_size;

    const float* x          = (const float*)d_in[0];
    const float* theta_attn = (const float*)d_in[1];
    const float* w_in       = (const float*)d_in[2];
    const float* b_in       = (const float*)d_in[3];
    const float* w_out      = (const float*)d_in[4];
    const float* b_out      = (const float*)d_in[5];
    const float* w_comb     = (const float*)d_in[6];
    const float* b_comb     = (const float*)d_in[7];
    const float* g1         = (const float*)d_in[8];
    const float* be1        = (const float*)d_in[9];
    const float* g2         = (const float*)d_in[10];
    const float* be2        = (const float*)d_in[11];
    const float* w_ip       = (const float*)d_in[12];
    const float* b_ip       = (const float*)d_in[13];
    const float* theta_ffn  = (const float*)d_in[14];
    const float* w1         = (const float*)d_in[15];
    const float* b1         = (const float*)d_in[16];
    const float* w2         = (const float*)d_in[17];
    const float* b2         = (const float*)d_in[18];
    float* out = (float*)d_out;

    float *p_qout, *p_qkv, *p_qkv2, *p_ctx, *p_Wf, *p_bf;
    float *p_tmp, *p_tmp2, *p_tmp3, *p_tmp4, *p_h, *p_hidden;
    cudaGetSymbolAddress((void**)&p_qout,   g_qout);
    cudaGetSymbolAddress((void**)&p_qkv,    g_qkv);
    cudaGetSymbolAddress((void**)&p_qkv2,   g_qkv2);
    cudaGetSymbolAddress((void**)&p_ctx,    g_ctx);
    cudaGetSymbolAddress((void**)&p_Wf,     g_Wf);
    cudaGetSymbolAddress((void**)&p_bf,     g_bf);
    cudaGetSymbolAddress((void**)&p_tmp,    g_tmp);
    cudaGetSymbolAddress((void**)&p_tmp2,   g_tmp2);
    cudaGetSymbolAddress((void**)&p_tmp3,   g_tmp3);
    cudaGetSymbolAddress((void**)&p_tmp4,   g_tmp4);
    cudaGetSymbolAddress((void**)&p_h,      g_h);
    cudaGetSymbolAddress((void**)&p_hidden, g_hidden);

    // 1. q_out = cos(x + theta)
    cos_encode_kernel<<<(M_ * E_) / 1024, 256>>>(x, theta_attn);

    // 2. fold w_comb @ w_out
    fold_w_kernel<<<E_, 256>>>(w_comb, w_out, b_out, b_comb);

    // 3. qkv partials = q_out @ w_in^T (+b_in), split-K=2  [4096 x 768]
    {
        dim3 grid((3 * E_) / 64, M_ / 128, 2);
        sgemm2s_kernel<<<grid, 256>>>(p_qout, w_in, b_in,
                                      p_qkv, p_qkv2, p_qkv, p_qkv,
                                      M_, 3 * E_, E_ / 2, E_);
    }
    // 3b. merge partials once
    qkv_sum_kernel<<<(M_ * 3 * E_) / 1024, 256>>>();

    // 4a. attention pass 1 (split-K=4 partials, keys-packed)
    {
        dim3 grid(4, 2, B_ * H_);
        attn_p1_kernel<<<grid, 128>>>();
    }
    // 4b. attention pass 2 (sum + normalize) -> ctx
    attn_p2_kernel<<<256, 128>>>();

    // 5. attn_out partials = ctx @ Wf^T (+bf), split-K=2   [4096 x 256]
    {
        dim3 grid(E_ / 64, M_ / 128, 2);
        sgemm2s_kernel<<<grid, 256>>>(p_ctx, p_Wf, p_bf,
                                      p_tmp, p_tmp2, p_tmp, p_tmp,
                                      M_, E_, E_ / 2, E_);
    }

    // 6. h = LN(x + tmp + tmp2) * g1 + be1 ; qf fused
    ln3q_kernel<<<M_ / 8, 256>>>(x, p_tmp, p_tmp2, g1, be1,
                                 w_ip, b_ip, theta_ffn, p_h);

    // 7. hidden = relu(qf @ w1^T + b1)    [4096 x 1024]
    hidden_kernel<<<M_ / 4, 256>>>(w1, b1);

    // 8. ffn_out partials = hidden @ w2^T (+b2), split-K=4  [4096 x 256]
    {
        dim3 grid(E_ / 64, M_ / 128, 4);
        sgemm2s_kernel<<<grid, 256>>>(p_hidden, w2, b2,
                                      p_tmp, p_tmp2, p_tmp3, p_tmp4,
                                      M_, E_, FF_ / 4, FF_);
    }

    // 9. out = LN(h + tmp + tmp2 + tmp3 + tmp4) * g2 + be2
    ln5_kernel<<<M_ / 8, 256>>>(p_h, p_tmp, p_tmp2, p_tmp3, p_tmp4,
                                g2, be2, out);
}